// round 1
// baseline (speedup 1.0000x reference)
#include <cuda_runtime.h>
#include <math.h>

#define BB 8
#define SS 1024
#define HH 128
#define PP 129
#define NROWS (BB*SS)   // 8192

// -------- device scratch (no allocations allowed) --------
__device__ float g_q[NROWS*HH];
__device__ float g_k[NROWS*HH];
__device__ float g_v[NROWS*HH];
__device__ float g_ctx[NROWS*HH];
__device__ float g_qrel[NROWS*PP];

// ============================================================
// Kernel 1: q/k/v = x @ W + b   (NN GEMM, M=8192, N=128, K=128)
// grid (2, 128, 3), block 256
// ============================================================
__global__ __launch_bounds__(256) void qkv_kernel(
    const float* __restrict__ x,
    const float* __restrict__ Wq, const float* __restrict__ bq,
    const float* __restrict__ Wk, const float* __restrict__ bk,
    const float* __restrict__ Wv, const float* __restrict__ bv)
{
    __shared__ float As[16][64];
    __shared__ float Bs[16][64];
    int z = blockIdx.z;
    const float* W    = (z == 0) ? Wq : (z == 1) ? Wk : Wv;
    const float* bias = (z == 0) ? bq : (z == 1) ? bk : bv;
    float* out        = (z == 0) ? g_q : (z == 1) ? g_k : g_v;

    int m0 = blockIdx.y * 64;
    int n0 = blockIdx.x * 64;
    int tid = threadIdx.x;
    int tx = tid & 15, ty = tid >> 4;
    int lr = tid >> 2, lq = tid & 3;       // A-load: row, k-quad
    int bk_ = tid >> 4, bn = tid & 15;     // B-load: k-row, n-quad

    float c[4][4] = {};
    for (int kc = 0; kc < HH; kc += 16) {
        float4 av = *(const float4*)(x + (size_t)(m0 + lr) * HH + kc + lq * 4);
        As[lq*4+0][lr] = av.x; As[lq*4+1][lr] = av.y;
        As[lq*4+2][lr] = av.z; As[lq*4+3][lr] = av.w;
        float4 wv = *(const float4*)(W + (size_t)(kc + bk_) * HH + n0 + bn * 4);
        ((float4*)Bs[bk_])[bn] = wv;
        __syncthreads();
        #pragma unroll
        for (int kk = 0; kk < 16; kk++) {
            float4 a = ((float4*)As[kk])[ty];
            float4 b = ((float4*)Bs[kk])[tx];
            float ar[4] = {a.x, a.y, a.z, a.w};
            float br[4] = {b.x, b.y, b.z, b.w};
            #pragma unroll
            for (int i = 0; i < 4; i++)
                #pragma unroll
                for (int j = 0; j < 4; j++)
                    c[i][j] += ar[i] * br[j];
        }
        __syncthreads();
    }
    #pragma unroll
    for (int i = 0; i < 4; i++) {
        int row = m0 + ty * 4 + i;
        #pragma unroll
        for (int j = 0; j < 4; j++) {
            int col = n0 + tx * 4 + j;
            out[(size_t)row * HH + col] = c[i][j] + bias[col];
        }
    }
}

// ============================================================
// Kernel 2: qrel = q @ rel_k^T   (NT GEMM, M=8192, N=129, K=128)
// grid (3, 128), block 256
// ============================================================
__global__ __launch_bounds__(256) void qrel_kernel(const float* __restrict__ rel_k)
{
    __shared__ float As[16][64];
    __shared__ float Bs[16][64];
    int m0 = blockIdx.y * 64;
    int n0 = blockIdx.x * 64;
    int tid = threadIdx.x;
    int tx = tid & 15, ty = tid >> 4;
    int lr = tid >> 2, lq = tid & 3;

    float c[4][4] = {};
    for (int kc = 0; kc < HH; kc += 16) {
        float4 av = *(const float4*)(g_q + (size_t)(m0 + lr) * HH + kc + lq * 4);
        As[lq*4+0][lr] = av.x; As[lq*4+1][lr] = av.y;
        As[lq*4+2][lr] = av.z; As[lq*4+3][lr] = av.w;
        float4 bv4 = make_float4(0.f, 0.f, 0.f, 0.f);
        if (n0 + lr < PP)
            bv4 = *(const float4*)(rel_k + (size_t)(n0 + lr) * HH + kc + lq * 4);
        Bs[lq*4+0][lr] = bv4.x; Bs[lq*4+1][lr] = bv4.y;
        Bs[lq*4+2][lr] = bv4.z; Bs[lq*4+3][lr] = bv4.w;
        __syncthreads();
        #pragma unroll
        for (int kk = 0; kk < 16; kk++) {
            float4 a = ((float4*)As[kk])[ty];
            float4 b = ((float4*)Bs[kk])[tx];
            float ar[4] = {a.x, a.y, a.z, a.w};
            float br[4] = {b.x, b.y, b.z, b.w};
            #pragma unroll
            for (int i = 0; i < 4; i++)
                #pragma unroll
                for (int j = 0; j < 4; j++)
                    c[i][j] += ar[i] * br[j];
        }
        __syncthreads();
    }
    #pragma unroll
    for (int i = 0; i < 4; i++) {
        int row = m0 + ty * 4 + i;
        #pragma unroll
        for (int j = 0; j < 4; j++) {
            int col = n0 + tx * 4 + j;
            if (col < PP)
                g_qrel[(size_t)row * PP + col] = c[i][j];
        }
    }
}

// ============================================================
// Kernel 3: scores[b] = q[b] @ k[b]^T / sqrt(H) + qrel lookup
// (NT GEMM per batch, M=N=1024, K=128) grid (16,16,8), block 256
// ============================================================
__global__ __launch_bounds__(256) void scores_kernel(float* __restrict__ scores)
{
    __shared__ float As[16][64];
    __shared__ float Bs[16][64];
    int b = blockIdx.z;
    const float* A = g_q + (size_t)b * SS * HH;
    const float* Bm = g_k + (size_t)b * SS * HH;
    int m0 = blockIdx.y * 64;
    int n0 = blockIdx.x * 64;
    int tid = threadIdx.x;
    int tx = tid & 15, ty = tid >> 4;
    int lr = tid >> 2, lq = tid & 3;

    float c[4][4] = {};
    for (int kc = 0; kc < HH; kc += 16) {
        float4 av = *(const float4*)(A + (size_t)(m0 + lr) * HH + kc + lq * 4);
        As[lq*4+0][lr] = av.x; As[lq*4+1][lr] = av.y;
        As[lq*4+2][lr] = av.z; As[lq*4+3][lr] = av.w;
        float4 bv4 = *(const float4*)(Bm + (size_t)(n0 + lr) * HH + kc + lq * 4);
        Bs[lq*4+0][lr] = bv4.x; Bs[lq*4+1][lr] = bv4.y;
        Bs[lq*4+2][lr] = bv4.z; Bs[lq*4+3][lr] = bv4.w;
        __syncthreads();
        #pragma unroll
        for (int kk = 0; kk < 16; kk++) {
            float4 a = ((float4*)As[kk])[ty];
            float4 b4 = ((float4*)Bs[kk])[tx];
            float ar[4] = {a.x, a.y, a.z, a.w};
            float br[4] = {b4.x, b4.y, b4.z, b4.w};
            #pragma unroll
            for (int i = 0; i < 4; i++)
                #pragma unroll
                for (int j = 0; j < 4; j++)
                    c[i][j] += ar[i] * br[j];
        }
        __syncthreads();
    }
    const float invscale = 0.08838834764831845f;  // 1/sqrt(128)
    #pragma unroll
    for (int i = 0; i < 4; i++) {
        int row = m0 + ty * 4 + i;
        #pragma unroll
        for (int j = 0; j < 4; j++) {
            int col = n0 + tx * 4 + j;
            int d = col - row;
            d = (d < -64) ? -64 : (d > 64) ? 64 : d;
            int p = d + 64;
            float val = c[i][j] * invscale + g_qrel[((size_t)b * SS + row) * PP + p];
            scores[((size_t)b * SS + row) * SS + col] = val;
        }
    }
}

// ============================================================
// Kernel 4: row-wise softmax (in place). grid 8192, block 256
// ============================================================
__global__ __launch_bounds__(256) void softmax_kernel(float* __restrict__ scores)
{
    __shared__ float row[SS];
    __shared__ float red[256];
    int r = blockIdx.x;
    float* sr = scores + (size_t)r * SS;
    int tid = threadIdx.x;

    float m = -1e30f;
    for (int j = tid; j < SS; j += 256) {
        float v = sr[j]; row[j] = v; m = fmaxf(m, v);
    }
    red[tid] = m; __syncthreads();
    for (int s = 128; s > 0; s >>= 1) {
        if (tid < s) red[tid] = fmaxf(red[tid], red[tid + s]);
        __syncthreads();
    }
    m = red[0]; __syncthreads();

    float sum = 0.f;
    for (int j = tid; j < SS; j += 256) {
        float e = __expf(row[j] - m); row[j] = e; sum += e;
    }
    red[tid] = sum; __syncthreads();
    for (int s = 128; s > 0; s >>= 1) {
        if (tid < s) red[tid] += red[tid + s];
        __syncthreads();
    }
    float inv = 1.0f / red[0];
    for (int j = tid; j < SS; j += 256) sr[j] = row[j] * inv;
}

// ============================================================
// Kernel 5: ctx[b] = attn[b] @ v[b]  (NN GEMM, M=1024, N=128, K=1024)
// grid (2,16,8), block 256
// ============================================================
__global__ __launch_bounds__(256) void ctx_kernel(const float* __restrict__ attn)
{
    __shared__ float As[16][64];
    __shared__ float Bs[16][64];
    int b = blockIdx.z;
    const float* A = attn + (size_t)b * SS * SS;
    const float* Bm = g_v + (size_t)b * SS * HH;
    float* out = g_ctx + (size_t)b * SS * HH;
    int m0 = blockIdx.y * 64;
    int n0 = blockIdx.x * 64;
    int tid = threadIdx.x;
    int tx = tid & 15, ty = tid >> 4;
    int lr = tid >> 2, lq = tid & 3;
    int bk_ = tid >> 4, bn = tid & 15;

    float c[4][4] = {};
    for (int kc = 0; kc < SS; kc += 16) {
        float4 av = *(const float4*)(A + (size_t)(m0 + lr) * SS + kc + lq * 4);
        As[lq*4+0][lr] = av.x; As[lq*4+1][lr] = av.y;
        As[lq*4+2][lr] = av.z; As[lq*4+3][lr] = av.w;
        float4 vv = *(const float4*)(Bm + (size_t)(kc + bk_) * HH + n0 + bn * 4);
        ((float4*)Bs[bk_])[bn] = vv;
        __syncthreads();
        #pragma unroll
        for (int kk = 0; kk < 16; kk++) {
            float4 a = ((float4*)As[kk])[ty];
            float4 b4 = ((float4*)Bs[kk])[tx];
            float ar[4] = {a.x, a.y, a.z, a.w};
            float br[4] = {b4.x, b4.y, b4.z, b4.w};
            #pragma unroll
            for (int i = 0; i < 4; i++)
                #pragma unroll
                for (int j = 0; j < 4; j++)
                    c[i][j] += ar[i] * br[j];
        }
        __syncthreads();
    }
    #pragma unroll
    for (int i = 0; i < 4; i++) {
        int row = m0 + ty * 4 + i;
        #pragma unroll
        for (int j = 0; j < 4; j++) {
            int col = n0 + tx * 4 + j;
            out[(size_t)row * HH + col] = c[i][j];
        }
    }
}

// ============================================================
// Kernel 6: ctx += arel @ rel_v, where arel[p] is derived from attn row.
// grid 8192, block 256
// ============================================================
__global__ __launch_bounds__(256) void relv_kernel(
    const float* __restrict__ attn, const float* __restrict__ rel_v)
{
    __shared__ float row[SS];
    __shared__ float ar[PP];
    __shared__ float red[256];
    int r = blockIdx.x;       // global row = b*S + i
    int i = r & (SS - 1);
    const float* sr = attn + (size_t)r * SS;
    int tid = threadIdx.x;

    float s_lo = 0.f, s_hi = 0.f;
    for (int j = tid; j < SS; j += 256) {
        float v = sr[j]; row[j] = v;
        int d = j - i;
        if (d <= -64) s_lo += v;
        if (d >= 64)  s_hi += v;
    }
    __syncthreads();
    if (tid >= 1 && tid <= 127) {
        int j = i + tid - 64;
        ar[tid] = (j >= 0 && j < SS) ? row[j] : 0.0f;
    }
    red[tid] = s_lo; __syncthreads();
    for (int s = 128; s > 0; s >>= 1) {
        if (tid < s) red[tid] += red[tid + s];
        __syncthreads();
    }
    if (tid == 0) ar[0] = red[0];
    __syncthreads();
    red[tid] = s_hi; __syncthreads();
    for (int s = 128; s > 0; s >>= 1) {
        if (tid < s) red[tid] += red[tid + s];
        __syncthreads();
    }
    if (tid == 0) ar[128] = red[0];
    __syncthreads();

    if (tid < HH) {
        float acc = 0.f;
        #pragma unroll 4
        for (int p = 0; p < PP; p++)
            acc += ar[p] * rel_v[p * HH + tid];
        g_ctx[(size_t)r * HH + tid] += acc;
    }
}

// ============================================================
// Kernel 7: out = ctx @ Wo + bo; y = LN(out + x). grid 8192, block 128
// ============================================================
__global__ __launch_bounds__(128) void out_ln_kernel(
    const float* __restrict__ x, const float* __restrict__ Wo,
    const float* __restrict__ bo, const float* __restrict__ gamma,
    const float* __restrict__ beta, float* __restrict__ y)
{
    __shared__ float cr[HH];
    __shared__ float red[HH];
    int r = blockIdx.x;
    int h = threadIdx.x;
    cr[h] = g_ctx[(size_t)r * HH + h];
    __syncthreads();

    float acc = bo[h];
    #pragma unroll 8
    for (int k = 0; k < HH; k++)
        acc += cr[k] * Wo[k * HH + h];
    float yv = acc + x[(size_t)r * HH + h];

    red[h] = yv; __syncthreads();
    for (int s = 64; s > 0; s >>= 1) {
        if (h < s) red[h] += red[h + s];
        __syncthreads();
    }
    float mu = red[0] * (1.0f / HH);
    __syncthreads();
    float d = yv - mu;
    red[h] = d * d; __syncthreads();
    for (int s = 64; s > 0; s >>= 1) {
        if (h < s) red[h] += red[h + s];
        __syncthreads();
    }
    float var = red[0] * (1.0f / HH);
    y[(size_t)r * HH + h] = d * rsqrtf(var + 1e-5f) * gamma[h] + beta[h];
}

// ============================================================
extern "C" void kernel_launch(void* const* d_in, const int* in_sizes, int n_in,
                              void* d_out, int out_size)
{
    const float* x     = (const float*)d_in[0];
    const float* Wq    = (const float*)d_in[1];
    const float* bq    = (const float*)d_in[2];
    const float* Wk    = (const float*)d_in[3];
    const float* bk    = (const float*)d_in[4];
    const float* Wv    = (const float*)d_in[5];
    const float* bv    = (const float*)d_in[6];
    const float* rel_k = (const float*)d_in[7];
    const float* rel_v = (const float*)d_in[8];
    const float* Wo    = (const float*)d_in[9];
    const float* bo    = (const float*)d_in[10];
    const float* gamma = (const float*)d_in[11];
    const float* beta  = (const float*)d_in[12];

    float* y    = (float*)d_out;
    float* attn = (float*)d_out + (size_t)BB * SS * HH;  // attn/scores region

    qkv_kernel<<<dim3(2, 128, 3), 256>>>(x, Wq, bq, Wk, bk, Wv, bv);
    qrel_kernel<<<dim3(3, 128), 256>>>(rel_k);
    scores_kernel<<<dim3(16, 16, 8), 256>>>(attn);
    softmax_kernel<<<NROWS, 256>>>(attn);
    ctx_kernel<<<dim3(2, 16, 8), 256>>>(attn);
    relv_kernel<<<NROWS, 256>>>(attn, rel_v);
    out_ln_kernel<<<NROWS, 128>>>(x, Wo, bo, gamma, beta, y);
}

// round 2
// speedup vs baseline: 1.1734x; 1.1734x over previous
#include <cuda_runtime.h>
#include <math.h>

#define BB 8
#define SS 1024
#define HH 128
#define PP 129
#define PPAD 160
#define NROWS (BB*SS)   // 8192
#define SL 132          // smem row stride (floats), 16B-aligned rows, 4-way-max STS conflicts

typedef unsigned long long ull;

// -------- device scratch (no allocations allowed) --------
__device__ float g_q[NROWS*HH];
__device__ float g_k[NROWS*HH];
__device__ float g_v[NROWS*HH];
__device__ float g_ctx[NROWS*HH];
__device__ float g_qrel[NROWS*PP];
__device__ float g_arel[NROWS*PPAD];

// ---------------- f32x2 helpers ----------------
__device__ __forceinline__ ull bcast2(float x) {
    unsigned int u = __float_as_uint(x);
    ull r;
    asm("mov.b64 %0, {%1, %2};" : "=l"(r) : "r"(u), "r"(u));
    return r;
}
__device__ __forceinline__ void ffma2(ull& c, ull a, ull b) {
    asm("fma.rn.f32x2 %0, %1, %2, %0;" : "+l"(c) : "l"(a), "l"(b));
}
__device__ __forceinline__ float2 up2(ull v) {
    unsigned int lo, hi;
    asm("mov.b64 {%0, %1}, %2;" : "=r"(lo), "=r"(hi) : "l"(v));
    return make_float2(__uint_as_float(lo), __uint_as_float(hi));
}

// ---------------- staging helpers ----------------
// 128 rows x 32 k, transposed into As[k][m] (also used for NT B tiles). 256 threads.
__device__ __forceinline__ void stageT128(const float* __restrict__ A, int lda,
                                          int m0, int kc, int tid, float* As) {
    #pragma unroll
    for (int i = 0; i < 4; i++) {
        int idx = tid + i*256;
        int r = idx >> 3, kq = idx & 7;
        float4 v = *(const float4*)(A + (size_t)(m0 + r)*lda + kc + kq*4);
        As[(kq*4+0)*SL + r] = v.x; As[(kq*4+1)*SL + r] = v.y;
        As[(kq*4+2)*SL + r] = v.z; As[(kq*4+3)*SL + r] = v.w;
    }
}
// 32 k x 128 n (NN B), 256 threads
__device__ __forceinline__ void stageNN128(const float* __restrict__ B, int ldb,
                                           int n0, int kc, int tid, float* Bs) {
    #pragma unroll
    for (int i = 0; i < 4; i++) {
        int idx = tid + i*256;
        int kr = idx >> 5, nq = idx & 31;
        *(float4*)&Bs[kr*SL + nq*4] = *(const float4*)(B + (size_t)(kc + kr)*ldb + n0 + nq*4);
    }
}
// 64 rows x 32 k transposed, 128 threads
__device__ __forceinline__ void stageT64(const float* __restrict__ A, int lda,
                                         int m0, int kc, int tid, float* As) {
    #pragma unroll
    for (int i = 0; i < 4; i++) {
        int idx = tid + i*128;
        int r = idx >> 3, kq = idx & 7;
        float4 v = *(const float4*)(A + (size_t)(m0 + r)*lda + kc + kq*4);
        As[(kq*4+0)*SL + r] = v.x; As[(kq*4+1)*SL + r] = v.y;
        As[(kq*4+2)*SL + r] = v.z; As[(kq*4+3)*SL + r] = v.w;
    }
}
// 32 k x 128 n (NN B), 128 threads
__device__ __forceinline__ void stageNN64t(const float* __restrict__ B, int ldb,
                                           int n0, int kc, int tid, float* Bs) {
    #pragma unroll
    for (int i = 0; i < 8; i++) {
        int idx = tid + i*128;
        int kr = idx >> 5, nq = idx & 31;
        *(float4*)&Bs[kr*SL + nq*4] = *(const float4*)(B + (size_t)(kc + kr)*ldb + n0 + nq*4);
    }
}

// micro step: 8 rows (ty*4.., ah+ty*4..) x 8 cols (tx*4.., 64+tx*4..)
__device__ __forceinline__ void micro8x8(const float* __restrict__ ak,
                                         const float* __restrict__ bk,
                                         int tx, int ty, int ah, ull (&c2)[8][4]) {
    float4 a0 = *(const float4*)(ak + ty*4);
    float4 a1 = *(const float4*)(ak + ah + ty*4);
    ulonglong2 b0 = *(const ulonglong2*)(bk + tx*4);
    ulonglong2 b1 = *(const ulonglong2*)(bk + 64 + tx*4);
    ull aa[8] = {bcast2(a0.x), bcast2(a0.y), bcast2(a0.z), bcast2(a0.w),
                 bcast2(a1.x), bcast2(a1.y), bcast2(a1.z), bcast2(a1.w)};
    ull bb[4] = {b0.x, b0.y, b1.x, b1.y};
    #pragma unroll
    for (int i = 0; i < 8; i++)
        #pragma unroll
        for (int j = 0; j < 4; j++)
            ffma2(c2[i][j], aa[i], bb[j]);
}

// ============================================================
// K1: q/k/v = x@W + b. tile 128x128, grid (64,3), 256 thr
// ============================================================
__global__ __launch_bounds__(256) void qkv_gemm(
    const float* __restrict__ x,
    const float* __restrict__ Wq, const float* __restrict__ bq,
    const float* __restrict__ Wk, const float* __restrict__ bk,
    const float* __restrict__ Wv, const float* __restrict__ bv)
{
    __shared__ float As[32*SL], Bs[32*SL];
    int z = blockIdx.y;
    const float* W    = (z == 0) ? Wq : (z == 1) ? Wk : Wv;
    const float* bias = (z == 0) ? bq : (z == 1) ? bk : bv;
    float* out        = (z == 0) ? g_q : (z == 1) ? g_k : g_v;
    int m0 = blockIdx.x * 128;
    int tid = threadIdx.x, tx = tid & 15, ty = tid >> 4;

    ull c2[8][4];
    ull z2 = bcast2(0.f);
    #pragma unroll
    for (int i = 0; i < 8; i++) for (int j = 0; j < 4; j++) c2[i][j] = z2;

    for (int kc = 0; kc < HH; kc += 32) {
        stageT128(x, HH, m0, kc, tid, As);
        stageNN128(W, HH, 0, kc, tid, Bs);
        __syncthreads();
        #pragma unroll 4
        for (int kk = 0; kk < 32; kk++)
            micro8x8(As + kk*SL, Bs + kk*SL, tx, ty, 64, c2);
        __syncthreads();
    }
    float4 bv0 = *(const float4*)&bias[tx*4];
    float4 bv1 = *(const float4*)&bias[64 + tx*4];
    float bvals[8] = {bv0.x, bv0.y, bv0.z, bv0.w, bv1.x, bv1.y, bv1.z, bv1.w};
    #pragma unroll
    for (int i = 0; i < 8; i++) {
        int row = m0 + ((i < 4) ? ty*4 + i : 64 + ty*4 + i - 4);
        #pragma unroll
        for (int jp = 0; jp < 4; jp++) {
            float2 f = up2(c2[i][jp]);
            int j0 = jp*2;
            int col = (j0 < 4) ? tx*4 + j0 : 64 + tx*4 + j0 - 4;
            *(float2*)&out[(size_t)row*HH + col] =
                make_float2(f.x + bvals[j0], f.y + bvals[j0+1]);
        }
    }
}

// ============================================================
// K2: qrel = q @ rel_k^T (129 cols: 128 via GEMM + col128 extra)
// tile 128x128, grid (64), 256 thr
// ============================================================
__global__ __launch_bounds__(256) void qrel_gemm(const float* __restrict__ rel_k)
{
    __shared__ float As[32*SL], Bs[32*SL];
    __shared__ float rk[32];
    int m0 = blockIdx.x * 128;
    int tid = threadIdx.x, tx = tid & 15, ty = tid >> 4;

    ull c2[8][4];
    ull z2 = bcast2(0.f);
    #pragma unroll
    for (int i = 0; i < 8; i++) for (int j = 0; j < 4; j++) c2[i][j] = z2;
    float ce[8] = {};

    for (int kc = 0; kc < HH; kc += 32) {
        stageT128(g_q, HH, m0, kc, tid, As);
        stageT128(rel_k, HH, 0, kc, tid, Bs);   // NT: rows of rel_k (0..127)
        if (tid < 32) rk[tid] = rel_k[(size_t)128*HH + kc + tid];
        __syncthreads();
        #pragma unroll 4
        for (int kk = 0; kk < 32; kk++) {
            const float* ak = As + kk*SL;
            const float* bk = Bs + kk*SL;
            float4 a0 = *(const float4*)(ak + ty*4);
            float4 a1 = *(const float4*)(ak + 64 + ty*4);
            ulonglong2 b0 = *(const ulonglong2*)(bk + tx*4);
            ulonglong2 b1 = *(const ulonglong2*)(bk + 64 + tx*4);
            ull aa[8] = {bcast2(a0.x), bcast2(a0.y), bcast2(a0.z), bcast2(a0.w),
                         bcast2(a1.x), bcast2(a1.y), bcast2(a1.z), bcast2(a1.w)};
            ull bb[4] = {b0.x, b0.y, b1.x, b1.y};
            #pragma unroll
            for (int i = 0; i < 8; i++)
                #pragma unroll
                for (int j = 0; j < 4; j++)
                    ffma2(c2[i][j], aa[i], bb[j]);
            float rkv = rk[kk];
            float av[8] = {a0.x, a0.y, a0.z, a0.w, a1.x, a1.y, a1.z, a1.w};
            #pragma unroll
            for (int i = 0; i < 8; i++) ce[i] += av[i] * rkv;
        }
        __syncthreads();
    }
    #pragma unroll
    for (int i = 0; i < 8; i++) {
        int row = m0 + ((i < 4) ? ty*4 + i : 64 + ty*4 + i - 4);
        #pragma unroll
        for (int jp = 0; jp < 4; jp++) {
            float2 f = up2(c2[i][jp]);
            int j0 = jp*2;
            int col = (j0 < 4) ? tx*4 + j0 : 64 + tx*4 + j0 - 4;
            g_qrel[(size_t)row*PP + col]     = f.x;
            g_qrel[(size_t)row*PP + col + 1] = f.y;
        }
        if (tx == 0) g_qrel[(size_t)row*PP + 128] = ce[i];
    }
}

// ============================================================
// K3: scores[b] = q[b]@k[b]^T/sqrt(H) + qrel lookup
// tile 128x128, grid (8,8,8), 256 thr
// ============================================================
__global__ __launch_bounds__(256) void scores_gemm(float* __restrict__ scores)
{
    __shared__ float As[32*SL], Bs[32*SL];
    int b = blockIdx.z;
    const float* A  = g_q + (size_t)b*SS*HH;
    const float* Bm = g_k + (size_t)b*SS*HH;
    int m0 = blockIdx.y * 128;
    int n0 = blockIdx.x * 128;
    int tid = threadIdx.x, tx = tid & 15, ty = tid >> 4;

    ull c2[8][4];
    ull z2 = bcast2(0.f);
    #pragma unroll
    for (int i = 0; i < 8; i++) for (int j = 0; j < 4; j++) c2[i][j] = z2;

    for (int kc = 0; kc < HH; kc += 32) {
        stageT128(A, HH, m0, kc, tid, As);
        stageT128(Bm, HH, n0, kc, tid, Bs);   // NT
        __syncthreads();
        #pragma unroll 4
        for (int kk = 0; kk < 32; kk++)
            micro8x8(As + kk*SL, Bs + kk*SL, tx, ty, 64, c2);
        __syncthreads();
    }
    const float invscale = 0.08838834764831845f;
    #pragma unroll
    for (int i = 0; i < 8; i++) {
        int row = m0 + ((i < 4) ? ty*4 + i : 64 + ty*4 + i - 4);
        const float* qr = g_qrel + ((size_t)b*SS + row)*PP;
        float* sr = scores + ((size_t)b*SS + row)*SS;
        #pragma unroll
        for (int jp = 0; jp < 4; jp++) {
            float2 f = up2(c2[i][jp]);
            int j0 = jp*2;
            int col = n0 + ((j0 < 4) ? tx*4 + j0 : 64 + tx*4 + j0 - 4);
            int d0 = col - row;     d0 = (d0 < -64) ? -64 : (d0 > 64) ? 64 : d0;
            int d1 = col + 1 - row; d1 = (d1 < -64) ? -64 : (d1 > 64) ? 64 : d1;
            *(float2*)&sr[col] = make_float2(f.x*invscale + qr[d0 + 64],
                                             f.y*invscale + qr[d1 + 64]);
        }
    }
}

// ============================================================
// K4: softmax, register-resident. grid 8192, 256 thr
// ============================================================
__global__ __launch_bounds__(256) void softmax_kernel(float* __restrict__ scores)
{
    __shared__ float sm[8];
    int r = blockIdx.x, tid = threadIdx.x;
    float* sr = scores + (size_t)r * SS;
    int lane = tid & 31, wid = tid >> 5;

    float v[4];
    #pragma unroll
    for (int t = 0; t < 4; t++) v[t] = sr[tid + t*256];

    float m = fmaxf(fmaxf(v[0], v[1]), fmaxf(v[2], v[3]));
    #pragma unroll
    for (int o = 16; o > 0; o >>= 1) m = fmaxf(m, __shfl_xor_sync(0xffffffffu, m, o));
    if (lane == 0) sm[wid] = m;
    __syncthreads();
    m = sm[0];
    #pragma unroll
    for (int w = 1; w < 8; w++) m = fmaxf(m, sm[w]);
    __syncthreads();

    float s = 0.f;
    #pragma unroll
    for (int t = 0; t < 4; t++) { v[t] = __expf(v[t] - m); s += v[t]; }
    #pragma unroll
    for (int o = 16; o > 0; o >>= 1) s += __shfl_xor_sync(0xffffffffu, s, o);
    if (lane == 0) sm[wid] = s;
    __syncthreads();
    s = sm[0] + sm[1] + sm[2] + sm[3] + sm[4] + sm[5] + sm[6] + sm[7];
    float inv = 1.0f / s;
    #pragma unroll
    for (int t = 0; t < 4; t++) sr[tid + t*256] = v[t] * inv;
}

// ============================================================
// K5: arel[r, p] extraction from attn rows. grid 8192, 256 thr
// ============================================================
__global__ __launch_bounds__(256) void arel_kernel(const float* __restrict__ attn)
{
    __shared__ float arw[PP];
    __shared__ float sred[16];
    int r = blockIdx.x, tid = threadIdx.x;
    int i = r & (SS - 1);
    const float* row = attn + (size_t)r * SS;
    int lane = tid & 31, wid = tid >> 5;

    if (tid < 127) arw[tid + 1] = 0.f;
    __syncthreads();

    float slo = 0.f, shi = 0.f;
    #pragma unroll
    for (int t = 0; t < 4; t++) {
        int j = tid + t*256;
        float val = row[j];
        int d = j - i;
        if (d <= -64) slo += val;
        else if (d >= 64) shi += val;
        else arw[d + 64] = val;
    }
    #pragma unroll
    for (int o = 16; o > 0; o >>= 1) {
        slo += __shfl_xor_sync(0xffffffffu, slo, o);
        shi += __shfl_xor_sync(0xffffffffu, shi, o);
    }
    if (lane == 0) { sred[wid] = slo; sred[8 + wid] = shi; }
    __syncthreads();
    if (tid == 0) {
        float a = 0.f, b = 0.f;
        #pragma unroll
        for (int w = 0; w < 8; w++) { a += sred[w]; b += sred[8 + w]; }
        arw[0] = a; arw[128] = b;
    }
    __syncthreads();
    if (tid < PPAD) g_arel[(size_t)r*PPAD + tid] = (tid < PP) ? arw[tid] : 0.f;
}

// ============================================================
// K6: ctx[b] = attn[b] @ v[b]. tile 64x128, grid (16,8), 128 thr
// ============================================================
__global__ __launch_bounds__(128) void ctx_gemm(const float* __restrict__ attn)
{
    __shared__ float As[32*SL], Bs[32*SL];
    int b = blockIdx.y;
    const float* A  = attn + (size_t)b*SS*SS;
    const float* Bm = g_v  + (size_t)b*SS*HH;
    float* out = g_ctx + (size_t)b*SS*HH;
    int m0 = blockIdx.x * 64;
    int tid = threadIdx.x, tx = tid & 15, ty = tid >> 4;  // ty 0..7

    ull c2[8][4];
    ull z2 = bcast2(0.f);
    #pragma unroll
    for (int i = 0; i < 8; i++) for (int j = 0; j < 4; j++) c2[i][j] = z2;

    for (int kc = 0; kc < SS; kc += 32) {
        stageT64(A, SS, m0, kc, tid, As);
        stageNN64t(Bm, HH, 0, kc, tid, Bs);
        __syncthreads();
        #pragma unroll 4
        for (int kk = 0; kk < 32; kk++)
            micro8x8(As + kk*SL, Bs + kk*SL, tx, ty, 32, c2);
        __syncthreads();
    }
    #pragma unroll
    for (int i = 0; i < 8; i++) {
        int row = m0 + ((i < 4) ? ty*4 + i : 32 + ty*4 + i - 4);
        #pragma unroll
        for (int jp = 0; jp < 4; jp++) {
            float2 f = up2(c2[i][jp]);
            int j0 = jp*2;
            int col = (j0 < 4) ? tx*4 + j0 : 64 + tx*4 + j0 - 4;
            *(float2*)&out[(size_t)row*HH + col] = f;
        }
    }
}

// ============================================================
// K7: ctx += arel @ rel_v. tile 128x128, grid (64), 256 thr, K=160 padded
// ============================================================
__global__ __launch_bounds__(256) void relv_gemm(const float* __restrict__ rel_v)
{
    __shared__ float As[32*SL], Bs[32*SL];
    int m0 = blockIdx.x * 128;
    int tid = threadIdx.x, tx = tid & 15, ty = tid >> 4;

    ull c2[8][4];
    ull z2 = bcast2(0.f);
    #pragma unroll
    for (int i = 0; i < 8; i++) for (int j = 0; j < 4; j++) c2[i][j] = z2;

    for (int kc = 0; kc < PPAD; kc += 32) {
        stageT128(g_arel, PPAD, m0, kc, tid, As);
        // guarded NN stage of rel_v (only 129 valid rows)
        #pragma unroll
        for (int i = 0; i < 4; i++) {
            int idx = tid + i*256;
            int kr = idx >> 5, nq = idx & 31;
            int krow = kc + kr;
            float4 v = make_float4(0.f, 0.f, 0.f, 0.f);
            if (krow < PP) v = *(const float4*)(rel_v + (size_t)krow*HH + nq*4);
            *(float4*)&Bs[kr*SL + nq*4] = v;
        }
        __syncthreads();
        #pragma unroll 4
        for (int kk = 0; kk < 32; kk++)
            micro8x8(As + kk*SL, Bs + kk*SL, tx, ty, 64, c2);
        __syncthreads();
    }
    #pragma unroll
    for (int i = 0; i < 8; i++) {
        int row = m0 + ((i < 4) ? ty*4 + i : 64 + ty*4 + i - 4);
        #pragma unroll
        for (int jp = 0; jp < 4; jp++) {
            float2 f = up2(c2[i][jp]);
            int j0 = jp*2;
            int col = (j0 < 4) ? tx*4 + j0 : 64 + tx*4 + j0 - 4;
            float2 old = *(float2*)&g_ctx[(size_t)row*HH + col];
            *(float2*)&g_ctx[(size_t)row*HH + col] =
                make_float2(old.x + f.x, old.y + f.y);
        }
    }
}

// ============================================================
// K8: out = ctx@Wo + bo; y = LN(out + x). tile 64x128, grid (128), 128 thr
// ============================================================
__global__ __launch_bounds__(128) void outln_gemm(
    const float* __restrict__ x, const float* __restrict__ Wo,
    const float* __restrict__ bo, const float* __restrict__ gamma,
    const float* __restrict__ beta, float* __restrict__ y)
{
    __shared__ float As[32*SL], Bs[32*SL];
    int m0 = blockIdx.x * 64;
    int tid = threadIdx.x, tx = tid & 15, ty = tid >> 4;

    ull c2[8][4];
    ull z2 = bcast2(0.f);
    #pragma unroll
    for (int i = 0; i < 8; i++) for (int j = 0; j < 4; j++) c2[i][j] = z2;

    for (int kc = 0; kc < HH; kc += 32) {
        stageT64(g_ctx, HH, m0, kc, tid, As);
        stageNN64t(Wo, HH, 0, kc, tid, Bs);
        __syncthreads();
        #pragma unroll 4
        for (int kk = 0; kk < 32; kk++)
            micro8x8(As + kk*SL, Bs + kk*SL, tx, ty, 32, c2);
        __syncthreads();
    }

    float4 b0 = *(const float4*)&bo[tx*4];
    float4 b1 = *(const float4*)&bo[64 + tx*4];
    float4 g0 = *(const float4*)&gamma[tx*4];
    float4 g1 = *(const float4*)&gamma[64 + tx*4];
    float4 e0 = *(const float4*)&beta[tx*4];
    float4 e1 = *(const float4*)&beta[64 + tx*4];
    float bv[8] = {b0.x,b0.y,b0.z,b0.w,b1.x,b1.y,b1.z,b1.w};
    float gv[8] = {g0.x,g0.y,g0.z,g0.w,g1.x,g1.y,g1.z,g1.w};
    float ev[8] = {e0.x,e0.y,e0.z,e0.w,e1.x,e1.y,e1.z,e1.w};

    #pragma unroll
    for (int i = 0; i < 8; i++) {
        int row = m0 + ((i < 4) ? ty*4 + i : 32 + ty*4 + i - 4);
        float4 x0 = *(const float4*)&x[(size_t)row*HH + tx*4];
        float4 x1 = *(const float4*)&x[(size_t)row*HH + 64 + tx*4];
        float xv[8] = {x0.x,x0.y,x0.z,x0.w,x1.x,x1.y,x1.z,x1.w};
        float yv[8];
        float s = 0.f;
        #pragma unroll
        for (int jp = 0; jp < 4; jp++) {
            float2 f = up2(c2[i][jp]);
            yv[jp*2]   = f.x + bv[jp*2]   + xv[jp*2];
            yv[jp*2+1] = f.y + bv[jp*2+1] + xv[jp*2+1];
            s += yv[jp*2] + yv[jp*2+1];
        }
        #pragma unroll
        for (int o = 1; o < 16; o <<= 1) s += __shfl_xor_sync(0xffffffffu, s, o, 16);
        float mu = s * (1.0f / HH);
        float q = 0.f;
        #pragma unroll
        for (int j = 0; j < 8; j++) { yv[j] -= mu; q += yv[j]*yv[j]; }
        #pragma unroll
        for (int o = 1; o < 16; o <<= 1) q += __shfl_xor_sync(0xffffffffu, q, o, 16);
        float rstd = rsqrtf(q * (1.0f / HH) + 1e-5f);
        #pragma unroll
        for (int jp = 0; jp < 4; jp++) {
            int j0 = jp*2;
            int col = (j0 < 4) ? tx*4 + j0 : 64 + tx*4 + j0 - 4;
            *(float2*)&y[(size_t)row*HH + col] =
                make_float2(yv[j0]*rstd*gv[j0] + ev[j0],
                            yv[j0+1]*rstd*gv[j0+1] + ev[j0+1]);
        }
    }
}

// ============================================================
extern "C" void kernel_launch(void* const* d_in, const int* in_sizes, int n_in,
                              void* d_out, int out_size)
{
    const float* x     = (const float*)d_in[0];
    const float* Wq    = (const float*)d_in[1];
    const float* bq    = (const float*)d_in[2];
    const float* Wk    = (const float*)d_in[3];
    const float* bk    = (const float*)d_in[4];
    const float* Wv    = (const float*)d_in[5];
    const float* bv    = (const float*)d_in[6];
    const float* rel_k = (const float*)d_in[7];
    const float* rel_v = (const float*)d_in[8];
    const float* Wo    = (const float*)d_in[9];
    const float* bo    = (const float*)d_in[10];
    const float* gamma = (const float*)d_in[11];
    const float* beta  = (const float*)d_in[12];

    float* y    = (float*)d_out;
    float* attn = (float*)d_out + (size_t)BB * SS * HH;

    qkv_gemm<<<dim3(64, 3), 256>>>(x, Wq, bq, Wk, bk, Wv, bv);
    qrel_gemm<<<64, 256>>>(rel_k);
    scores_gemm<<<dim3(8, 8, 8), 256>>>(attn);
    softmax_kernel<<<NROWS, 256>>>(attn);
    arel_kernel<<<NROWS, 256>>>(attn);
    ctx_gemm<<<dim3(16, 8), 128>>>(attn);
    relv_gemm<<<64, 256>>>(rel_v);
    outln_gemm<<<128, 128>>>(x, Wo, bo, gamma, beta, y);
}

// round 4
// speedup vs baseline: 1.2027x; 1.0250x over previous
#include <cuda_runtime.h>
#include <math.h>

#define BB 8
#define SS 1024
#define HH 128
#define PP 129
#define QSTR 132        // g_qrel row stride (16B-aligned rows)
#define PPAD 160
#define NROWS (BB*SS)   // 8192
#define KC 16           // K-chunk
#define SLA 260         // dup-A smem row stride (floats), 128-row tiles
#define SLA64 132       // dup-A stride, 64-row tiles
#define SLB 132         // B smem row stride

typedef unsigned long long ull;

// -------- device scratch --------
__device__ float g_q[NROWS*HH];
__device__ float g_k[NROWS*HH];
__device__ float g_v[NROWS*HH];
__device__ float g_ctx[NROWS*HH];
__device__ float g_qrel[NROWS*QSTR];
__device__ float g_arel[NROWS*PPAD];

// ---------------- f32x2 helpers ----------------
__device__ __forceinline__ ull bcast2(float x) {
    unsigned int u = __float_as_uint(x);
    ull r;
    asm("mov.b64 %0, {%1, %2};" : "=l"(r) : "r"(u), "r"(u));
    return r;
}
__device__ __forceinline__ void ffma2(ull& c, ull a, ull b) {
    asm("fma.rn.f32x2 %0, %1, %2, %0;" : "+l"(c) : "l"(a), "l"(b));
}
__device__ __forceinline__ float2 up2(ull v) {
    unsigned int lo, hi;
    asm("mov.b64 {%0, %1}, %2;" : "=r"(lo), "=r"(hi) : "l"(v));
    return make_float2(__uint_as_float(lo), __uint_as_float(hi));
}
__device__ __forceinline__ float lo2f(ull v) {
    unsigned int lo, hi;
    asm("mov.b64 {%0, %1}, %2;" : "=r"(lo), "=r"(hi) : "l"(v));
    return __uint_as_float(lo);
}

// micro step with duplicated-A smem: 8 rows x 8 cols per thread.
__device__ __forceinline__ void micro_dup(const float* __restrict__ akd,
                                          const float* __restrict__ bk,
                                          int tx, int ty, int ah, ull (&c2)[8][4]) {
    ulonglong2 a01 = *(const ulonglong2*)(akd + 8*ty);
    ulonglong2 a23 = *(const ulonglong2*)(akd + 8*ty + 4);
    ulonglong2 a45 = *(const ulonglong2*)(akd + 2*ah + 8*ty);
    ulonglong2 a67 = *(const ulonglong2*)(akd + 2*ah + 8*ty + 4);
    ulonglong2 b0 = *(const ulonglong2*)(bk + tx*4);
    ulonglong2 b1 = *(const ulonglong2*)(bk + 64 + tx*4);
    ull aa[8] = {a01.x, a01.y, a23.x, a23.y, a45.x, a45.y, a67.x, a67.y};
    ull bb[4] = {b0.x, b0.y, b1.x, b1.y};
    #pragma unroll
    for (int i = 0; i < 8; i++)
        #pragma unroll
        for (int j = 0; j < 4; j++)
            ffma2(c2[i][j], aa[i], bb[j]);
}

// ============================================================
// K1: q/k/v = x@W + b. tile 128x128, grid (64,3), 256 thr
// ============================================================
__global__ __launch_bounds__(256) void qkv_gemm(
    const float* __restrict__ x,
    const float* __restrict__ Wq, const float* __restrict__ bq,
    const float* __restrict__ Wk, const float* __restrict__ bk,
    const float* __restrict__ Wv, const float* __restrict__ bv)
{
    __shared__ __align__(16) float As[KC*SLA];
    __shared__ __align__(16) float Bs[KC*SLB];
    int z = blockIdx.y;
    const float* W    = (z == 0) ? Wq : (z == 1) ? Wk : Wv;
    const float* bias = (z == 0) ? bq : (z == 1) ? bk : bv;
    float* out        = (z == 0) ? g_q : (z == 1) ? g_k : g_v;
    int m0 = blockIdx.x * 128;
    int tid = threadIdx.x, tx = tid & 15, ty = tid >> 4;

    int ra[2], kqa[2], krb[2], nqb[2];
    #pragma unroll
    for (int i = 0; i < 2; i++) {
        int idx = tid + i*256;
        ra[i] = idx >> 2; kqa[i] = idx & 3;
        krb[i] = idx >> 5; nqb[i] = idx & 31;
    }

    ull c2[8][4];
    ull z2 = bcast2(0.f);
    #pragma unroll
    for (int i = 0; i < 8; i++) for (int j = 0; j < 4; j++) c2[i][j] = z2;

    float4 pa[2], pb[2];
    #pragma unroll
    for (int i = 0; i < 2; i++) {
        pa[i] = *(const float4*)(x + (size_t)(m0 + ra[i])*HH + kqa[i]*4);
        pb[i] = *(const float4*)(W + (size_t)krb[i]*HH + nqb[i]*4);
    }
    for (int kc = 0; kc < HH; kc += KC) {
        #pragma unroll
        for (int i = 0; i < 2; i++) {
            float* d = &As[(kqa[i]*4)*SLA + 2*ra[i]];
            *(float2*)(d + 0*SLA) = make_float2(pa[i].x, pa[i].x);
            *(float2*)(d + 1*SLA) = make_float2(pa[i].y, pa[i].y);
            *(float2*)(d + 2*SLA) = make_float2(pa[i].z, pa[i].z);
            *(float2*)(d + 3*SLA) = make_float2(pa[i].w, pa[i].w);
            *(float4*)&Bs[krb[i]*SLB + nqb[i]*4] = pb[i];
        }
        __syncthreads();
        if (kc + KC < HH) {
            #pragma unroll
            for (int i = 0; i < 2; i++) {
                pa[i] = *(const float4*)(x + (size_t)(m0 + ra[i])*HH + kc + KC + kqa[i]*4);
                pb[i] = *(const float4*)(W + (size_t)(kc + KC + krb[i])*HH + nqb[i]*4);
            }
        }
        #pragma unroll
        for (int kk = 0; kk < KC; kk++)
            micro_dup(As + kk*SLA, Bs + kk*SLB, tx, ty, 64, c2);
        __syncthreads();
    }
    float4 bv0 = *(const float4*)&bias[tx*4];
    float4 bv1 = *(const float4*)&bias[64 + tx*4];
    #pragma unroll
    for (int i = 0; i < 8; i++) {
        int row = m0 + ((i < 4) ? ty*4 + i : 64 + ty*4 + i - 4);
        float2 f0 = up2(c2[i][0]), f1 = up2(c2[i][1]);
        float2 f2 = up2(c2[i][2]), f3 = up2(c2[i][3]);
        *(float4*)&out[(size_t)row*HH + tx*4] =
            make_float4(f0.x + bv0.x, f0.y + bv0.y, f1.x + bv0.z, f1.y + bv0.w);
        *(float4*)&out[(size_t)row*HH + 64 + tx*4] =
            make_float4(f2.x + bv1.x, f2.y + bv1.y, f3.x + bv1.z, f3.y + bv1.w);
    }
}

// ============================================================
// K2: qrel = q @ rel_k^T. tile 64x(128+1), grid (128), 128 thr
// ============================================================
__global__ __launch_bounds__(128) void qrel_gemm(const float* __restrict__ rel_k)
{
    __shared__ __align__(16) float As[KC*SLA64];
    __shared__ __align__(16) float Bs[KC*SLB];
    __shared__ float rk[KC];
    int m0 = blockIdx.x * 64;
    int tid = threadIdx.x, tx = tid & 15, ty = tid >> 4;  // ty 0..7

    int ra[2], kqa[2], rb[4], kqb[4];
    #pragma unroll
    for (int i = 0; i < 2; i++) { int idx = tid + i*128; ra[i] = idx >> 2; kqa[i] = idx & 3; }
    #pragma unroll
    for (int i = 0; i < 4; i++) { int idx = tid + i*128; rb[i] = idx >> 2; kqb[i] = idx & 3; }

    ull c2[8][4];
    ull z2 = bcast2(0.f);
    #pragma unroll
    for (int i = 0; i < 8; i++) for (int j = 0; j < 4; j++) c2[i][j] = z2;
    float ce[8] = {};

    float4 pa[2], pb[4];
    float prk = (tid < KC) ? rel_k[(size_t)128*HH + tid] : 0.f;
    #pragma unroll
    for (int i = 0; i < 2; i++)
        pa[i] = *(const float4*)(g_q + (size_t)(m0 + ra[i])*HH + kqa[i]*4);
    #pragma unroll
    for (int i = 0; i < 4; i++)
        pb[i] = *(const float4*)(rel_k + (size_t)rb[i]*HH + kqb[i]*4);

    for (int kc = 0; kc < HH; kc += KC) {
        #pragma unroll
        for (int i = 0; i < 2; i++) {
            float* d = &As[(kqa[i]*4)*SLA64 + 2*ra[i]];
            *(float2*)(d + 0*SLA64) = make_float2(pa[i].x, pa[i].x);
            *(float2*)(d + 1*SLA64) = make_float2(pa[i].y, pa[i].y);
            *(float2*)(d + 2*SLA64) = make_float2(pa[i].z, pa[i].z);
            *(float2*)(d + 3*SLA64) = make_float2(pa[i].w, pa[i].w);
        }
        #pragma unroll
        for (int i = 0; i < 4; i++) {
            Bs[(kqb[i]*4+0)*SLB + rb[i]] = pb[i].x;
            Bs[(kqb[i]*4+1)*SLB + rb[i]] = pb[i].y;
            Bs[(kqb[i]*4+2)*SLB + rb[i]] = pb[i].z;
            Bs[(kqb[i]*4+3)*SLB + rb[i]] = pb[i].w;
        }
        if (tid < KC) rk[tid] = prk;
        __syncthreads();
        if (kc + KC < HH) {
            #pragma unroll
            for (int i = 0; i < 2; i++)
                pa[i] = *(const float4*)(g_q + (size_t)(m0 + ra[i])*HH + kc + KC + kqa[i]*4);
            #pragma unroll
            for (int i = 0; i < 4; i++)
                pb[i] = *(const float4*)(rel_k + (size_t)rb[i]*HH + kc + KC + kqb[i]*4);
            if (tid < KC) prk = rel_k[(size_t)128*HH + kc + KC + tid];
        }
        #pragma unroll
        for (int kk = 0; kk < KC; kk++) {
            const float* akd = As + kk*SLA64;
            const float* bk  = Bs + kk*SLB;
            ulonglong2 a01 = *(const ulonglong2*)(akd + 8*ty);
            ulonglong2 a23 = *(const ulonglong2*)(akd + 8*ty + 4);
            ulonglong2 a45 = *(const ulonglong2*)(akd + 64 + 8*ty);
            ulonglong2 a67 = *(const ulonglong2*)(akd + 64 + 8*ty + 4);
            ulonglong2 b0 = *(const ulonglong2*)(bk + tx*4);
            ulonglong2 b1 = *(const ulonglong2*)(bk + 64 + tx*4);
            ull aa[8] = {a01.x, a01.y, a23.x, a23.y, a45.x, a45.y, a67.x, a67.y};
            ull bb[4] = {b0.x, b0.y, b1.x, b1.y};
            #pragma unroll
            for (int i = 0; i < 8; i++)
                #pragma unroll
                for (int j = 0; j < 4; j++)
                    ffma2(c2[i][j], aa[i], bb[j]);
            float rkv = rk[kk];
            #pragma unroll
            for (int i = 0; i < 8; i++) ce[i] += lo2f(aa[i]) * rkv;
        }
        __syncthreads();
    }
    #pragma unroll
    for (int i = 0; i < 8; i++) {
        int row = m0 + ((i < 4) ? ty*4 + i : 32 + ty*4 + i - 4);
        float2 f0 = up2(c2[i][0]), f1 = up2(c2[i][1]);
        float2 f2 = up2(c2[i][2]), f3 = up2(c2[i][3]);
        float* qr = g_qrel + (size_t)row*QSTR;
        *(float4*)&qr[tx*4]      = make_float4(f0.x, f0.y, f1.x, f1.y);
        *(float4*)&qr[64 + tx*4] = make_float4(f2.x, f2.y, f3.x, f3.y);
        if (tx == 0) qr[128] = ce[i];
    }
}

// ============================================================
// K3: scores[b] = q[b]@k[b]^T/sqrt(H) + qrel. tile 128x128, grid (8,8,8), 256 thr
// ============================================================
__global__ __launch_bounds__(256) void scores_gemm(float* __restrict__ scores)
{
    __shared__ __align__(16) float As[KC*SLA];
    __shared__ __align__(16) float Bs[KC*SLB];
    int b = blockIdx.z;
    const float* A  = g_q + (size_t)b*SS*HH;
    const float* Bm = g_k + (size_t)b*SS*HH;
    int m0 = blockIdx.y * 128;
    int n0 = blockIdx.x * 128;
    int tid = threadIdx.x, tx = tid & 15, ty = tid >> 4;

    int ra[2], kqa[2];
    #pragma unroll
    for (int i = 0; i < 2; i++) { int idx = tid + i*256; ra[i] = idx >> 2; kqa[i] = idx & 3; }

    ull c2[8][4];
    ull z2 = bcast2(0.f);
    #pragma unroll
    for (int i = 0; i < 8; i++) for (int j = 0; j < 4; j++) c2[i][j] = z2;

    float4 pa[2], pb[2];
    #pragma unroll
    for (int i = 0; i < 2; i++) {
        pa[i] = *(const float4*)(A  + (size_t)(m0 + ra[i])*HH + kqa[i]*4);
        pb[i] = *(const float4*)(Bm + (size_t)(n0 + ra[i])*HH + kqa[i]*4);
    }
    for (int kc = 0; kc < HH; kc += KC) {
        #pragma unroll
        for (int i = 0; i < 2; i++) {
            float* d = &As[(kqa[i]*4)*SLA + 2*ra[i]];
            *(float2*)(d + 0*SLA) = make_float2(pa[i].x, pa[i].x);
            *(float2*)(d + 1*SLA) = make_float2(pa[i].y, pa[i].y);
            *(float2*)(d + 2*SLA) = make_float2(pa[i].z, pa[i].z);
            *(float2*)(d + 3*SLA) = make_float2(pa[i].w, pa[i].w);
            Bs[(kqa[i]*4+0)*SLB + ra[i]] = pb[i].x;
            Bs[(kqa[i]*4+1)*SLB + ra[i]] = pb[i].y;
            Bs[(kqa[i]*4+2)*SLB + ra[i]] = pb[i].z;
            Bs[(kqa[i]*4+3)*SLB + ra[i]] = pb[i].w;
        }
        __syncthreads();
        if (kc + KC < HH) {
            #pragma unroll
            for (int i = 0; i < 2; i++) {
                pa[i] = *(const float4*)(A  + (size_t)(m0 + ra[i])*HH + kc + KC + kqa[i]*4);
                pb[i] = *(const float4*)(Bm + (size_t)(n0 + ra[i])*HH + kc + KC + kqa[i]*4);
            }
        }
        #pragma unroll
        for (int kk = 0; kk < KC; kk++)
            micro_dup(As + kk*SLA, Bs + kk*SLB, tx, ty, 64, c2);
        __syncthreads();
    }
    const float invscale = 0.08838834764831845f;
    #pragma unroll
    for (int i = 0; i < 8; i++) {
        int row = m0 + ((i < 4) ? ty*4 + i : 64 + ty*4 + i - 4);
        const float* qr = g_qrel + ((size_t)b*SS + row)*QSTR;
        float* sr = scores + ((size_t)b*SS + row)*SS;
        #pragma unroll
        for (int jp = 0; jp < 4; jp++) {
            float2 f = up2(c2[i][jp]);
            int j0 = jp*2;
            int col = n0 + ((j0 < 4) ? tx*4 + j0 : 64 + tx*4 + j0 - 4);
            int d0 = col - row;     d0 = (d0 < -64) ? -64 : (d0 > 64) ? 64 : d0;
            int d1 = col + 1 - row; d1 = (d1 < -64) ? -64 : (d1 > 64) ? 64 : d1;
            *(float2*)&sr[col] = make_float2(f.x*invscale + qr[d0 + 64],
                                             f.y*invscale + qr[d1 + 64]);
        }
    }
}

// ============================================================
// K4: fused softmax + arel extraction. grid 8192, 256 thr
// ============================================================
__global__ __launch_bounds__(256) void softmax_arel(float* __restrict__ scores)
{
    __shared__ __align__(16) float rowbuf[SS];
    __shared__ float sm[8];
    __shared__ float sred[16];
    __shared__ float stot[2];
    int r = blockIdx.x, tid = threadIdx.x;
    int i = r & (SS - 1);
    float* sr = scores + (size_t)r * SS;
    int lane = tid & 31, wid = tid >> 5;

    float4 v = ((const float4*)sr)[tid];

    float m = fmaxf(fmaxf(v.x, v.y), fmaxf(v.z, v.w));
    #pragma unroll
    for (int o = 16; o > 0; o >>= 1) m = fmaxf(m, __shfl_xor_sync(0xffffffffu, m, o));
    if (lane == 0) sm[wid] = m;
    __syncthreads();
    m = fmaxf(fmaxf(fmaxf(sm[0], sm[1]), fmaxf(sm[2], sm[3])),
              fmaxf(fmaxf(sm[4], sm[5]), fmaxf(sm[6], sm[7])));
    __syncthreads();

    v.x = __expf(v.x - m); v.y = __expf(v.y - m);
    v.z = __expf(v.z - m); v.w = __expf(v.w - m);
    float s = v.x + v.y + v.z + v.w;
    #pragma unroll
    for (int o = 16; o > 0; o >>= 1) s += __shfl_xor_sync(0xffffffffu, s, o);
    if (lane == 0) sm[wid] = s;
    __syncthreads();
    s = sm[0] + sm[1] + sm[2] + sm[3] + sm[4] + sm[5] + sm[6] + sm[7];
    float inv = 1.0f / s;
    v.x *= inv; v.y *= inv; v.z *= inv; v.w *= inv;

    ((float4*)sr)[tid] = v;
    ((float4*)rowbuf)[tid] = v;

    // lo/hi tail sums for arel[0], arel[128]
    int j0 = tid * 4;
    float p[4] = {v.x, v.y, v.z, v.w};
    float slo = 0.f, shi = 0.f;
    #pragma unroll
    for (int t = 0; t < 4; t++) {
        int d = j0 + t - i;
        if (d <= -64) slo += p[t];
        else if (d >= 64) shi += p[t];
    }
    #pragma unroll
    for (int o = 16; o > 0; o >>= 1) {
        slo += __shfl_xor_sync(0xffffffffu, slo, o);
        shi += __shfl_xor_sync(0xffffffffu, shi, o);
    }
    if (lane == 0) { sred[wid] = slo; sred[8 + wid] = shi; }
    __syncthreads();
    if (tid == 0) {
        float a = 0.f, b = 0.f;
        #pragma unroll
        for (int w = 0; w < 8; w++) { a += sred[w]; b += sred[8 + w]; }
        stot[0] = a; stot[1] = b;
    }
    __syncthreads();

    if (tid < PPAD) {
        float val;
        if (tid == 0)        val = stot[0];
        else if (tid == 128) val = stot[1];
        else if (tid < 128) {
            int j = i + tid - 64;
            val = (j >= 0 && j < SS) ? rowbuf[j] : 0.f;
        } else val = 0.f;
        g_arel[(size_t)r*PPAD + tid] = val;
    }
}

// ============================================================
// K5: ctx[b] = attn[b] @ v[b]. tile 64x128, grid (16,8), 128 thr
// ============================================================
__global__ __launch_bounds__(128) void ctx_gemm(const float* __restrict__ attn)
{
    __shared__ __align__(16) float As[KC*SLA64];
    __shared__ __align__(16) float Bs[KC*SLB];
    int b = blockIdx.y;
    const float* A  = attn + (size_t)b*SS*SS;
    const float* Bm = g_v  + (size_t)b*SS*HH;
    float* out = g_ctx + (size_t)b*SS*HH;
    int m0 = blockIdx.x * 64;
    int tid = threadIdx.x, tx = tid & 15, ty = tid >> 4;

    int ra[2], kqa[2], krb[4], nqb[4];
    #pragma unroll
    for (int i = 0; i < 2; i++) { int idx = tid + i*128; ra[i] = idx >> 2; kqa[i] = idx & 3; }
    #pragma unroll
    for (int i = 0; i < 4; i++) { int idx = tid + i*128; krb[i] = idx >> 5; nqb[i] = idx & 31; }

    ull c2[8][4];
    ull z2 = bcast2(0.f);
    #pragma unroll
    for (int i = 0; i < 8; i++) for (int j = 0; j < 4; j++) c2[i][j] = z2;

    float4 pa[2], pb[4];
    #pragma unroll
    for (int i = 0; i < 2; i++)
        pa[i] = *(const float4*)(A + (size_t)(m0 + ra[i])*SS + kqa[i]*4);
    #pragma unroll
    for (int i = 0; i < 4; i++)
        pb[i] = *(const float4*)(Bm + (size_t)krb[i]*HH + nqb[i]*4);

    for (int kc = 0; kc < SS; kc += KC) {
        #pragma unroll
        for (int i = 0; i < 2; i++) {
            float* d = &As[(kqa[i]*4)*SLA64 + 2*ra[i]];
            *(float2*)(d + 0*SLA64) = make_float2(pa[i].x, pa[i].x);
            *(float2*)(d + 1*SLA64) = make_float2(pa[i].y, pa[i].y);
            *(float2*)(d + 2*SLA64) = make_float2(pa[i].z, pa[i].z);
            *(float2*)(d + 3*SLA64) = make_float2(pa[i].w, pa[i].w);
        }
        #pragma unroll
        for (int i = 0; i < 4; i++)
            *(float4*)&Bs[krb[i]*SLB + nqb[i]*4] = pb[i];
        __syncthreads();
        if (kc + KC < SS) {
            #pragma unroll
            for (int i = 0; i < 2; i++)
                pa[i] = *(const float4*)(A + (size_t)(m0 + ra[i])*SS + kc + KC + kqa[i]*4);
            #pragma unroll
            for (int i = 0; i < 4; i++)
                pb[i] = *(const float4*)(Bm + (size_t)(kc + KC + krb[i])*HH + nqb[i]*4);
        }
        #pragma unroll
        for (int kk = 0; kk < KC; kk++)
            micro_dup(As + kk*SLA64, Bs + kk*SLB, tx, ty, 32, c2);
        __syncthreads();
    }
    #pragma unroll
    for (int i = 0; i < 8; i++) {
        int row = m0 + ((i < 4) ? ty*4 + i : 32 + ty*4 + i - 4);
        float2 f0 = up2(c2[i][0]), f1 = up2(c2[i][1]);
        float2 f2 = up2(c2[i][2]), f3 = up2(c2[i][3]);
        *(float4*)&out[(size_t)row*HH + tx*4]      = make_float4(f0.x, f0.y, f1.x, f1.y);
        *(float4*)&out[(size_t)row*HH + 64 + tx*4] = make_float4(f2.x, f2.y, f3.x, f3.y);
    }
}

// ============================================================
// K6: ctx += arel @ rel_v. tile 64x128, grid (128), 128 thr, K=160
// ============================================================
__global__ __launch_bounds__(128) void relv_gemm(const float* __restrict__ rel_v)
{
    __shared__ __align__(16) float As[KC*SLA64];
    __shared__ __align__(16) float Bs[KC*SLB];
    int m0 = blockIdx.x * 64;
    int tid = threadIdx.x, tx = tid & 15, ty = tid >> 4;

    int ra[2], kqa[2], krb[4], nqb[4];
    #pragma unroll
    for (int i = 0; i < 2; i++) { int idx = tid + i*128; ra[i] = idx >> 2; kqa[i] = idx & 3; }
    #pragma unroll
    for (int i = 0; i < 4; i++) { int idx = tid + i*128; krb[i] = idx >> 5; nqb[i] = idx & 31; }

    ull c2[8][4];
    ull z2 = bcast2(0.f);
    #pragma unroll
    for (int i = 0; i < 8; i++) for (int j = 0; j < 4; j++) c2[i][j] = z2;

    float4 pa[2], pb[4];
    #pragma unroll
    for (int i = 0; i < 2; i++)
        pa[i] = *(const float4*)(g_arel + (size_t)(m0 + ra[i])*PPAD + kqa[i]*4);
    #pragma unroll
    for (int i = 0; i < 4; i++)
        pb[i] = (krb[i] < PP) ? *(const float4*)(rel_v + (size_t)krb[i]*HH + nqb[i]*4)
                              : make_float4(0.f, 0.f, 0.f, 0.f);

    for (int kc = 0; kc < PPAD; kc += KC) {
        #pragma unroll
        for (int i = 0; i < 2; i++) {
            float* d = &As[(kqa[i]*4)*SLA64 + 2*ra[i]];
            *(float2*)(d + 0*SLA64) = make_float2(pa[i].x, pa[i].x);
            *(float2*)(d + 1*SLA64) = make_float2(pa[i].y, pa[i].y);
            *(float2*)(d + 2*SLA64) = make_float2(pa[i].z, pa[i].z);
            *(float2*)(d + 3*SLA64) = make_float2(pa[i].w, pa[i].w);
        }
        #pragma unroll
        for (int i = 0; i < 4; i++)
            *(float4*)&Bs[krb[i]*SLB + nqb[i]*4] = pb[i];
        __syncthreads();
        if (kc + KC < PPAD) {
            #pragma unroll
            for (int i = 0; i < 2; i++)
                pa[i] = *(const float4*)(g_arel + (size_t)(m0 + ra[i])*PPAD + kc + KC + kqa[i]*4);
            #pragma unroll
            for (int i = 0; i < 4; i++) {
                int krow = kc + KC + krb[i];
                pb[i] = (krow < PP) ? *(const float4*)(rel_v + (size_t)krow*HH + nqb[i]*4)
                                    : make_float4(0.f, 0.f, 0.f, 0.f);
            }
        }
        #pragma unroll
        for (int kk = 0; kk < KC; kk++)
            micro_dup(As + kk*SLA64, Bs + kk*SLB, tx, ty, 32, c2);
        __syncthreads();
    }
    #pragma unroll
    for (int i = 0; i < 8; i++) {
        int row = m0 + ((i < 4) ? ty*4 + i : 32 + ty*4 + i - 4);
        float2 f0 = up2(c2[i][0]), f1 = up2(c2[i][1]);
        float2 f2 = up2(c2[i][2]), f3 = up2(c2[i][3]);
        float4 o0 = *(float4*)&g_ctx[(size_t)row*HH + tx*4];
        float4 o1 = *(float4*)&g_ctx[(size_t)row*HH + 64 + tx*4];
        *(float4*)&g_ctx[(size_t)row*HH + tx*4] =
            make_float4(o0.x + f0.x, o0.y + f0.y, o0.z + f1.x, o0.w + f1.y);
        *(float4*)&g_ctx[(size_t)row*HH + 64 + tx*4] =
            make_float4(o1.x + f2.x, o1.y + f2.y, o1.z + f3.x, o1.w + f3.y);
    }
}

// ============================================================
// K7: out = ctx@Wo + bo; y = LN(out + x). tile 64x128, grid (128), 128 thr
// ============================================================
__global__ __launch_bounds__(128) void outln_gemm(
    const float* __restrict__ x, const float* __restrict__ Wo,
    const float* __restrict__ bo, const float* __restrict__ gamma,
    const float* __restrict__ beta, float* __restrict__ y)
{
    __shared__ __align__(16) float As[KC*SLA64];
    __shared__ __align__(16) float Bs[KC*SLB];
    int m0 = blockIdx.x * 64;
    int tid = threadIdx.x, tx = tid & 15, ty = tid >> 4;

    int ra[2], kqa[2], krb[4], nqb[4];
    #pragma unroll
    for (int i = 0; i < 2; i++) { int idx = tid + i*128; ra[i] = idx >> 2; kqa[i] = idx & 3; }
    #pragma unroll
    for (int i = 0; i < 4; i++) { int idx = tid + i*128; krb[i] = idx >> 5; nqb[i] = idx & 31; }

    ull c2[8][4];
    ull z2 = bcast2(0.f);
    #pragma unroll
    for (int i = 0; i < 8; i++) for (int j = 0; j < 4; j++) c2[i][j] = z2;

    float4 pa[2], pb[4];
    #pragma unroll
    for (int i = 0; i < 2; i++)
        pa[i] = *(const float4*)(g_ctx + (size_t)(m0 + ra[i])*HH + kqa[i]*4);
    #pragma unroll
    for (int i = 0; i < 4; i++)
        pb[i] = *(const float4*)(Wo + (size_t)krb[i]*HH + nqb[i]*4);

    for (int kc = 0; kc < HH; kc += KC) {
        #pragma unroll
        for (int i = 0; i < 2; i++) {
            float* d = &As[(kqa[i]*4)*SLA64 + 2*ra[i]];
            *(float2*)(d + 0*SLA64) = make_float2(pa[i].x, pa[i].x);
            *(float2*)(d + 1*SLA64) = make_float2(pa[i].y, pa[i].y);
            *(float2*)(d + 2*SLA64) = make_float2(pa[i].z, pa[i].z);
            *(float2*)(d + 3*SLA64) = make_float2(pa[i].w, pa[i].w);
        }
        #pragma unroll
        for (int i = 0; i < 4; i++)
            *(float4*)&Bs[krb[i]*SLB + nqb[i]*4] = pb[i];
        __syncthreads();
        if (kc + KC < HH) {
            #pragma unroll
            for (int i = 0; i < 2; i++)
                pa[i] = *(const float4*)(g_ctx + (size_t)(m0 + ra[i])*HH + kc + KC + kqa[i]*4);
            #pragma unroll
            for (int i = 0; i < 4; i++)
                pb[i] = *(const float4*)(Wo + (size_t)(kc + KC + krb[i])*HH + nqb[i]*4);
        }
        #pragma unroll
        for (int kk = 0; kk < KC; kk++)
            micro_dup(As + kk*SLA64, Bs + kk*SLB, tx, ty, 32, c2);
        __syncthreads();
    }

    float4 b0 = *(const float4*)&bo[tx*4];
    float4 b1 = *(const float4*)&bo[64 + tx*4];
    float4 g0 = *(const float4*)&gamma[tx*4];
    float4 g1 = *(const float4*)&gamma[64 + tx*4];
    float4 e0 = *(const float4*)&beta[tx*4];
    float4 e1 = *(const float4*)&beta[64 + tx*4];
    float bv[8] = {b0.x,b0.y,b0.z,b0.w,b1.x,b1.y,b1.z,b1.w};
    float gv[8] = {g0.x,g0.y,g0.z,g0.w,g1.x,g1.y,g1.z,g1.w};
    float ev[8] = {e0.x,e0.y,e0.z,e0.w,e1.x,e1.y,e1.z,e1.w};

    #pragma unroll
    for (int i = 0; i < 8; i++) {
        int row = m0 + ((i < 4) ? ty*4 + i : 32 + ty*4 + i - 4);
        float4 x0 = *(const float4*)&x[(size_t)row*HH + tx*4];
        float4 x1 = *(const float4*)&x[(size_t)row*HH + 64 + tx*4];
        float xv[8] = {x0.x,x0.y,x0.z,x0.w,x1.x,x1.y,x1.z,x1.w};
        float yv[8];
        float s = 0.f;
        #pragma unroll
        for (int jp = 0; jp < 4; jp++) {
            float2 f = up2(c2[i][jp]);
            yv[jp*2]   = f.x + bv[jp*2]   + xv[jp*2];
            yv[jp*2+1] = f.y + bv[jp*2+1] + xv[jp*2+1];
            s += yv[jp*2] + yv[jp*2+1];
        }
        #pragma unroll
        for (int o = 1; o < 16; o <<= 1) s += __shfl_xor_sync(0xffffffffu, s, o, 16);
        float mu = s * (1.0f / HH);
        float q = 0.f;
        #pragma unroll
        for (int j = 0; j < 8; j++) { yv[j] -= mu; q += yv[j]*yv[j]; }
        #pragma unroll
        for (int o = 1; o < 16; o <<= 1) q += __shfl_xor_sync(0xffffffffu, q, o, 16);
        float rstd = rsqrtf(q * (1.0f / HH) + 1e-5f);
        *(float4*)&y[(size_t)row*HH + tx*4] =
            make_float4(yv[0]*rstd*gv[0] + ev[0], yv[1]*rstd*gv[1] + ev[1],
                        yv[2]*rstd*gv[2] + ev[2], yv[3]*rstd*gv[3] + ev[3]);
        *(float4*)&y[(size_t)row*HH + 64 + tx*4] =
            make_float4(yv[4]*rstd*gv[4] + ev[4], yv[5]*rstd*gv[5] + ev[5],
                        yv[6]*rstd*gv[6] + ev[6], yv[7]*rstd*gv[7] + ev[7]);
    }
}

// ============================================================
extern "C" void kernel_launch(void* const* d_in, const int* in_sizes, int n_in,
                              void* d_out, int out_size)
{
    const float* x     = (const float*)d_in[0];
    const float* Wq    = (const float*)d_in[1];
    const float* bq    = (const float*)d_in[2];
    const float* Wk    = (const float*)d_in[3];
    const float* bk    = (const float*)d_in[4];
    const float* Wv    = (const float*)d_in[5];
    const float* bv    = (const float*)d_in[6];
    const float* rel_k = (const float*)d_in[7];
    const float* rel_v = (const float*)d_in[8];
    const float* Wo    = (const float*)d_in[9];
    const float* bo    = (const float*)d_in[10];
    const float* gamma = (const float*)d_in[11];
    const float* beta  = (const float*)d_in[12];

    float* y    = (float*)d_out;
    float* attn = (float*)d_out + (size_t)BB * SS * HH;

    qkv_gemm<<<dim3(64, 3), 256>>>(x, Wq, bq, Wk, bk, Wv, bv);
    qrel_gemm<<<128, 128>>>(rel_k);
    scores_gemm<<<dim3(8, 8, 8), 256>>>(attn);
    softmax_arel<<<NROWS, 256>>>(attn);
    ctx_gemm<<<dim3(16, 8), 128>>>(attn);
    relv_gemm<<<128, 128>>>(rel_v);
    outln_gemm<<<128, 128>>>(x, Wo, bo, gamma, beta, y);
}

// round 5
// speedup vs baseline: 1.4062x; 1.1692x over previous
#include <cuda_runtime.h>
#include <math.h>

#define BB 8
#define SS 1024
#define HH 128
#define PP 129
#define QSTR 132        // g_qrel row stride (16B-aligned rows)
#define PPAD 160
#define NROWS (BB*SS)   // 8192
#define KC 16           // K-chunk (128-K GEMMs)
#define KCC 32          // K-chunk (ctx long-K GEMM)
#define KTOT (SS + PPAD) // 1184 merged ctx K
#define SLA 260         // dup-A smem row stride, 128-row tiles
#define SLA64 132       // dup-A stride, 64-row tiles
#define SLB 132         // B smem row stride

typedef unsigned long long ull;

// -------- device scratch --------
__device__ float g_q[NROWS*HH];
__device__ float g_k[NROWS*HH];
__device__ float g_v[NROWS*HH];
__device__ float g_ctx[NROWS*HH];
__device__ float g_qrel[NROWS*QSTR];
__device__ float g_arel[NROWS*PPAD];

// ---------------- f32x2 helpers ----------------
__device__ __forceinline__ ull bcast2(float x) {
    unsigned int u = __float_as_uint(x);
    ull r;
    asm("mov.b64 %0, {%1, %2};" : "=l"(r) : "r"(u), "r"(u));
    return r;
}
__device__ __forceinline__ void ffma2(ull& c, ull a, ull b) {
    asm("fma.rn.f32x2 %0, %1, %2, %0;" : "+l"(c) : "l"(a), "l"(b));
}
__device__ __forceinline__ float2 up2(ull v) {
    unsigned int lo, hi;
    asm("mov.b64 {%0, %1}, %2;" : "=r"(lo), "=r"(hi) : "l"(v));
    return make_float2(__uint_as_float(lo), __uint_as_float(hi));
}
__device__ __forceinline__ float lo2f(ull v) {
    unsigned int lo, hi;
    asm("mov.b64 {%0, %1}, %2;" : "=r"(lo), "=r"(hi) : "l"(v));
    return __uint_as_float(lo);
}

// 8-row x 8-col micro (128-row tiles, 256 thr, ty 0..15)
__device__ __forceinline__ void micro8(const float* __restrict__ akd,
                                       const float* __restrict__ bk,
                                       int tx, int ty, ull (&c2)[8][4]) {
    ulonglong2 a01 = *(const ulonglong2*)(akd + 8*ty);
    ulonglong2 a23 = *(const ulonglong2*)(akd + 8*ty + 4);
    ulonglong2 a45 = *(const ulonglong2*)(akd + 128 + 8*ty);
    ulonglong2 a67 = *(const ulonglong2*)(akd + 128 + 8*ty + 4);
    ulonglong2 b0 = *(const ulonglong2*)(bk + tx*4);
    ulonglong2 b1 = *(const ulonglong2*)(bk + 64 + tx*4);
    ull aa[8] = {a01.x, a01.y, a23.x, a23.y, a45.x, a45.y, a67.x, a67.y};
    ull bb[4] = {b0.x, b0.y, b1.x, b1.y};
    #pragma unroll
    for (int i = 0; i < 8; i++)
        #pragma unroll
        for (int j = 0; j < 4; j++)
            ffma2(c2[i][j], aa[i], bb[j]);
}

// 4-row x 8-col micro (64-row tiles, 256 thr, ty 0..15)
__device__ __forceinline__ void micro4(const float* __restrict__ akd,
                                       const float* __restrict__ bk,
                                       int tx, int ty, ull (&c2)[4][4]) {
    ulonglong2 a01 = *(const ulonglong2*)(akd + 8*ty);
    ulonglong2 a23 = *(const ulonglong2*)(akd + 8*ty + 4);
    ulonglong2 b0 = *(const ulonglong2*)(bk + tx*4);
    ulonglong2 b1 = *(const ulonglong2*)(bk + 64 + tx*4);
    ull aa[4] = {a01.x, a01.y, a23.x, a23.y};
    ull bb[4] = {b0.x, b0.y, b1.x, b1.y};
    #pragma unroll
    for (int i = 0; i < 4; i++)
        #pragma unroll
        for (int j = 0; j < 4; j++)
            ffma2(c2[i][j], aa[i], bb[j]);
}

// ============================================================
// K1: q/k/v = x@W + b. tile 128x128, grid (64,3), 256 thr
// ============================================================
__global__ __launch_bounds__(256) void qkv_gemm(
    const float* __restrict__ x,
    const float* __restrict__ Wq, const float* __restrict__ bq,
    const float* __restrict__ Wk, const float* __restrict__ bk,
    const float* __restrict__ Wv, const float* __restrict__ bv)
{
    __shared__ __align__(16) float As[KC*SLA];
    __shared__ __align__(16) float Bs[KC*SLB];
    int z = blockIdx.y;
    const float* W    = (z == 0) ? Wq : (z == 1) ? Wk : Wv;
    const float* bias = (z == 0) ? bq : (z == 1) ? bk : bv;
    float* out        = (z == 0) ? g_q : (z == 1) ? g_k : g_v;
    int m0 = blockIdx.x * 128;
    int tid = threadIdx.x, tx = tid & 15, ty = tid >> 4;

    int ra[2], kqa[2], krb[2], nqb[2];
    #pragma unroll
    for (int i = 0; i < 2; i++) {
        int idx = tid + i*256;
        ra[i] = idx >> 2; kqa[i] = idx & 3;
        krb[i] = idx >> 5; nqb[i] = idx & 31;
    }

    ull c2[8][4];
    ull z2 = bcast2(0.f);
    #pragma unroll
    for (int i = 0; i < 8; i++) for (int j = 0; j < 4; j++) c2[i][j] = z2;

    float4 pa[2], pb[2];
    #pragma unroll
    for (int i = 0; i < 2; i++) {
        pa[i] = *(const float4*)(x + (size_t)(m0 + ra[i])*HH + kqa[i]*4);
        pb[i] = *(const float4*)(W + (size_t)krb[i]*HH + nqb[i]*4);
    }
    for (int kc = 0; kc < HH; kc += KC) {
        #pragma unroll
        for (int i = 0; i < 2; i++) {
            float* d = &As[(kqa[i]*4)*SLA + 2*ra[i]];
            *(float2*)(d + 0*SLA) = make_float2(pa[i].x, pa[i].x);
            *(float2*)(d + 1*SLA) = make_float2(pa[i].y, pa[i].y);
            *(float2*)(d + 2*SLA) = make_float2(pa[i].z, pa[i].z);
            *(float2*)(d + 3*SLA) = make_float2(pa[i].w, pa[i].w);
            *(float4*)&Bs[krb[i]*SLB + nqb[i]*4] = pb[i];
        }
        __syncthreads();
        if (kc + KC < HH) {
            #pragma unroll
            for (int i = 0; i < 2; i++) {
                pa[i] = *(const float4*)(x + (size_t)(m0 + ra[i])*HH + kc + KC + kqa[i]*4);
                pb[i] = *(const float4*)(W + (size_t)(kc + KC + krb[i])*HH + nqb[i]*4);
            }
        }
        #pragma unroll
        for (int kk = 0; kk < KC; kk++)
            micro8(As + kk*SLA, Bs + kk*SLB, tx, ty, c2);
        __syncthreads();
    }
    float4 bv0 = *(const float4*)&bias[tx*4];
    float4 bv1 = *(const float4*)&bias[64 + tx*4];
    #pragma unroll
    for (int i = 0; i < 8; i++) {
        int row = m0 + ((i < 4) ? ty*4 + i : 64 + ty*4 + i - 4);
        float2 f0 = up2(c2[i][0]), f1 = up2(c2[i][1]);
        float2 f2 = up2(c2[i][2]), f3 = up2(c2[i][3]);
        *(float4*)&out[(size_t)row*HH + tx*4] =
            make_float4(f0.x + bv0.x, f0.y + bv0.y, f1.x + bv0.z, f1.y + bv0.w);
        *(float4*)&out[(size_t)row*HH + 64 + tx*4] =
            make_float4(f2.x + bv1.x, f2.y + bv1.y, f3.x + bv1.z, f3.y + bv1.w);
    }
}

// ============================================================
// K2: qrel = q @ rel_k^T. tile 64x(128+1), grid (128), 256 thr
// ============================================================
__global__ __launch_bounds__(256) void qrel_gemm(const float* __restrict__ rel_k)
{
    __shared__ __align__(16) float As[KC*SLA64];
    __shared__ __align__(16) float Bs[KC*SLB];
    __shared__ float rk[KC];
    int m0 = blockIdx.x * 64;
    int tid = threadIdx.x, tx = tid & 15, ty = tid >> 4;

    // A stage: 64 rows x 16 k = 256 float4 -> 1/thread
    int raA = tid >> 2, kqA = tid & 3;
    // B stage (NT): 128 rows x 16 k = 512 float4 -> 2/thread
    int rb[2], kqb[2];
    #pragma unroll
    for (int i = 0; i < 2; i++) { int idx = tid + i*256; rb[i] = idx >> 2; kqb[i] = idx & 3; }

    ull c2[4][4];
    ull z2 = bcast2(0.f);
    #pragma unroll
    for (int i = 0; i < 4; i++) for (int j = 0; j < 4; j++) c2[i][j] = z2;
    float ce[4] = {};

    float4 pa, pb[2];
    float prk = (tid < KC) ? rel_k[(size_t)128*HH + tid] : 0.f;
    pa = *(const float4*)(g_q + (size_t)(m0 + raA)*HH + kqA*4);
    #pragma unroll
    for (int i = 0; i < 2; i++)
        pb[i] = *(const float4*)(rel_k + (size_t)rb[i]*HH + kqb[i]*4);

    for (int kc = 0; kc < HH; kc += KC) {
        {
            float* d = &As[(kqA*4)*SLA64 + 2*raA];
            *(float2*)(d + 0*SLA64) = make_float2(pa.x, pa.x);
            *(float2*)(d + 1*SLA64) = make_float2(pa.y, pa.y);
            *(float2*)(d + 2*SLA64) = make_float2(pa.z, pa.z);
            *(float2*)(d + 3*SLA64) = make_float2(pa.w, pa.w);
        }
        #pragma unroll
        for (int i = 0; i < 2; i++) {
            Bs[(kqb[i]*4+0)*SLB + rb[i]] = pb[i].x;
            Bs[(kqb[i]*4+1)*SLB + rb[i]] = pb[i].y;
            Bs[(kqb[i]*4+2)*SLB + rb[i]] = pb[i].z;
            Bs[(kqb[i]*4+3)*SLB + rb[i]] = pb[i].w;
        }
        if (tid < KC) rk[tid] = prk;
        __syncthreads();
        if (kc + KC < HH) {
            pa = *(const float4*)(g_q + (size_t)(m0 + raA)*HH + kc + KC + kqA*4);
            #pragma unroll
            for (int i = 0; i < 2; i++)
                pb[i] = *(const float4*)(rel_k + (size_t)rb[i]*HH + kc + KC + kqb[i]*4);
            if (tid < KC) prk = rel_k[(size_t)128*HH + kc + KC + tid];
        }
        #pragma unroll
        for (int kk = 0; kk < KC; kk++) {
            const float* akd = As + kk*SLA64;
            const float* bk  = Bs + kk*SLB;
            ulonglong2 a01 = *(const ulonglong2*)(akd + 8*ty);
            ulonglong2 a23 = *(const ulonglong2*)(akd + 8*ty + 4);
            ulonglong2 b0 = *(const ulonglong2*)(bk + tx*4);
            ulonglong2 b1 = *(const ulonglong2*)(bk + 64 + tx*4);
            ull aa[4] = {a01.x, a01.y, a23.x, a23.y};
            ull bb[4] = {b0.x, b0.y, b1.x, b1.y};
            #pragma unroll
            for (int i = 0; i < 4; i++)
                #pragma unroll
                for (int j = 0; j < 4; j++)
                    ffma2(c2[i][j], aa[i], bb[j]);
            float rkv = rk[kk];
            #pragma unroll
            for (int i = 0; i < 4; i++) ce[i] += lo2f(aa[i]) * rkv;
        }
        __syncthreads();
    }
    #pragma unroll
    for (int i = 0; i < 4; i++) {
        int row = m0 + ty*4 + i;
        float2 f0 = up2(c2[i][0]), f1 = up2(c2[i][1]);
        float2 f2 = up2(c2[i][2]), f3 = up2(c2[i][3]);
        float* qr = g_qrel + (size_t)row*QSTR;
        *(float4*)&qr[tx*4]      = make_float4(f0.x, f0.y, f1.x, f1.y);
        *(float4*)&qr[64 + tx*4] = make_float4(f2.x, f2.y, f3.x, f3.y);
        if (tx == 0) qr[128] = ce[i];
    }
}

// ============================================================
// K3: scores[b] = q[b]@k[b]^T/sqrt(H) + qrel. tile 128x128, grid (8,8,8), 256 thr
// ============================================================
__global__ __launch_bounds__(256) void scores_gemm(float* __restrict__ scores)
{
    __shared__ __align__(16) float As[KC*SLA];
    __shared__ __align__(16) float Bs[KC*SLB];
    int b = blockIdx.z;
    const float* A  = g_q + (size_t)b*SS*HH;
    const float* Bm = g_k + (size_t)b*SS*HH;
    int m0 = blockIdx.y * 128;
    int n0 = blockIdx.x * 128;
    int tid = threadIdx.x, tx = tid & 15, ty = tid >> 4;

    int ra[2], kqa[2];
    #pragma unroll
    for (int i = 0; i < 2; i++) { int idx = tid + i*256; ra[i] = idx >> 2; kqa[i] = idx & 3; }

    ull c2[8][4];
    ull z2 = bcast2(0.f);
    #pragma unroll
    for (int i = 0; i < 8; i++) for (int j = 0; j < 4; j++) c2[i][j] = z2;

    float4 pa[2], pb[2];
    #pragma unroll
    for (int i = 0; i < 2; i++) {
        pa[i] = *(const float4*)(A  + (size_t)(m0 + ra[i])*HH + kqa[i]*4);
        pb[i] = *(const float4*)(Bm + (size_t)(n0 + ra[i])*HH + kqa[i]*4);
    }
    for (int kc = 0; kc < HH; kc += KC) {
        #pragma unroll
        for (int i = 0; i < 2; i++) {
            float* d = &As[(kqa[i]*4)*SLA + 2*ra[i]];
            *(float2*)(d + 0*SLA) = make_float2(pa[i].x, pa[i].x);
            *(float2*)(d + 1*SLA) = make_float2(pa[i].y, pa[i].y);
            *(float2*)(d + 2*SLA) = make_float2(pa[i].z, pa[i].z);
            *(float2*)(d + 3*SLA) = make_float2(pa[i].w, pa[i].w);
            Bs[(kqa[i]*4+0)*SLB + ra[i]] = pb[i].x;
            Bs[(kqa[i]*4+1)*SLB + ra[i]] = pb[i].y;
            Bs[(kqa[i]*4+2)*SLB + ra[i]] = pb[i].z;
            Bs[(kqa[i]*4+3)*SLB + ra[i]] = pb[i].w;
        }
        __syncthreads();
        if (kc + KC < HH) {
            #pragma unroll
            for (int i = 0; i < 2; i++) {
                pa[i] = *(const float4*)(A  + (size_t)(m0 + ra[i])*HH + kc + KC + kqa[i]*4);
                pb[i] = *(const float4*)(Bm + (size_t)(n0 + ra[i])*HH + kc + KC + kqa[i]*4);
            }
        }
        #pragma unroll
        for (int kk = 0; kk < KC; kk++)
            micro8(As + kk*SLA, Bs + kk*SLB, tx, ty, c2);
        __syncthreads();
    }
    const float invscale = 0.08838834764831845f;
    #pragma unroll
    for (int i = 0; i < 8; i++) {
        int row = m0 + ((i < 4) ? ty*4 + i : 64 + ty*4 + i - 4);
        const float* qr = g_qrel + ((size_t)b*SS + row)*QSTR;
        float* sr = scores + ((size_t)b*SS + row)*SS;
        #pragma unroll
        for (int jp = 0; jp < 4; jp++) {
            float2 f = up2(c2[i][jp]);
            int j0 = jp*2;
            int col = n0 + ((j0 < 4) ? tx*4 + j0 : 64 + tx*4 + j0 - 4);
            int d0 = col - row;     d0 = (d0 < -64) ? -64 : (d0 > 64) ? 64 : d0;
            int d1 = col + 1 - row; d1 = (d1 < -64) ? -64 : (d1 > 64) ? 64 : d1;
            *(float2*)&sr[col] = make_float2(f.x*invscale + qr[d0 + 64],
                                             f.y*invscale + qr[d1 + 64]);
        }
    }
}

// ============================================================
// K4: fused softmax + arel extraction. grid 8192, 256 thr
// ============================================================
__global__ __launch_bounds__(256) void softmax_arel(float* __restrict__ scores)
{
    __shared__ __align__(16) float rowbuf[SS];
    __shared__ float sm[8];
    __shared__ float sred[16];
    __shared__ float stot[2];
    int r = blockIdx.x, tid = threadIdx.x;
    int i = r & (SS - 1);
    float* sr = scores + (size_t)r * SS;
    int lane = tid & 31, wid = tid >> 5;

    float4 v = ((const float4*)sr)[tid];

    float m = fmaxf(fmaxf(v.x, v.y), fmaxf(v.z, v.w));
    #pragma unroll
    for (int o = 16; o > 0; o >>= 1) m = fmaxf(m, __shfl_xor_sync(0xffffffffu, m, o));
    if (lane == 0) sm[wid] = m;
    __syncthreads();
    m = fmaxf(fmaxf(fmaxf(sm[0], sm[1]), fmaxf(sm[2], sm[3])),
              fmaxf(fmaxf(sm[4], sm[5]), fmaxf(sm[6], sm[7])));
    __syncthreads();

    v.x = __expf(v.x - m); v.y = __expf(v.y - m);
    v.z = __expf(v.z - m); v.w = __expf(v.w - m);
    float s = v.x + v.y + v.z + v.w;
    #pragma unroll
    for (int o = 16; o > 0; o >>= 1) s += __shfl_xor_sync(0xffffffffu, s, o);
    if (lane == 0) sm[wid] = s;
    __syncthreads();
    s = sm[0] + sm[1] + sm[2] + sm[3] + sm[4] + sm[5] + sm[6] + sm[7];
    float inv = 1.0f / s;
    v.x *= inv; v.y *= inv; v.z *= inv; v.w *= inv;

    ((float4*)sr)[tid] = v;
    ((float4*)rowbuf)[tid] = v;

    int j0 = tid * 4;
    float p[4] = {v.x, v.y, v.z, v.w};
    float slo = 0.f, shi = 0.f;
    #pragma unroll
    for (int t = 0; t < 4; t++) {
        int d = j0 + t - i;
        if (d <= -64) slo += p[t];
        else if (d >= 64) shi += p[t];
    }
    #pragma unroll
    for (int o = 16; o > 0; o >>= 1) {
        slo += __shfl_xor_sync(0xffffffffu, slo, o);
        shi += __shfl_xor_sync(0xffffffffu, shi, o);
    }
    if (lane == 0) { sred[wid] = slo; sred[8 + wid] = shi; }
    __syncthreads();
    if (tid == 0) {
        float a = 0.f, b = 0.f;
        #pragma unroll
        for (int w = 0; w < 8; w++) { a += sred[w]; b += sred[8 + w]; }
        stot[0] = a; stot[1] = b;
    }
    __syncthreads();

    if (tid < PPAD) {
        float val;
        if (tid == 0)        val = stot[0];
        else if (tid == 128) val = stot[1];
        else if (tid < 128) {
            int j = i + tid - 64;
            val = (j >= 0 && j < SS) ? rowbuf[j] : 0.f;
        } else val = 0.f;
        g_arel[(size_t)r*PPAD + tid] = val;
    }
}

// ============================================================
// K5: ctx[b] = [attn[b] | arel[b]] @ [v[b]; rel_v], K=1184.
// tile 64x128, grid (16,8), 256 thr, KC=32
// ============================================================
__global__ __launch_bounds__(256) void ctxrel_gemm(const float* __restrict__ attn,
                                                   const float* __restrict__ rel_v)
{
    __shared__ __align__(16) float As[KCC*SLA64];
    __shared__ __align__(16) float Bs[KCC*SLB];
    int b = blockIdx.y;
    const float* A  = attn + (size_t)b*SS*SS;
    const float* Ar = g_arel + (size_t)b*SS*PPAD;
    const float* Bm = g_v  + (size_t)b*SS*HH;
    float* out = g_ctx + (size_t)b*SS*HH;
    int m0 = blockIdx.x * 64;
    int tid = threadIdx.x, tx = tid & 15, ty = tid >> 4;

    // A stage: 64 rows x 32 k = 512 float4 -> 2/thread
    int ra[2], kqa[2];
    #pragma unroll
    for (int i = 0; i < 2; i++) { int idx = tid + i*256; ra[i] = idx >> 3; kqa[i] = idx & 7; }
    // B stage: 32 rows x 128 n = 1024 float4 -> 4/thread
    int krb[4], nqb[4];
    #pragma unroll
    for (int i = 0; i < 4; i++) { int idx = tid + i*256; krb[i] = idx >> 5; nqb[i] = idx & 31; }

    ull c2[4][4];
    ull z2 = bcast2(0.f);
    #pragma unroll
    for (int i = 0; i < 4; i++) for (int j = 0; j < 4; j++) c2[i][j] = z2;

    float4 pa[2], pb[4];
    #pragma unroll
    for (int i = 0; i < 2; i++)
        pa[i] = *(const float4*)(A + (size_t)(m0 + ra[i])*SS + kqa[i]*4);
    #pragma unroll
    for (int i = 0; i < 4; i++)
        pb[i] = *(const float4*)(Bm + (size_t)krb[i]*HH + nqb[i]*4);

    for (int kc = 0; kc < KTOT; kc += KCC) {
        #pragma unroll
        for (int i = 0; i < 2; i++) {
            float* d = &As[(kqa[i]*4)*SLA64 + 2*ra[i]];
            *(float2*)(d + 0*SLA64) = make_float2(pa[i].x, pa[i].x);
            *(float2*)(d + 1*SLA64) = make_float2(pa[i].y, pa[i].y);
            *(float2*)(d + 2*SLA64) = make_float2(pa[i].z, pa[i].z);
            *(float2*)(d + 3*SLA64) = make_float2(pa[i].w, pa[i].w);
        }
        #pragma unroll
        for (int i = 0; i < 4; i++)
            *(float4*)&Bs[krb[i]*SLB + nqb[i]*4] = pb[i];
        __syncthreads();
        int kn = kc + KCC;
        if (kn < KTOT) {
            if (kn < SS) {
                #pragma unroll
                for (int i = 0; i < 2; i++)
                    pa[i] = *(const float4*)(A + (size_t)(m0 + ra[i])*SS + kn + kqa[i]*4);
                #pragma unroll
                for (int i = 0; i < 4; i++)
                    pb[i] = *(const float4*)(Bm + (size_t)(kn + krb[i])*HH + nqb[i]*4);
            } else {
                int ko = kn - SS;
                #pragma unroll
                for (int i = 0; i < 2; i++)
                    pa[i] = *(const float4*)(Ar + (size_t)(m0 + ra[i])*PPAD + ko + kqa[i]*4);
                #pragma unroll
                for (int i = 0; i < 4; i++) {
                    int krow = ko + krb[i];
                    pb[i] = (krow < PP) ? *(const float4*)(rel_v + (size_t)krow*HH + nqb[i]*4)
                                        : make_float4(0.f, 0.f, 0.f, 0.f);
                }
            }
        }
        #pragma unroll
        for (int kk = 0; kk < KCC; kk++)
            micro4(As + kk*SLA64, Bs + kk*SLB, tx, ty, c2);
        __syncthreads();
    }
    #pragma unroll
    for (int i = 0; i < 4; i++) {
        int row = m0 + ty*4 + i;
        float2 f0 = up2(c2[i][0]), f1 = up2(c2[i][1]);
        float2 f2 = up2(c2[i][2]), f3 = up2(c2[i][3]);
        *(float4*)&out[(size_t)row*HH + tx*4]      = make_float4(f0.x, f0.y, f1.x, f1.y);
        *(float4*)&out[(size_t)row*HH + 64 + tx*4] = make_float4(f2.x, f2.y, f3.x, f3.y);
    }
}

// ============================================================
// K6: out = ctx@Wo + bo; y = LN(out + x). tile 64x128, grid (128), 256 thr
// ============================================================
__global__ __launch_bounds__(256) void outln_gemm(
    const float* __restrict__ x, const float* __restrict__ Wo,
    const float* __restrict__ bo, const float* __restrict__ gamma,
    const float* __restrict__ beta, float* __restrict__ y)
{
    __shared__ __align__(16) float As[KC*SLA64];
    __shared__ __align__(16) float Bs[KC*SLB];
    int m0 = blockIdx.x * 64;
    int tid = threadIdx.x, tx = tid & 15, ty = tid >> 4;

    int raA = tid >> 2, kqA = tid & 3;      // A: 1 float4/thread
    int krb[2], nqb[2];                      // B: 2 float4/thread
    #pragma unroll
    for (int i = 0; i < 2; i++) { int idx = tid + i*256; krb[i] = idx >> 5; nqb[i] = idx & 31; }

    ull c2[4][4];
    ull z2 = bcast2(0.f);
    #pragma unroll
    for (int i = 0; i < 4; i++) for (int j = 0; j < 4; j++) c2[i][j] = z2;

    float4 pa, pb[2];
    pa = *(const float4*)(g_ctx + (size_t)(m0 + raA)*HH + kqA*4);
    #pragma unroll
    for (int i = 0; i < 2; i++)
        pb[i] = *(const float4*)(Wo + (size_t)krb[i]*HH + nqb[i]*4);

    for (int kc = 0; kc < HH; kc += KC) {
        {
            float* d = &As[(kqA*4)*SLA64 + 2*raA];
            *(float2*)(d + 0*SLA64) = make_float2(pa.x, pa.x);
            *(float2*)(d + 1*SLA64) = make_float2(pa.y, pa.y);
            *(float2*)(d + 2*SLA64) = make_float2(pa.z, pa.z);
            *(float2*)(d + 3*SLA64) = make_float2(pa.w, pa.w);
        }
        #pragma unroll
        for (int i = 0; i < 2; i++)
            *(float4*)&Bs[krb[i]*SLB + nqb[i]*4] = pb[i];
        __syncthreads();
        if (kc + KC < HH) {
            pa = *(const float4*)(g_ctx + (size_t)(m0 + raA)*HH + kc + KC + kqA*4);
            #pragma unroll
            for (int i = 0; i < 2; i++)
                pb[i] = *(const float4*)(Wo + (size_t)(kc + KC + krb[i])*HH + nqb[i]*4);
        }
        #pragma unroll
        for (int kk = 0; kk < KC; kk++)
            micro4(As + kk*SLA64, Bs + kk*SLB, tx, ty, c2);
        __syncthreads();
    }

    float4 b0 = *(const float4*)&bo[tx*4];
    float4 b1 = *(const float4*)&bo[64 + tx*4];
    float4 g0 = *(const float4*)&gamma[tx*4];
    float4 g1 = *(const float4*)&gamma[64 + tx*4];
    float4 e0 = *(const float4*)&beta[tx*4];
    float4 e1 = *(const float4*)&beta[64 + tx*4];
    float bv[8] = {b0.x,b0.y,b0.z,b0.w,b1.x,b1.y,b1.z,b1.w};
    float gv[8] = {g0.x,g0.y,g0.z,g0.w,g1.x,g1.y,g1.z,g1.w};
    float ev[8] = {e0.x,e0.y,e0.z,e0.w,e1.x,e1.y,e1.z,e1.w};

    #pragma unroll
    for (int i = 0; i < 4; i++) {
        int row = m0 + ty*4 + i;
        float4 x0 = *(const float4*)&x[(size_t)row*HH + tx*4];
        float4 x1 = *(const float4*)&x[(size_t)row*HH + 64 + tx*4];
        float xv[8] = {x0.x,x0.y,x0.z,x0.w,x1.x,x1.y,x1.z,x1.w};
        float yv[8];
        float s = 0.f;
        #pragma unroll
        for (int jp = 0; jp < 4; jp++) {
            float2 f = up2(c2[i][jp]);
            yv[jp*2]   = f.x + bv[jp*2]   + xv[jp*2];
            yv[jp*2+1] = f.y + bv[jp*2+1] + xv[jp*2+1];
            s += yv[jp*2] + yv[jp*2+1];
        }
        #pragma unroll
        for (int o = 1; o < 16; o <<= 1) s += __shfl_xor_sync(0xffffffffu, s, o, 16);
        float mu = s * (1.0f / HH);
        float q = 0.f;
        #pragma unroll
        for (int j = 0; j < 8; j++) { yv[j] -= mu; q += yv[j]*yv[j]; }
        #pragma unroll
        for (int o = 1; o < 16; o <<= 1) q += __shfl_xor_sync(0xffffffffu, q, o, 16);
        float rstd = rsqrtf(q * (1.0f / HH) + 1e-5f);
        *(float4*)&y[(size_t)row*HH + tx*4] =
            make_float4(yv[0]*rstd*gv[0] + ev[0], yv[1]*rstd*gv[1] + ev[1],
                        yv[2]*rstd*gv[2] + ev[2], yv[3]*rstd*gv[3] + ev[3]);
        *(float4*)&y[(size_t)row*HH + 64 + tx*4] =
            make_float4(yv[4]*rstd*gv[4] + ev[4], yv[5]*rstd*gv[5] + ev[5],
                        yv[6]*rstd*gv[6] + ev[6], yv[7]*rstd*gv[7] + ev[7]);
    }
}

// ============================================================
extern "C" void kernel_launch(void* const* d_in, const int* in_sizes, int n_in,
                              void* d_out, int out_size)
{
    const float* x     = (const float*)d_in[0];
    const float* Wq    = (const float*)d_in[1];
    const float* bq    = (const float*)d_in[2];
    const float* Wk    = (const float*)d_in[3];
    const float* bk    = (const float*)d_in[4];
    const float* Wv    = (const float*)d_in[5];
    const float* bv    = (const float*)d_in[6];
    const float* rel_k = (const float*)d_in[7];
    const float* rel_v = (const float*)d_in[8];
    const float* Wo    = (const float*)d_in[9];
    const float* bo    = (const float*)d_in[10];
    const float* gamma = (const float*)d_in[11];
    const float* beta  = (const float*)d_in[12];

    float* y    = (float*)d_out;
    float* attn = (float*)d_out + (size_t)BB * SS * HH;

    qkv_gemm<<<dim3(64, 3), 256>>>(x, Wq, bq, Wk, bk, Wv, bv);
    qrel_gemm<<<128, 256>>>(rel_k);
    scores_gemm<<<dim3(8, 8, 8), 256>>>(attn);
    softmax_arel<<<NROWS, 256>>>(attn);
    ctxrel_gemm<<<dim3(16, 8), 256>>>(attn, rel_v);
    outln_gemm<<<128, 256>>>(x, Wo, bo, gamma, beta, y);
}

// round 7
// speedup vs baseline: 1.9499x; 1.3866x over previous
#include <cuda_runtime.h>
#include <cuda_bf16.h>
#include <math.h>
#include <stdint.h>

#define BB 8
#define SS 1024
#define HH 128
#define PP 129
#define QSTR 132
#define AW 256            // padded arel width
#define NROWS (BB*SS)
#define KC 16
#define SLA 260
#define SLA64 132
#define SLB 132
#define SMS 136           // scores smem tile stride (bf16 elems)
#define SMC 72            // ctx smem tile stride
#define SCORES_SMEM (4*128*SMS*2)                 // 139264 B
#define CTX_SMEM ((2*64*SMC + 2*128*SMC)*2)       // 55296 B

typedef unsigned long long ull;

// -------- device scratch --------
__device__ float g_q[NROWS*HH];
__device__ float g_v[NROWS*HH];
__device__ float g_qrel[NROWS*QSTR];
__device__ float g_ctxA[NROWS*HH];
__device__ float g_ctxB[NROWS*HH];
__device__ unsigned short g_qh[NROWS*HH], g_ql[NROWS*HH];
__device__ unsigned short g_kh[NROWS*HH], g_kl[NROWS*HH];
__device__ unsigned short g_vth[BB*HH*SS], g_vtl[BB*HH*SS];
__device__ unsigned short g_ah[NROWS*SS], g_al[NROWS*SS];
__device__ unsigned short g_arh[NROWS*AW], g_arl[NROWS*AW];
__device__ unsigned short g_rvh[HH*AW], g_rvl[HH*AW];

// ---------------- f32x2 helpers ----------------
__device__ __forceinline__ ull bcast2(float x) {
    unsigned int u = __float_as_uint(x);
    ull r; asm("mov.b64 %0, {%1, %2};" : "=l"(r) : "r"(u), "r"(u));
    return r;
}
__device__ __forceinline__ void ffma2(ull& c, ull a, ull b) {
    asm("fma.rn.f32x2 %0, %1, %2, %0;" : "+l"(c) : "l"(a), "l"(b));
}
__device__ __forceinline__ float2 up2(ull v) {
    unsigned int lo, hi;
    asm("mov.b64 {%0, %1}, %2;" : "=r"(lo), "=r"(hi) : "l"(v));
    return make_float2(__uint_as_float(lo), __uint_as_float(hi));
}
__device__ __forceinline__ float lo2f(ull v) {
    unsigned int lo, hi;
    asm("mov.b64 {%0, %1}, %2;" : "=r"(lo), "=r"(hi) : "l"(v));
    return __uint_as_float(lo);
}
__device__ __forceinline__ void fsplit(float f, unsigned short& h, unsigned short& l) {
    __nv_bfloat16 bh = __float2bfloat16(f);
    h = __bfloat16_as_ushort(bh);
    l = __bfloat16_as_ushort(__float2bfloat16(f - __bfloat162float(bh)));
}

// ---------------- mma.sync helpers ----------------
__device__ __forceinline__ uint32_t smem_u32(const void* p) {
    uint32_t a;
    asm("{ .reg .u64 t; cvta.to.shared.u64 t, %1; cvt.u32.u64 %0, t; }" : "=r"(a) : "l"(p));
    return a;
}
__device__ __forceinline__ void ldmx4(uint32_t* r, uint32_t addr) {
    asm volatile("ldmatrix.sync.aligned.m8n8.x4.shared.b16 {%0,%1,%2,%3}, [%4];"
        : "=r"(r[0]), "=r"(r[1]), "=r"(r[2]), "=r"(r[3]) : "r"(addr));
}
__device__ __forceinline__ void mma16816(float* c, const uint32_t* a, const uint32_t* b) {
    asm volatile("mma.sync.aligned.m16n8k16.row.col.f32.bf16.bf16.f32 "
        "{%0,%1,%2,%3}, {%4,%5,%6,%7}, {%8,%9}, {%0,%1,%2,%3};"
        : "+f"(c[0]), "+f"(c[1]), "+f"(c[2]), "+f"(c[3])
        : "r"(a[0]), "r"(a[1]), "r"(a[2]), "r"(a[3]), "r"(b[0]), "r"(b[1]));
}

// fp32 micro kernels (scalar GEMM path)
__device__ __forceinline__ void micro8(const float* __restrict__ akd,
                                       const float* __restrict__ bk,
                                       int tx, int ty, ull (&c2)[8][4]) {
    ulonglong2 a01 = *(const ulonglong2*)(akd + 8*ty);
    ulonglong2 a23 = *(const ulonglong2*)(akd + 8*ty + 4);
    ulonglong2 a45 = *(const ulonglong2*)(akd + 128 + 8*ty);
    ulonglong2 a67 = *(const ulonglong2*)(akd + 128 + 8*ty + 4);
    ulonglong2 b0 = *(const ulonglong2*)(bk + tx*4);
    ulonglong2 b1 = *(const ulonglong2*)(bk + 64 + tx*4);
    ull aa[8] = {a01.x, a01.y, a23.x, a23.y, a45.x, a45.y, a67.x, a67.y};
    ull bb[4] = {b0.x, b0.y, b1.x, b1.y};
    #pragma unroll
    for (int i = 0; i < 8; i++)
        #pragma unroll
        for (int j = 0; j < 4; j++) ffma2(c2[i][j], aa[i], bb[j]);
}
__device__ __forceinline__ void micro4(const float* __restrict__ akd,
                                       const float* __restrict__ bk,
                                       int tx, int ty, ull (&c2)[4][4]) {
    ulonglong2 a01 = *(const ulonglong2*)(akd + 8*ty);
    ulonglong2 a23 = *(const ulonglong2*)(akd + 8*ty + 4);
    ulonglong2 b0 = *(const ulonglong2*)(bk + tx*4);
    ulonglong2 b1 = *(const ulonglong2*)(bk + 64 + tx*4);
    ull aa[4] = {a01.x, a01.y, a23.x, a23.y};
    ull bb[4] = {b0.x, b0.y, b1.x, b1.y};
    #pragma unroll
    for (int i = 0; i < 4; i++)
        #pragma unroll
        for (int j = 0; j < 4; j++) ffma2(c2[i][j], aa[i], bb[j]);
}

// ============================================================
// K1: q/k/v = x@W + b. tile 128x128, grid (64,3), 256 thr.
// z=0: g_q fp32 + q hi/lo. z=1: k hi/lo. z=2: g_v fp32.
// ============================================================
__global__ __launch_bounds__(256) void qkv_gemm(
    const float* __restrict__ x,
    const float* __restrict__ Wq, const float* __restrict__ bq,
    const float* __restrict__ Wk, const float* __restrict__ bk,
    const float* __restrict__ Wv, const float* __restrict__ bv)
{
    __shared__ __align__(16) float As[KC*SLA];
    __shared__ __align__(16) float Bs[KC*SLB];
    int z = blockIdx.y;
    const float* W    = (z == 0) ? Wq : (z == 1) ? Wk : Wv;
    const float* bias = (z == 0) ? bq : (z == 1) ? bk : bv;
    int m0 = blockIdx.x * 128;
    int tid = threadIdx.x, tx = tid & 15, ty = tid >> 4;

    int ra[2], kqa[2], krb[2], nqb[2];
    #pragma unroll
    for (int i = 0; i < 2; i++) {
        int idx = tid + i*256;
        ra[i] = idx >> 2; kqa[i] = idx & 3;
        krb[i] = idx >> 5; nqb[i] = idx & 31;
    }

    ull c2[8][4];
    ull z2 = bcast2(0.f);
    #pragma unroll
    for (int i = 0; i < 8; i++) for (int j = 0; j < 4; j++) c2[i][j] = z2;

    float4 pa[2], pb[2];
    #pragma unroll
    for (int i = 0; i < 2; i++) {
        pa[i] = *(const float4*)(x + (size_t)(m0 + ra[i])*HH + kqa[i]*4);
        pb[i] = *(const float4*)(W + (size_t)krb[i]*HH + nqb[i]*4);
    }
    for (int kc = 0; kc < HH; kc += KC) {
        #pragma unroll
        for (int i = 0; i < 2; i++) {
            float* d = &As[(kqa[i]*4)*SLA + 2*ra[i]];
            *(float2*)(d + 0*SLA) = make_float2(pa[i].x, pa[i].x);
            *(float2*)(d + 1*SLA) = make_float2(pa[i].y, pa[i].y);
            *(float2*)(d + 2*SLA) = make_float2(pa[i].z, pa[i].z);
            *(float2*)(d + 3*SLA) = make_float2(pa[i].w, pa[i].w);
            *(float4*)&Bs[krb[i]*SLB + nqb[i]*4] = pb[i];
        }
        __syncthreads();
        if (kc + KC < HH) {
            #pragma unroll
            for (int i = 0; i < 2; i++) {
                pa[i] = *(const float4*)(x + (size_t)(m0 + ra[i])*HH + kc + KC + kqa[i]*4);
                pb[i] = *(const float4*)(W + (size_t)(kc + KC + krb[i])*HH + nqb[i]*4);
            }
        }
        #pragma unroll
        for (int kk = 0; kk < KC; kk++)
            micro8(As + kk*SLA, Bs + kk*SLB, tx, ty, c2);
        __syncthreads();
    }
    float4 bv0 = *(const float4*)&bias[tx*4];
    float4 bv1 = *(const float4*)&bias[64 + tx*4];
    #pragma unroll
    for (int i = 0; i < 8; i++) {
        int row = m0 + ((i < 4) ? ty*4 + i : 64 + ty*4 + i - 4);
        float2 f0 = up2(c2[i][0]), f1 = up2(c2[i][1]);
        float2 f2 = up2(c2[i][2]), f3 = up2(c2[i][3]);
        float v0[4] = {f0.x + bv0.x, f0.y + bv0.y, f1.x + bv0.z, f1.y + bv0.w};
        float v1[4] = {f2.x + bv1.x, f2.y + bv1.y, f3.x + bv1.z, f3.y + bv1.w};
        if (z == 2) {
            *(float4*)&g_v[(size_t)row*HH + tx*4]      = make_float4(v0[0],v0[1],v0[2],v0[3]);
            *(float4*)&g_v[(size_t)row*HH + 64 + tx*4] = make_float4(v1[0],v1[1],v1[2],v1[3]);
        } else {
            if (z == 0) {
                *(float4*)&g_q[(size_t)row*HH + tx*4]      = make_float4(v0[0],v0[1],v0[2],v0[3]);
                *(float4*)&g_q[(size_t)row*HH + 64 + tx*4] = make_float4(v1[0],v1[1],v1[2],v1[3]);
            }
            unsigned short* dh = (z == 0) ? g_qh : g_kh;
            unsigned short* dl = (z == 0) ? g_ql : g_kl;
            unsigned short h0[4], l0[4], h1[4], l1[4];
            #pragma unroll
            for (int t = 0; t < 4; t++) { fsplit(v0[t], h0[t], l0[t]); fsplit(v1[t], h1[t], l1[t]); }
            *(ushort4*)&dh[(size_t)row*HH + tx*4]      = make_ushort4(h0[0],h0[1],h0[2],h0[3]);
            *(ushort4*)&dh[(size_t)row*HH + 64 + tx*4] = make_ushort4(h1[0],h1[1],h1[2],h1[3]);
            *(ushort4*)&dl[(size_t)row*HH + tx*4]      = make_ushort4(l0[0],l0[1],l0[2],l0[3]);
            *(ushort4*)&dl[(size_t)row*HH + 64 + tx*4] = make_ushort4(l1[0],l1[1],l1[2],l1[3]);
        }
    }
}

// ============================================================
// K2: v transpose + split. grid (16,2,8), 256 thr
// ============================================================
__global__ __launch_bounds__(256) void vsplitT()
{
    __shared__ float tile[64][65];
    int b = blockIdx.z, k0 = blockIdx.x*64, n0 = blockIdx.y*64;
    int tx = threadIdx.x & 63, ty = threadIdx.x >> 6;
    #pragma unroll
    for (int i = 0; i < 16; i++)
        tile[ty + i*4][tx] = g_v[(size_t)(b*SS + k0 + ty + i*4)*HH + n0 + tx];
    __syncthreads();
    #pragma unroll
    for (int i = 0; i < 16; i++) {
        int n = n0 + ty + i*4;
        float val = tile[tx][ty + i*4];
        unsigned short h, l; fsplit(val, h, l);
        size_t o = ((size_t)b*HH + n)*SS + k0 + tx;
        g_vth[o] = h; g_vtl[o] = l;
    }
}

// ============================================================
// K3: rel_v transpose + split (p padded to 256). grid (128), 256 thr
// ============================================================
__global__ __launch_bounds__(256) void relvt_prep(const float* __restrict__ rel_v)
{
    int n = blockIdx.x, k = threadIdx.x;
    float val = (k < PP) ? rel_v[(size_t)k*HH + n] : 0.f;
    unsigned short h, l; fsplit(val, h, l);
    g_rvh[n*AW + k] = h; g_rvl[n*AW + k] = l;
}

// ============================================================
// K4: qrel = q @ rel_k^T (fp32). grid (128), 256 thr
// ============================================================
__global__ __launch_bounds__(256) void qrel_gemm(const float* __restrict__ rel_k)
{
    __shared__ __align__(16) float As[KC*SLA64];
    __shared__ __align__(16) float Bs[KC*SLB];
    __shared__ float rk[KC];
    int m0 = blockIdx.x * 64;
    int tid = threadIdx.x, tx = tid & 15, ty = tid >> 4;

    int raA = tid >> 2, kqA = tid & 3;
    int rb[2], kqb[2];
    #pragma unroll
    for (int i = 0; i < 2; i++) { int idx = tid + i*256; rb[i] = idx >> 2; kqb[i] = idx & 3; }

    ull c2[4][4];
    ull z2 = bcast2(0.f);
    #pragma unroll
    for (int i = 0; i < 4; i++) for (int j = 0; j < 4; j++) c2[i][j] = z2;
    float ce[4] = {};

    float4 pa, pb[2];
    float prk = (tid < KC) ? rel_k[(size_t)128*HH + tid] : 0.f;
    pa = *(const float4*)(g_q + (size_t)(m0 + raA)*HH + kqA*4);
    #pragma unroll
    for (int i = 0; i < 2; i++)
        pb[i] = *(const float4*)(rel_k + (size_t)rb[i]*HH + kqb[i]*4);

    for (int kc = 0; kc < HH; kc += KC) {
        {
            float* d = &As[(kqA*4)*SLA64 + 2*raA];
            *(float2*)(d + 0*SLA64) = make_float2(pa.x, pa.x);
            *(float2*)(d + 1*SLA64) = make_float2(pa.y, pa.y);
            *(float2*)(d + 2*SLA64) = make_float2(pa.z, pa.z);
            *(float2*)(d + 3*SLA64) = make_float2(pa.w, pa.w);
        }
        #pragma unroll
        for (int i = 0; i < 2; i++) {
            Bs[(kqb[i]*4+0)*SLB + rb[i]] = pb[i].x;
            Bs[(kqb[i]*4+1)*SLB + rb[i]] = pb[i].y;
            Bs[(kqb[i]*4+2)*SLB + rb[i]] = pb[i].z;
            Bs[(kqb[i]*4+3)*SLB + rb[i]] = pb[i].w;
        }
        if (tid < KC) rk[tid] = prk;
        __syncthreads();
        if (kc + KC < HH) {
            pa = *(const float4*)(g_q + (size_t)(m0 + raA)*HH + kc + KC + kqA*4);
            #pragma unroll
            for (int i = 0; i < 2; i++)
                pb[i] = *(const float4*)(rel_k + (size_t)rb[i]*HH + kc + KC + kqb[i]*4);
            if (tid < KC) prk = rel_k[(size_t)128*HH + kc + KC + tid];
        }
        #pragma unroll
        for (int kk = 0; kk < KC; kk++) {
            const float* akd = As + kk*SLA64;
            const float* bkp = Bs + kk*SLB;
            ulonglong2 a01 = *(const ulonglong2*)(akd + 8*ty);
            ulonglong2 a23 = *(const ulonglong2*)(akd + 8*ty + 4);
            ulonglong2 b0 = *(const ulonglong2*)(bkp + tx*4);
            ulonglong2 b1 = *(const ulonglong2*)(bkp + 64 + tx*4);
            ull aa[4] = {a01.x, a01.y, a23.x, a23.y};
            ull bb[4] = {b0.x, b0.y, b1.x, b1.y};
            #pragma unroll
            for (int i = 0; i < 4; i++)
                #pragma unroll
                for (int j = 0; j < 4; j++) ffma2(c2[i][j], aa[i], bb[j]);
            float rkv = rk[kk];
            #pragma unroll
            for (int i = 0; i < 4; i++) ce[i] += lo2f(aa[i]) * rkv;
        }
        __syncthreads();
    }
    #pragma unroll
    for (int i = 0; i < 4; i++) {
        int row = m0 + ty*4 + i;
        float2 f0 = up2(c2[i][0]), f1 = up2(c2[i][1]);
        float2 f2 = up2(c2[i][2]), f3 = up2(c2[i][3]);
        float* qr = g_qrel + (size_t)row*QSTR;
        *(float4*)&qr[tx*4]      = make_float4(f0.x, f0.y, f1.x, f1.y);
        *(float4*)&qr[64 + tx*4] = make_float4(f2.x, f2.y, f3.x, f3.y);
        if (tx == 0) qr[128] = ce[i];
    }
}

// ============================================================
// K5: scores via mma.sync bf16 3-GEMM. grid (8,8,8), 256 thr
// ============================================================
__global__ __launch_bounds__(256) void scores_mma(float* __restrict__ scores)
{
    extern __shared__ __align__(16) unsigned short smz[];
    unsigned short* SAh = smz;
    unsigned short* SAl = smz + 128*SMS;
    unsigned short* SBh = smz + 2*128*SMS;
    unsigned short* SBl = smz + 3*128*SMS;
    int tid = threadIdx.x;
    int b = blockIdx.z, m0 = blockIdx.y*128, n0 = blockIdx.x*128;

    const unsigned short* gqh = g_qh + (size_t)(b*SS + m0)*HH;
    const unsigned short* gql = g_ql + (size_t)(b*SS + m0)*HH;
    const unsigned short* gkh = g_kh + (size_t)(b*SS + n0)*HH;
    const unsigned short* gkl = g_kl + (size_t)(b*SS + n0)*HH;
    #pragma unroll
    for (int it = 0; it < 8; it++) {
        int idx = tid + it*256;
        int row = idx >> 4, c8 = (idx & 15)*8;
        *(uint4*)&SAh[row*SMS + c8] = *(const uint4*)(gqh + (size_t)row*HH + c8);
        *(uint4*)&SAl[row*SMS + c8] = *(const uint4*)(gql + (size_t)row*HH + c8);
        *(uint4*)&SBh[row*SMS + c8] = *(const uint4*)(gkh + (size_t)row*HH + c8);
        *(uint4*)&SBl[row*SMS + c8] = *(const uint4*)(gkl + (size_t)row*HH + c8);
    }
    __syncthreads();

    int warp = tid >> 5, lane = tid & 31;
    int mw = (warp >> 2)*64, nw = (warp & 3)*32;

    uint32_t aBh = smem_u32(&SAh[(mw + (lane & 15))*SMS]) + (lane >> 4)*16;
    uint32_t aBl = smem_u32(&SAl[(mw + (lane & 15))*SMS]) + (lane >> 4)*16;
    int bn = nw + ((lane >> 4)*8) + (lane & 7);
    int bk16 = ((lane >> 3) & 1)*8;
    uint32_t bBh = smem_u32(&SBh[bn*SMS + bk16]);
    uint32_t bBl = smem_u32(&SBl[bn*SMS + bk16]);

    float acc[4][4][4] = {};
    #pragma unroll
    for (int k = 0; k < 8; k++) {
        uint32_t ah[4][4], al[4][4], bh[2][4], bl[2][4];
        #pragma unroll
        for (int mt = 0; mt < 4; mt++) {
            uint32_t off = (mt*16*SMS + k*16)*2;
            ldmx4(ah[mt], aBh + off);
            ldmx4(al[mt], aBl + off);
        }
        #pragma unroll
        for (int np = 0; np < 2; np++) {
            uint32_t off = (np*16*SMS + k*16)*2;
            ldmx4(bh[np], bBh + off);
            ldmx4(bl[np], bBl + off);
        }
        #pragma unroll
        for (int mt = 0; mt < 4; mt++)
            #pragma unroll
            for (int nt = 0; nt < 4; nt++) {
                const uint32_t* fh = bh[nt >> 1] + (nt & 1)*2;
                const uint32_t* fl = bl[nt >> 1] + (nt & 1)*2;
                mma16816(acc[mt][nt], ah[mt], fh);
                mma16816(acc[mt][nt], ah[mt], fl);
                mma16816(acc[mt][nt], al[mt], fh);
            }
    }

    const float invscale = 0.08838834764831845f;
    #pragma unroll
    for (int mt = 0; mt < 4; mt++) {
        #pragma unroll
        for (int half = 0; half < 2; half++) {
            int row = m0 + mw + mt*16 + (lane >> 2) + half*8;
            size_t gr = (size_t)b*SS + row;
            const float* qr = g_qrel + gr*QSTR;
            float* srow = scores + gr*SS;
            #pragma unroll
            for (int nt = 0; nt < 4; nt++) {
                int col = n0 + nw + nt*8 + (lane & 3)*2;
                int d0 = col - row;     d0 = (d0 < -64) ? -64 : (d0 > 64) ? 64 : d0;
                int d1 = col + 1 - row; d1 = (d1 < -64) ? -64 : (d1 > 64) ? 64 : d1;
                float v0 = acc[mt][nt][half*2 + 0]*invscale + qr[d0 + 64];
                float v1 = acc[mt][nt][half*2 + 1]*invscale + qr[d1 + 64];
                *(float2*)&srow[col] = make_float2(v0, v1);
            }
        }
    }
}

// ============================================================
// K6: softmax + arel + bf16 splits. grid 8192, 256 thr
// ============================================================
__global__ __launch_bounds__(256) void softmax_arel(float* __restrict__ scores)
{
    __shared__ __align__(16) float rowbuf[SS];
    __shared__ float smx[8];
    __shared__ float sred[16];
    __shared__ float stot[2];
    int r = blockIdx.x, tid = threadIdx.x;
    int i = r & (SS - 1);
    float* sr = scores + (size_t)r * SS;
    int lane = tid & 31, wid = tid >> 5;

    float4 v = ((const float4*)sr)[tid];

    float m = fmaxf(fmaxf(v.x, v.y), fmaxf(v.z, v.w));
    #pragma unroll
    for (int o = 16; o > 0; o >>= 1) m = fmaxf(m, __shfl_xor_sync(0xffffffffu, m, o));
    if (lane == 0) smx[wid] = m;
    __syncthreads();
    m = fmaxf(fmaxf(fmaxf(smx[0], smx[1]), fmaxf(smx[2], smx[3])),
              fmaxf(fmaxf(smx[4], smx[5]), fmaxf(smx[6], smx[7])));
    __syncthreads();

    v.x = __expf(v.x - m); v.y = __expf(v.y - m);
    v.z = __expf(v.z - m); v.w = __expf(v.w - m);
    float s = v.x + v.y + v.z + v.w;
    #pragma unroll
    for (int o = 16; o > 0; o >>= 1) s += __shfl_xor_sync(0xffffffffu, s, o);
    if (lane == 0) smx[wid] = s;
    __syncthreads();
    s = smx[0] + smx[1] + smx[2] + smx[3] + smx[4] + smx[5] + smx[6] + smx[7];
    float inv = 1.0f / s;
    v.x *= inv; v.y *= inv; v.z *= inv; v.w *= inv;

    ((float4*)sr)[tid] = v;
    ((float4*)rowbuf)[tid] = v;

    {
        unsigned short h[4], l[4];
        fsplit(v.x, h[0], l[0]); fsplit(v.y, h[1], l[1]);
        fsplit(v.z, h[2], l[2]); fsplit(v.w, h[3], l[3]);
        *(ushort4*)&g_ah[(size_t)r*SS + tid*4] = make_ushort4(h[0], h[1], h[2], h[3]);
        *(ushort4*)&g_al[(size_t)r*SS + tid*4] = make_ushort4(l[0], l[1], l[2], l[3]);
    }

    int j0 = tid * 4;
    float p[4] = {v.x, v.y, v.z, v.w};
    float slo = 0.f, shi = 0.f;
    #pragma unroll
    for (int t = 0; t < 4; t++) {
        int d = j0 + t - i;
        if (d <= -64) slo += p[t];
        else if (d >= 64) shi += p[t];
    }
    #pragma unroll
    for (int o = 16; o > 0; o >>= 1) {
        slo += __shfl_xor_sync(0xffffffffu, slo, o);
        shi += __shfl_xor_sync(0xffffffffu, shi, o);
    }
    if (lane == 0) { sred[wid] = slo; sred[8 + wid] = shi; }
    __syncthreads();
    if (tid == 0) {
        float a = 0.f, bb2 = 0.f;
        #pragma unroll
        for (int w = 0; w < 8; w++) { a += sred[w]; bb2 += sred[8 + w]; }
        stot[0] = a; stot[1] = bb2;
    }
    __syncthreads();

    {
        float val;
        if (tid == 0)        val = stot[0];
        else if (tid == 128) val = stot[1];
        else if (tid < 128) {
            int j = i + tid - 64;
            val = (j >= 0 && j < SS) ? rowbuf[j] : 0.f;
        } else val = 0.f;
        unsigned short h, l; fsplit(val, h, l);
        g_arh[(size_t)r*AW + tid] = h;
        g_arl[(size_t)r*AW + tid] = l;
    }
}

// ============================================================
// K7: ctx via mma.sync, K=1280, z-split halves of 640.
// grid (16,8,2), 256 thr, tile 64x128
// ============================================================
__global__ __launch_bounds__(256) void ctx_mma()
{
    extern __shared__ __align__(16) unsigned short smz[];
    unsigned short* CAh = smz;
    unsigned short* CAl = smz + 64*SMC;
    unsigned short* CBh = smz + 2*64*SMC;
    unsigned short* CBl = smz + 2*64*SMC + 128*SMC;
    int tid = threadIdx.x;
    int m0 = blockIdx.x*64, b = blockIdx.y, z = blockIdx.z;

    int warp = tid >> 5, lane = tid & 31;
    int mw = (warp >> 2)*32, nw = (warp & 3)*32;

    uint32_t aBh = smem_u32(&CAh[(mw + (lane & 15))*SMC]) + (lane >> 4)*16;
    uint32_t aBl = smem_u32(&CAl[(mw + (lane & 15))*SMC]) + (lane >> 4)*16;
    int bn = nw + ((lane >> 4)*8) + (lane & 7);
    int bk16 = ((lane >> 3) & 1)*8;
    uint32_t bBh = smem_u32(&CBh[bn*SMC + bk16]);
    uint32_t bBl = smem_u32(&CBl[bn*SMC + bk16]);

    float acc[2][4][4] = {};

    for (int ci = 0; ci < 10; ci++) {
        int kglob = z*640 + ci*64;
        #pragma unroll
        for (int it = 0; it < 2; it++) {
            int idx = tid + it*256;
            int row = idx >> 3, c8 = (idx & 7)*8;
            const unsigned short *pah, *pal;
            if (kglob < SS) {
                size_t o = (size_t)(b*SS + m0 + row)*SS + kglob + c8;
                pah = g_ah + o; pal = g_al + o;
            } else {
                size_t o = (size_t)(b*SS + m0 + row)*AW + (kglob - SS) + c8;
                pah = g_arh + o; pal = g_arl + o;
            }
            *(uint4*)&CAh[row*SMC + c8] = *(const uint4*)pah;
            *(uint4*)&CAl[row*SMC + c8] = *(const uint4*)pal;
        }
        #pragma unroll
        for (int it = 0; it < 4; it++) {
            int idx = tid + it*256;
            int row = idx >> 3, c8 = (idx & 7)*8;
            const unsigned short *pbh, *pbl;
            if (kglob < SS) {
                size_t o = ((size_t)b*HH + row)*SS + kglob + c8;
                pbh = g_vth + o; pbl = g_vtl + o;
            } else {
                size_t o = (size_t)row*AW + (kglob - SS) + c8;
                pbh = g_rvh + o; pbl = g_rvl + o;
            }
            *(uint4*)&CBh[row*SMC + c8] = *(const uint4*)pbh;
            *(uint4*)&CBl[row*SMC + c8] = *(const uint4*)pbl;
        }
        __syncthreads();

        #pragma unroll
        for (int k = 0; k < 4; k++) {
            uint32_t ah[2][4], al[2][4], bh[2][4], bl[2][4];
            #pragma unroll
            for (int mt = 0; mt < 2; mt++) {
                uint32_t off = (mt*16*SMC + k*16)*2;
                ldmx4(ah[mt], aBh + off);
                ldmx4(al[mt], aBl + off);
            }
            #pragma unroll
            for (int np = 0; np < 2; np++) {
                uint32_t off = (np*16*SMC + k*16)*2;
                ldmx4(bh[np], bBh + off);
                ldmx4(bl[np], bBl + off);
            }
            #pragma unroll
            for (int mt = 0; mt < 2; mt++)
                #pragma unroll
                for (int nt = 0; nt < 4; nt++) {
                    const uint32_t* fh = bh[nt >> 1] + (nt & 1)*2;
                    const uint32_t* fl = bl[nt >> 1] + (nt & 1)*2;
                    mma16816(acc[mt][nt], ah[mt], fh);
                    mma16816(acc[mt][nt], ah[mt], fl);
                    mma16816(acc[mt][nt], al[mt], fh);
                }
        }
        __syncthreads();
    }

    float* out = z ? g_ctxB : g_ctxA;
    #pragma unroll
    for (int mt = 0; mt < 2; mt++) {
        #pragma unroll
        for (int half = 0; half < 2; half++) {
            int row = m0 + mw + mt*16 + (lane >> 2) + half*8;
            float* orow = out + ((size_t)b*SS + row)*HH;
            #pragma unroll
            for (int nt = 0; nt < 4; nt++) {
                int col = nw + nt*8 + (lane & 3)*2;
                *(float2*)&orow[col] = make_float2(acc[mt][nt][half*2], acc[mt][nt][half*2 + 1]);
            }
        }
    }
}

// ============================================================
// K8: out = (ctxA+ctxB)@Wo + bo; y = LN(out + x). grid (128), 256 thr
// ============================================================
__global__ __launch_bounds__(256) void outln_gemm(
    const float* __restrict__ x, const float* __restrict__ Wo,
    const float* __restrict__ bo, const float* __restrict__ gamma,
    const float* __restrict__ beta, float* __restrict__ y)
{
    __shared__ __align__(16) float As[KC*SLA64];
    __shared__ __align__(16) float Bs[KC*SLB];
    int m0 = blockIdx.x * 64;
    int tid = threadIdx.x, tx = tid & 15, ty = tid >> 4;

    int raA = tid >> 2, kqA = tid & 3;
    int krb[2], nqb[2];
    #pragma unroll
    for (int i = 0; i < 2; i++) { int idx = tid + i*256; krb[i] = idx >> 5; nqb[i] = idx & 31; }

    ull c2[4][4];
    ull z2 = bcast2(0.f);
    #pragma unroll
    for (int i = 0; i < 4; i++) for (int j = 0; j < 4; j++) c2[i][j] = z2;

    size_t aoff = (size_t)(m0 + raA)*HH + kqA*4;
    float4 a4 = *(const float4*)(g_ctxA + aoff);
    float4 b4 = *(const float4*)(g_ctxB + aoff);
    float4 pa = make_float4(a4.x + b4.x, a4.y + b4.y, a4.z + b4.z, a4.w + b4.w);
    float4 pb[2];
    #pragma unroll
    for (int i = 0; i < 2; i++)
        pb[i] = *(const float4*)(Wo + (size_t)krb[i]*HH + nqb[i]*4);

    for (int kc = 0; kc < HH; kc += KC) {
        {
            float* d = &As[(kqA*4)*SLA64 + 2*raA];
            *(float2*)(d + 0*SLA64) = make_float2(pa.x, pa.x);
            *(float2*)(d + 1*SLA64) = make_float2(pa.y, pa.y);
            *(float2*)(d + 2*SLA64) = make_float2(pa.z, pa.z);
            *(float2*)(d + 3*SLA64) = make_float2(pa.w, pa.w);
        }
        #pragma unroll
        for (int i = 0; i < 2; i++)
            *(float4*)&Bs[krb[i]*SLB + nqb[i]*4] = pb[i];
        __syncthreads();
        if (kc + KC < HH) {
            size_t o2 = (size_t)(m0 + raA)*HH + kc + KC + kqA*4;
            a4 = *(const float4*)(g_ctxA + o2);
            b4 = *(const float4*)(g_ctxB + o2);
            pa = make_float4(a4.x + b4.x, a4.y + b4.y, a4.z + b4.z, a4.w + b4.w);
            #pragma unroll
            for (int i = 0; i < 2; i++)
                pb[i] = *(const float4*)(Wo + (size_t)(kc + KC + krb[i])*HH + nqb[i]*4);
        }
        #pragma unroll
        for (int kk = 0; kk < KC; kk++)
            micro4(As + kk*SLA64, Bs + kk*SLB, tx, ty, c2);
        __syncthreads();
    }

    float4 b0 = *(const float4*)&bo[tx*4];
    float4 b1 = *(const float4*)&bo[64 + tx*4];
    float4 g0 = *(const float4*)&gamma[tx*4];
    float4 g1 = *(const float4*)&gamma[64 + tx*4];
    float4 e0 = *(const float4*)&beta[tx*4];
    float4 e1 = *(const float4*)&beta[64 + tx*4];
    float bv[8] = {b0.x,b0.y,b0.z,b0.w,b1.x,b1.y,b1.z,b1.w};
    float gv[8] = {g0.x,g0.y,g0.z,g0.w,g1.x,g1.y,g1.z,g1.w};
    float ev[8] = {e0.x,e0.y,e0.z,e0.w,e1.x,e1.y,e1.z,e1.w};

    #pragma unroll
    for (int i = 0; i < 4; i++) {
        int row = m0 + ty*4 + i;
        float4 x0 = *(const float4*)&x[(size_t)row*HH + tx*4];
        float4 x1 = *(const float4*)&x[(size_t)row*HH + 64 + tx*4];
        float xv[8] = {x0.x,x0.y,x0.z,x0.w,x1.x,x1.y,x1.z,x1.w};
        float yv[8];
        float s = 0.f;
        #pragma unroll
        for (int jp = 0; jp < 4; jp++) {
            float2 f = up2(c2[i][jp]);
            yv[jp*2]   = f.x + bv[jp*2]   + xv[jp*2];
            yv[jp*2+1] = f.y + bv[jp*2+1] + xv[jp*2+1];
            s += yv[jp*2] + yv[jp*2+1];
        }
        #pragma unroll
        for (int o = 1; o < 16; o <<= 1) s += __shfl_xor_sync(0xffffffffu, s, o, 16);
        float mu = s * (1.0f / HH);
        float q = 0.f;
        #pragma unroll
        for (int j = 0; j < 8; j++) { yv[j] -= mu; q += yv[j]*yv[j]; }
        #pragma unroll
        for (int o = 1; o < 16; o <<= 1) q += __shfl_xor_sync(0xffffffffu, q, o, 16);
        float rstd = rsqrtf(q * (1.0f / HH) + 1e-5f);
        *(float4*)&y[(size_t)row*HH + tx*4] =
            make_float4(yv[0]*rstd*gv[0] + ev[0], yv[1]*rstd*gv[1] + ev[1],
                        yv[2]*rstd*gv[2] + ev[2], yv[3]*rstd*gv[3] + ev[3]);
        *(float4*)&y[(size_t)row*HH + 64 + tx*4] =
            make_float4(yv[4]*rstd*gv[4] + ev[4], yv[5]*rstd*gv[5] + ev[5],
                        yv[6]*rstd*gv[6] + ev[6], yv[7]*rstd*gv[7] + ev[7]);
    }
}

// ============================================================
extern "C" void kernel_launch(void* const* d_in, const int* in_sizes, int n_in,
                              void* d_out, int out_size)
{
    const float* x     = (const float*)d_in[0];
    const float* Wq    = (const float*)d_in[1];
    const float* bq    = (const float*)d_in[2];
    const float* Wk    = (const float*)d_in[3];
    const float* bk    = (const float*)d_in[4];
    const float* Wv    = (const float*)d_in[5];
    const float* bv    = (const float*)d_in[6];
    const float* rel_k = (const float*)d_in[7];
    const float* rel_v = (const float*)d_in[8];
    const float* Wo    = (const float*)d_in[9];
    const float* bo    = (const float*)d_in[10];
    const float* gamma = (const float*)d_in[11];
    const float* beta  = (const float*)d_in[12];

    float* y    = (float*)d_out;
    float* attn = (float*)d_out + (size_t)BB * SS * HH;

    cudaFuncSetAttribute(scores_mma, cudaFuncAttributeMaxDynamicSharedMemorySize, SCORES_SMEM);
    cudaFuncSetAttribute(ctx_mma,    cudaFuncAttributeMaxDynamicSharedMemorySize, CTX_SMEM);

    qkv_gemm<<<dim3(64, 3), 256>>>(x, Wq, bq, Wk, bk, Wv, bv);
    vsplitT<<<dim3(16, 2, 8), 256>>>();
    relvt_prep<<<128, 256>>>(rel_v);
    qrel_gemm<<<128, 256>>>(rel_k);
    scores_mma<<<dim3(8, 8, 8), 256, SCORES_SMEM>>>(attn);
    softmax_arel<<<NROWS, 256>>>(attn);
    ctx_mma<<<dim3(16, 8, 2), 256, CTX_SMEM>>>();
    outln_gemm<<<128, 256>>>(x, Wo, bo, gamma, beta, y);
}

// round 8
// speedup vs baseline: 1.9662x; 1.0084x over previous
#include <cuda_runtime.h>
#include <cuda_bf16.h>
#include <math.h>
#include <stdint.h>

#define BB 8
#define SS 1024
#define HH 128
#define PP 129
#define QSTR 132
#define AW 256            // padded arel width
#define NROWS (BB*SS)
#define KC 16
#define SLA 260
#define SLA64 132
#define SLB 132
#define SMS 136           // scores/qrel smem tile stride (bf16 elems)
#define SMC 72            // ctx smem tile stride
#define SCORES_SMEM (4*128*SMS*2)                 // 139264 B
#define QREL_SMEM ((2*128 + 2*144)*SMS*2)         // 147968 B
#define CTX_SMEM ((2*64*SMC + 2*128*SMC)*2)       // 55296 B

typedef unsigned long long ull;

// -------- device scratch --------
__device__ float g_q[NROWS*HH];
__device__ float g_v[NROWS*HH];
__device__ float g_qrel[NROWS*QSTR];
__device__ float g_ctxA[NROWS*HH];
__device__ float g_ctxB[NROWS*HH];
__device__ unsigned short g_qh[NROWS*HH], g_ql[NROWS*HH];
__device__ unsigned short g_kh[NROWS*HH], g_kl[NROWS*HH];
__device__ unsigned short g_vth[BB*HH*SS], g_vtl[BB*HH*SS];
__device__ unsigned short g_ah[NROWS*SS], g_al[NROWS*SS];
__device__ unsigned short g_arh[NROWS*AW], g_arl[NROWS*AW];
__device__ unsigned short g_rvh[HH*AW], g_rvl[HH*AW];
__device__ unsigned short g_rkh[144*HH], g_rkl[144*HH];

// ---------------- f32x2 helpers ----------------
__device__ __forceinline__ ull bcast2(float x) {
    unsigned int u = __float_as_uint(x);
    ull r; asm("mov.b64 %0, {%1, %2};" : "=l"(r) : "r"(u), "r"(u));
    return r;
}
__device__ __forceinline__ void ffma2(ull& c, ull a, ull b) {
    asm("fma.rn.f32x2 %0, %1, %2, %0;" : "+l"(c) : "l"(a), "l"(b));
}
__device__ __forceinline__ float2 up2(ull v) {
    unsigned int lo, hi;
    asm("mov.b64 {%0, %1}, %2;" : "=r"(lo), "=r"(hi) : "l"(v));
    return make_float2(__uint_as_float(lo), __uint_as_float(hi));
}
__device__ __forceinline__ void fsplit(float f, unsigned short& h, unsigned short& l) {
    __nv_bfloat16 bh = __float2bfloat16(f);
    h = __bfloat16_as_ushort(bh);
    l = __bfloat16_as_ushort(__float2bfloat16(f - __bfloat162float(bh)));
}

// ---------------- mma.sync helpers ----------------
__device__ __forceinline__ uint32_t smem_u32(const void* p) {
    uint32_t a;
    asm("{ .reg .u64 t; cvta.to.shared.u64 t, %1; cvt.u32.u64 %0, t; }" : "=r"(a) : "l"(p));
    return a;
}
__device__ __forceinline__ void ldmx4(uint32_t* r, uint32_t addr) {
    asm volatile("ldmatrix.sync.aligned.m8n8.x4.shared.b16 {%0,%1,%2,%3}, [%4];"
        : "=r"(r[0]), "=r"(r[1]), "=r"(r[2]), "=r"(r[3]) : "r"(addr));
}
__device__ __forceinline__ void mma16816(float* c, const uint32_t* a, const uint32_t* b) {
    asm volatile("mma.sync.aligned.m16n8k16.row.col.f32.bf16.bf16.f32 "
        "{%0,%1,%2,%3}, {%4,%5,%6,%7}, {%8,%9}, {%0,%1,%2,%3};"
        : "+f"(c[0]), "+f"(c[1]), "+f"(c[2]), "+f"(c[3])
        : "r"(a[0]), "r"(a[1]), "r"(a[2]), "r"(a[3]), "r"(b[0]), "r"(b[1]));
}

// fp32 micro kernels (scalar GEMM path)
__device__ __forceinline__ void micro8(const float* __restrict__ akd,
                                       const float* __restrict__ bk,
                                       int tx, int ty, ull (&c2)[8][4]) {
    ulonglong2 a01 = *(const ulonglong2*)(akd + 8*ty);
    ulonglong2 a23 = *(const ulonglong2*)(akd + 8*ty + 4);
    ulonglong2 a45 = *(const ulonglong2*)(akd + 128 + 8*ty);
    ulonglong2 a67 = *(const ulonglong2*)(akd + 128 + 8*ty + 4);
    ulonglong2 b0 = *(const ulonglong2*)(bk + tx*4);
    ulonglong2 b1 = *(const ulonglong2*)(bk + 64 + tx*4);
    ull aa[8] = {a01.x, a01.y, a23.x, a23.y, a45.x, a45.y, a67.x, a67.y};
    ull bb[4] = {b0.x, b0.y, b1.x, b1.y};
    #pragma unroll
    for (int i = 0; i < 8; i++)
        #pragma unroll
        for (int j = 0; j < 4; j++) ffma2(c2[i][j], aa[i], bb[j]);
}
__device__ __forceinline__ void micro4(const float* __restrict__ akd,
                                       const float* __restrict__ bk,
                                       int tx, int ty, ull (&c2)[4][4]) {
    ulonglong2 a01 = *(const ulonglong2*)(akd + 8*ty);
    ulonglong2 a23 = *(const ulonglong2*)(akd + 8*ty + 4);
    ulonglong2 b0 = *(const ulonglong2*)(bk + tx*4);
    ulonglong2 b1 = *(const ulonglong2*)(bk + 64 + tx*4);
    ull aa[4] = {a01.x, a01.y, a23.x, a23.y};
    ull bb[4] = {b0.x, b0.y, b1.x, b1.y};
    #pragma unroll
    for (int i = 0; i < 4; i++)
        #pragma unroll
        for (int j = 0; j < 4; j++) ffma2(c2[i][j], aa[i], bb[j]);
}

// ============================================================
// K1: q/k/v = x@W + b. tile 128x128, grid (64,3), 256 thr.
// ============================================================
__global__ __launch_bounds__(256) void qkv_gemm(
    const float* __restrict__ x,
    const float* __restrict__ Wq, const float* __restrict__ bq,
    const float* __restrict__ Wk, const float* __restrict__ bk,
    const float* __restrict__ Wv, const float* __restrict__ bv)
{
    __shared__ __align__(16) float As[KC*SLA];
    __shared__ __align__(16) float Bs[KC*SLB];
    int z = blockIdx.y;
    const float* W    = (z == 0) ? Wq : (z == 1) ? Wk : Wv;
    const float* bias = (z == 0) ? bq : (z == 1) ? bk : bv;
    int m0 = blockIdx.x * 128;
    int tid = threadIdx.x, tx = tid & 15, ty = tid >> 4;

    int ra[2], kqa[2], krb[2], nqb[2];
    #pragma unroll
    for (int i = 0; i < 2; i++) {
        int idx = tid + i*256;
        ra[i] = idx >> 2; kqa[i] = idx & 3;
        krb[i] = idx >> 5; nqb[i] = idx & 31;
    }

    ull c2[8][4];
    ull z2 = bcast2(0.f);
    #pragma unroll
    for (int i = 0; i < 8; i++) for (int j = 0; j < 4; j++) c2[i][j] = z2;

    float4 pa[2], pb[2];
    #pragma unroll
    for (int i = 0; i < 2; i++) {
        pa[i] = *(const float4*)(x + (size_t)(m0 + ra[i])*HH + kqa[i]*4);
        pb[i] = *(const float4*)(W + (size_t)krb[i]*HH + nqb[i]*4);
    }
    for (int kc = 0; kc < HH; kc += KC) {
        #pragma unroll
        for (int i = 0; i < 2; i++) {
            float* d = &As[(kqa[i]*4)*SLA + 2*ra[i]];
            *(float2*)(d + 0*SLA) = make_float2(pa[i].x, pa[i].x);
            *(float2*)(d + 1*SLA) = make_float2(pa[i].y, pa[i].y);
            *(float2*)(d + 2*SLA) = make_float2(pa[i].z, pa[i].z);
            *(float2*)(d + 3*SLA) = make_float2(pa[i].w, pa[i].w);
            *(float4*)&Bs[krb[i]*SLB + nqb[i]*4] = pb[i];
        }
        __syncthreads();
        if (kc + KC < HH) {
            #pragma unroll
            for (int i = 0; i < 2; i++) {
                pa[i] = *(const float4*)(x + (size_t)(m0 + ra[i])*HH + kc + KC + kqa[i]*4);
                pb[i] = *(const float4*)(W + (size_t)(kc + KC + krb[i])*HH + nqb[i]*4);
            }
        }
        #pragma unroll
        for (int kk = 0; kk < KC; kk++)
            micro8(As + kk*SLA, Bs + kk*SLB, tx, ty, c2);
        __syncthreads();
    }
    float4 bv0 = *(const float4*)&bias[tx*4];
    float4 bv1 = *(const float4*)&bias[64 + tx*4];
    #pragma unroll
    for (int i = 0; i < 8; i++) {
        int row = m0 + ((i < 4) ? ty*4 + i : 64 + ty*4 + i - 4);
        float2 f0 = up2(c2[i][0]), f1 = up2(c2[i][1]);
        float2 f2 = up2(c2[i][2]), f3 = up2(c2[i][3]);
        float v0[4] = {f0.x + bv0.x, f0.y + bv0.y, f1.x + bv0.z, f1.y + bv0.w};
        float v1[4] = {f2.x + bv1.x, f2.y + bv1.y, f3.x + bv1.z, f3.y + bv1.w};
        if (z == 2) {
            *(float4*)&g_v[(size_t)row*HH + tx*4]      = make_float4(v0[0],v0[1],v0[2],v0[3]);
            *(float4*)&g_v[(size_t)row*HH + 64 + tx*4] = make_float4(v1[0],v1[1],v1[2],v1[3]);
        } else {
            if (z == 0) {
                *(float4*)&g_q[(size_t)row*HH + tx*4]      = make_float4(v0[0],v0[1],v0[2],v0[3]);
                *(float4*)&g_q[(size_t)row*HH + 64 + tx*4] = make_float4(v1[0],v1[1],v1[2],v1[3]);
            }
            unsigned short* dh = (z == 0) ? g_qh : g_kh;
            unsigned short* dl = (z == 0) ? g_ql : g_kl;
            unsigned short h0[4], l0[4], h1[4], l1[4];
            #pragma unroll
            for (int t = 0; t < 4; t++) { fsplit(v0[t], h0[t], l0[t]); fsplit(v1[t], h1[t], l1[t]); }
            *(ushort4*)&dh[(size_t)row*HH + tx*4]      = make_ushort4(h0[0],h0[1],h0[2],h0[3]);
            *(ushort4*)&dh[(size_t)row*HH + 64 + tx*4] = make_ushort4(h1[0],h1[1],h1[2],h1[3]);
            *(ushort4*)&dl[(size_t)row*HH + tx*4]      = make_ushort4(l0[0],l0[1],l0[2],l0[3]);
            *(ushort4*)&dl[(size_t)row*HH + 64 + tx*4] = make_ushort4(l1[0],l1[1],l1[2],l1[3]);
        }
    }
}

// ============================================================
// K2: v transpose + split. grid (16,2,8), 256 thr
// ============================================================
__global__ __launch_bounds__(256) void vsplitT()
{
    __shared__ float tile[64][65];
    int b = blockIdx.z, k0 = blockIdx.x*64, n0 = blockIdx.y*64;
    int tx = threadIdx.x & 63, ty = threadIdx.x >> 6;
    #pragma unroll
    for (int i = 0; i < 16; i++)
        tile[ty + i*4][tx] = g_v[(size_t)(b*SS + k0 + ty + i*4)*HH + n0 + tx];
    __syncthreads();
    #pragma unroll
    for (int i = 0; i < 16; i++) {
        int n = n0 + ty + i*4;
        float val = tile[tx][ty + i*4];
        unsigned short h, l; fsplit(val, h, l);
        size_t o = ((size_t)b*HH + n)*SS + k0 + tx;
        g_vth[o] = h; g_vtl[o] = l;
    }
}

// ============================================================
// K3: rel_v transpose + split (p padded to 256). grid (128), 256 thr
// ============================================================
__global__ __launch_bounds__(256) void relvt_prep(const float* __restrict__ rel_v)
{
    int n = blockIdx.x, k = threadIdx.x;
    float val = (k < PP) ? rel_v[(size_t)k*HH + n] : 0.f;
    unsigned short h, l; fsplit(val, h, l);
    g_rvh[n*AW + k] = h; g_rvl[n*AW + k] = l;
}

// ============================================================
// K3b: rel_k split (rows padded to 144). grid (144), 128 thr
// ============================================================
__global__ __launch_bounds__(128) void rksplit_prep(const float* __restrict__ rel_k)
{
    int n = blockIdx.x, k = threadIdx.x;
    float val = (n < PP) ? rel_k[(size_t)n*HH + k] : 0.f;
    unsigned short h, l; fsplit(val, h, l);
    g_rkh[n*HH + k] = h; g_rkl[n*HH + k] = l;
}

// ============================================================
// K4: qrel = q @ rel_k^T via mma (N=136 covers p=0..128). grid (64), 256 thr
// ============================================================
__global__ __launch_bounds__(256) void qrel_mma()
{
    extern __shared__ __align__(16) unsigned short smz[];
    unsigned short* QAh = smz;
    unsigned short* QAl = smz + 128*SMS;
    unsigned short* QBh = smz + 2*128*SMS;
    unsigned short* QBl = smz + 2*128*SMS + 144*SMS;
    int tid = threadIdx.x;
    int m0 = blockIdx.x * 128;

    #pragma unroll
    for (int it = 0; it < 8; it++) {
        int idx = tid + it*256;
        int row = idx >> 4, c8 = (idx & 15)*8;
        *(uint4*)&QAh[row*SMS + c8] = *(const uint4*)(g_qh + (size_t)(m0 + row)*HH + c8);
        *(uint4*)&QAl[row*SMS + c8] = *(const uint4*)(g_ql + (size_t)(m0 + row)*HH + c8);
    }
    #pragma unroll
    for (int it = 0; it < 9; it++) {
        int idx = tid + it*256;
        int row = idx >> 4, c8 = (idx & 15)*8;
        *(uint4*)&QBh[row*SMS + c8] = *(const uint4*)(g_rkh + (size_t)row*HH + c8);
        *(uint4*)&QBl[row*SMS + c8] = *(const uint4*)(g_rkl + (size_t)row*HH + c8);
    }
    __syncthreads();

    int warp = tid >> 5, lane = tid & 31;
    int mw = warp * 16;

    uint32_t aBh = smem_u32(&QAh[(mw + (lane & 15))*SMS]) + (lane >> 4)*16;
    uint32_t aBl = smem_u32(&QAl[(mw + (lane & 15))*SMS]) + (lane >> 4)*16;
    int bn_base = ((lane >> 4)*8) + (lane & 7);
    int bk16 = ((lane >> 3) & 1)*8;
    uint32_t bBh = smem_u32(&QBh[bn_base*SMS + bk16]);
    uint32_t bBl = smem_u32(&QBl[bn_base*SMS + bk16]);

    float acc[17][4] = {};
    #pragma unroll
    for (int k = 0; k < 8; k++) {
        uint32_t ah[4], al[4], bh[9][4], bl[9][4];
        uint32_t aoff = (k*16)*2;
        ldmx4(ah, aBh + aoff);
        ldmx4(al, aBl + aoff);
        #pragma unroll
        for (int np = 0; np < 9; np++) {
            uint32_t off = (np*16*SMS + k*16)*2;
            ldmx4(bh[np], bBh + off);
            ldmx4(bl[np], bBl + off);
        }
        #pragma unroll
        for (int nt = 0; nt < 17; nt++) {
            const uint32_t* fh = bh[nt >> 1] + (nt & 1)*2;
            const uint32_t* fl = bl[nt >> 1] + (nt & 1)*2;
            mma16816(acc[nt], ah, fh);
            mma16816(acc[nt], ah, fl);
            mma16816(acc[nt], al, fh);
        }
    }

    #pragma unroll
    for (int half = 0; half < 2; half++) {
        int row = m0 + mw + (lane >> 2) + half*8;
        float* qr = g_qrel + (size_t)row*QSTR;
        #pragma unroll
        for (int nt = 0; nt < 17; nt++) {
            int col = nt*8 + (lane & 3)*2;
            if (nt < 16 || (lane & 3) == 0)
                *(float2*)&qr[col] = make_float2(acc[nt][half*2], acc[nt][half*2 + 1]);
        }
    }
}

// ============================================================
// K5: scores via mma.sync bf16 3-GEMM. grid (8,8,8), 256 thr
// ============================================================
__global__ __launch_bounds__(256) void scores_mma(float* __restrict__ scores)
{
    extern __shared__ __align__(16) unsigned short smz[];
    unsigned short* SAh = smz;
    unsigned short* SAl = smz + 128*SMS;
    unsigned short* SBh = smz + 2*128*SMS;
    unsigned short* SBl = smz + 3*128*SMS;
    int tid = threadIdx.x;
    int b = blockIdx.z, m0 = blockIdx.y*128, n0 = blockIdx.x*128;

    const unsigned short* gqh = g_qh + (size_t)(b*SS + m0)*HH;
    const unsigned short* gql = g_ql + (size_t)(b*SS + m0)*HH;
    const unsigned short* gkh = g_kh + (size_t)(b*SS + n0)*HH;
    const unsigned short* gkl = g_kl + (size_t)(b*SS + n0)*HH;
    #pragma unroll
    for (int it = 0; it < 8; it++) {
        int idx = tid + it*256;
        int row = idx >> 4, c8 = (idx & 15)*8;
        *(uint4*)&SAh[row*SMS + c8] = *(const uint4*)(gqh + (size_t)row*HH + c8);
        *(uint4*)&SAl[row*SMS + c8] = *(const uint4*)(gql + (size_t)row*HH + c8);
        *(uint4*)&SBh[row*SMS + c8] = *(const uint4*)(gkh + (size_t)row*HH + c8);
        *(uint4*)&SBl[row*SMS + c8] = *(const uint4*)(gkl + (size_t)row*HH + c8);
    }
    __syncthreads();

    int warp = tid >> 5, lane = tid & 31;
    int mw = (warp >> 2)*64, nw = (warp & 3)*32;

    uint32_t aBh = smem_u32(&SAh[(mw + (lane & 15))*SMS]) + (lane >> 4)*16;
    uint32_t aBl = smem_u32(&SAl[(mw + (lane & 15))*SMS]) + (lane >> 4)*16;
    int bn = nw + ((lane >> 4)*8) + (lane & 7);
    int bk16 = ((lane >> 3) & 1)*8;
    uint32_t bBh = smem_u32(&SBh[bn*SMS + bk16]);
    uint32_t bBl = smem_u32(&SBl[bn*SMS + bk16]);

    float acc[4][4][4] = {};
    #pragma unroll
    for (int k = 0; k < 8; k++) {
        uint32_t ah[4][4], al[4][4], bh[2][4], bl[2][4];
        #pragma unroll
        for (int mt = 0; mt < 4; mt++) {
            uint32_t off = (mt*16*SMS + k*16)*2;
            ldmx4(ah[mt], aBh + off);
            ldmx4(al[mt], aBl + off);
        }
        #pragma unroll
        for (int np = 0; np < 2; np++) {
            uint32_t off = (np*16*SMS + k*16)*2;
            ldmx4(bh[np], bBh + off);
            ldmx4(bl[np], bBl + off);
        }
        #pragma unroll
        for (int mt = 0; mt < 4; mt++)
            #pragma unroll
            for (int nt = 0; nt < 4; nt++) {
                const uint32_t* fh = bh[nt >> 1] + (nt & 1)*2;
                const uint32_t* fl = bl[nt >> 1] + (nt & 1)*2;
                mma16816(acc[mt][nt], ah[mt], fh);
                mma16816(acc[mt][nt], ah[mt], fl);
                mma16816(acc[mt][nt], al[mt], fh);
            }
    }

    const float invscale = 0.08838834764831845f;
    #pragma unroll
    for (int mt = 0; mt < 4; mt++) {
        #pragma unroll
        for (int half = 0; half < 2; half++) {
            int row = m0 + mw + mt*16 + (lane >> 2) + half*8;
            size_t gr = (size_t)b*SS + row;
            const float* qr = g_qrel + gr*QSTR;
            float* srow = scores + gr*SS;
            #pragma unroll
            for (int nt = 0; nt < 4; nt++) {
                int col = n0 + nw + nt*8 + (lane & 3)*2;
                int d0 = col - row;     d0 = (d0 < -64) ? -64 : (d0 > 64) ? 64 : d0;
                int d1 = col + 1 - row; d1 = (d1 < -64) ? -64 : (d1 > 64) ? 64 : d1;
                float v0 = acc[mt][nt][half*2 + 0]*invscale + qr[d0 + 64];
                float v1 = acc[mt][nt][half*2 + 1]*invscale + qr[d1 + 64];
                *(float2*)&srow[col] = make_float2(v0, v1);
            }
        }
    }
}

// ============================================================
// K6: softmax + arel + bf16 splits. grid 8192, 256 thr
// ============================================================
__global__ __launch_bounds__(256) void softmax_arel(float* __restrict__ scores)
{
    __shared__ __align__(16) float rowbuf[SS];
    __shared__ float smx[8];
    __shared__ float sred[16];
    __shared__ float stot[2];
    int r = blockIdx.x, tid = threadIdx.x;
    int i = r & (SS - 1);
    float* sr = scores + (size_t)r * SS;
    int lane = tid & 31, wid = tid >> 5;

    float4 v = ((const float4*)sr)[tid];

    float m = fmaxf(fmaxf(v.x, v.y), fmaxf(v.z, v.w));
    #pragma unroll
    for (int o = 16; o > 0; o >>= 1) m = fmaxf(m, __shfl_xor_sync(0xffffffffu, m, o));
    if (lane == 0) smx[wid] = m;
    __syncthreads();
    m = fmaxf(fmaxf(fmaxf(smx[0], smx[1]), fmaxf(smx[2], smx[3])),
              fmaxf(fmaxf(smx[4], smx[5]), fmaxf(smx[6], smx[7])));
    __syncthreads();

    v.x = __expf(v.x - m); v.y = __expf(v.y - m);
    v.z = __expf(v.z - m); v.w = __expf(v.w - m);
    float s = v.x + v.y + v.z + v.w;
    #pragma unroll
    for (int o = 16; o > 0; o >>= 1) s += __shfl_xor_sync(0xffffffffu, s, o);
    if (lane == 0) smx[wid] = s;
    __syncthreads();
    s = smx[0] + smx[1] + smx[2] + smx[3] + smx[4] + smx[5] + smx[6] + smx[7];
    float inv = 1.0f / s;
    v.x *= inv; v.y *= inv; v.z *= inv; v.w *= inv;

    ((float4*)sr)[tid] = v;
    ((float4*)rowbuf)[tid] = v;

    {
        unsigned short h[4], l[4];
        fsplit(v.x, h[0], l[0]); fsplit(v.y, h[1], l[1]);
        fsplit(v.z, h[2], l[2]); fsplit(v.w, h[3], l[3]);
        *(ushort4*)&g_ah[(size_t)r*SS + tid*4] = make_ushort4(h[0], h[1], h[2], h[3]);
        *(ushort4*)&g_al[(size_t)r*SS + tid*4] = make_ushort4(l[0], l[1], l[2], l[3]);
    }

    int j0 = tid * 4;
    float p[4] = {v.x, v.y, v.z, v.w};
    float slo = 0.f, shi = 0.f;
    #pragma unroll
    for (int t = 0; t < 4; t++) {
        int d = j0 + t - i;
        if (d <= -64) slo += p[t];
        else if (d >= 64) shi += p[t];
    }
    #pragma unroll
    for (int o = 16; o > 0; o >>= 1) {
        slo += __shfl_xor_sync(0xffffffffu, slo, o);
        shi += __shfl_xor_sync(0xffffffffu, shi, o);
    }
    if (lane == 0) { sred[wid] = slo; sred[8 + wid] = shi; }
    __syncthreads();
    if (tid == 0) {
        float a = 0.f, bb2 = 0.f;
        #pragma unroll
        for (int w = 0; w < 8; w++) { a += sred[w]; bb2 += sred[8 + w]; }
        stot[0] = a; stot[1] = bb2;
    }
    __syncthreads();

    {
        float val;
        if (tid == 0)        val = stot[0];
        else if (tid == 128) val = stot[1];
        else if (tid < 128) {
            int j = i + tid - 64;
            val = (j >= 0 && j < SS) ? rowbuf[j] : 0.f;
        } else val = 0.f;
        unsigned short h, l; fsplit(val, h, l);
        g_arh[(size_t)r*AW + tid] = h;
        g_arl[(size_t)r*AW + tid] = l;
    }
}

// ============================================================
// K7: ctx via mma.sync, K=1280, z-split halves of 640, reg-prefetch.
// grid (16,8,2), 256 thr, tile 64x128
// ============================================================
__device__ __forceinline__ void ctx_loadA(int b, int m0, int kglob, int row, int c8,
                                          uint4& h, uint4& l) {
    if (kglob < SS) {
        size_t o = (size_t)(b*SS + m0 + row)*SS + kglob + c8;
        h = *(const uint4*)&g_ah[o]; l = *(const uint4*)&g_al[o];
    } else {
        size_t o = (size_t)(b*SS + m0 + row)*AW + (kglob - SS) + c8;
        h = *(const uint4*)&g_arh[o]; l = *(const uint4*)&g_arl[o];
    }
}
__device__ __forceinline__ void ctx_loadB(int b, int kglob, int row, int c8,
                                          uint4& h, uint4& l) {
    if (kglob < SS) {
        size_t o = ((size_t)b*HH + row)*SS + kglob + c8;
        h = *(const uint4*)&g_vth[o]; l = *(const uint4*)&g_vtl[o];
    } else {
        size_t o = (size_t)row*AW + (kglob - SS) + c8;
        h = *(const uint4*)&g_rvh[o]; l = *(const uint4*)&g_rvl[o];
    }
}

__global__ __launch_bounds__(256) void ctx_mma()
{
    extern __shared__ __align__(16) unsigned short smz[];
    unsigned short* CAh = smz;
    unsigned short* CAl = smz + 64*SMC;
    unsigned short* CBh = smz + 2*64*SMC;
    unsigned short* CBl = smz + 2*64*SMC + 128*SMC;
    int tid = threadIdx.x;
    int m0 = blockIdx.x*64, b = blockIdx.y, z = blockIdx.z;

    int warp = tid >> 5, lane = tid & 31;
    int mw = (warp >> 2)*32, nw = (warp & 3)*32;

    uint32_t aBh = smem_u32(&CAh[(mw + (lane & 15))*SMC]) + (lane >> 4)*16;
    uint32_t aBl = smem_u32(&CAl[(mw + (lane & 15))*SMC]) + (lane >> 4)*16;
    int bn = nw + ((lane >> 4)*8) + (lane & 7);
    int bk16 = ((lane >> 3) & 1)*8;
    uint32_t bBh = smem_u32(&CBh[bn*SMC + bk16]);
    uint32_t bBl = smem_u32(&CBl[bn*SMC + bk16]);

    int arow[2], ac8[2], brow[4], bc8[4];
    #pragma unroll
    for (int it = 0; it < 2; it++) { int idx = tid + it*256; arow[it] = idx >> 3; ac8[it] = (idx & 7)*8; }
    #pragma unroll
    for (int it = 0; it < 4; it++) { int idx = tid + it*256; brow[it] = idx >> 3; bc8[it] = (idx & 7)*8; }

    float acc[2][4][4] = {};
    uint4 rah[2], ral[2], rbh[4], rbl[4];

    {
        int kglob = z*640;
        #pragma unroll
        for (int it = 0; it < 2; it++) ctx_loadA(b, m0, kglob, arow[it], ac8[it], rah[it], ral[it]);
        #pragma unroll
        for (int it = 0; it < 4; it++) ctx_loadB(b, kglob, brow[it], bc8[it], rbh[it], rbl[it]);
    }

    for (int ci = 0; ci < 10; ci++) {
        #pragma unroll
        for (int it = 0; it < 2; it++) {
            *(uint4*)&CAh[arow[it]*SMC + ac8[it]] = rah[it];
            *(uint4*)&CAl[arow[it]*SMC + ac8[it]] = ral[it];
        }
        #pragma unroll
        for (int it = 0; it < 4; it++) {
            *(uint4*)&CBh[brow[it]*SMC + bc8[it]] = rbh[it];
            *(uint4*)&CBl[brow[it]*SMC + bc8[it]] = rbl[it];
        }
        __syncthreads();
        if (ci < 9) {
            int kglob = z*640 + (ci + 1)*64;
            #pragma unroll
            for (int it = 0; it < 2; it++) ctx_loadA(b, m0, kglob, arow[it], ac8[it], rah[it], ral[it]);
            #pragma unroll
            for (int it = 0; it < 4; it++) ctx_loadB(b, kglob, brow[it], bc8[it], rbh[it], rbl[it]);
        }

        #pragma unroll
        for (int k = 0; k < 4; k++) {
            uint32_t ah[2][4], al[2][4], bh[2][4], bl[2][4];
            #pragma unroll
            for (int mt = 0; mt < 2; mt++) {
                uint32_t off = (mt*16*SMC + k*16)*2;
                ldmx4(ah[mt], aBh + off);
                ldmx4(al[mt], aBl + off);
            }
            #pragma unroll
            for (int np = 0; np < 2; np++) {
                uint32_t off = (np*16*SMC + k*16)*2;
                ldmx4(bh[np], bBh + off);
                ldmx4(bl[np], bBl + off);
            }
            #pragma unroll
            for (int mt = 0; mt < 2; mt++)
                #pragma unroll
                for (int nt = 0; nt < 4; nt++) {
                    const uint32_t* fh = bh[nt >> 1] + (nt & 1)*2;
                    const uint32_t* fl = bl[nt >> 1] + (nt & 1)*2;
                    mma16816(acc[mt][nt], ah[mt], fh);
                    mma16816(acc[mt][nt], ah[mt], fl);
                    mma16816(acc[mt][nt], al[mt], fh);
                }
        }
        __syncthreads();
    }

    float* out = z ? g_ctxB : g_ctxA;
    #pragma unroll
    for (int mt = 0; mt < 2; mt++) {
        #pragma unroll
        for (int half = 0; half < 2; half++) {
            int row = m0 + mw + mt*16 + (lane >> 2) + half*8;
            float* orow = out + ((size_t)b*SS + row)*HH;
            #pragma unroll
            for (int nt = 0; nt < 4; nt++) {
                int col = nw + nt*8 + (lane & 3)*2;
                *(float2*)&orow[col] = make_float2(acc[mt][nt][half*2], acc[mt][nt][half*2 + 1]);
            }
        }
    }
}

// ============================================================
// K8: out = (ctxA+ctxB)@Wo + bo; y = LN(out + x). grid (128), 256 thr
// ============================================================
__global__ __launch_bounds__(256) void outln_gemm(
    const float* __restrict__ x, const float* __restrict__ Wo,
    const float* __restrict__ bo, const float* __restrict__ gamma,
    const float* __restrict__ beta, float* __restrict__ y)
{
    __shared__ __align__(16) float As[KC*SLA64];
    __shared__ __align__(16) float Bs[KC*SLB];
    int m0 = blockIdx.x * 64;
    int tid = threadIdx.x, tx = tid & 15, ty = tid >> 4;

    int raA = tid >> 2, kqA = tid & 3;
    int krb[2], nqb[2];
    #pragma unroll
    for (int i = 0; i < 2; i++) { int idx = tid + i*256; krb[i] = idx >> 5; nqb[i] = idx & 31; }

    ull c2[4][4];
    ull z2 = bcast2(0.f);
    #pragma unroll
    for (int i = 0; i < 4; i++) for (int j = 0; j < 4; j++) c2[i][j] = z2;

    size_t aoff = (size_t)(m0 + raA)*HH + kqA*4;
    float4 a4 = *(const float4*)(g_ctxA + aoff);
    float4 b4 = *(const float4*)(g_ctxB + aoff);
    float4 pa = make_float4(a4.x + b4.x, a4.y + b4.y, a4.z + b4.z, a4.w + b4.w);
    float4 pb[2];
    #pragma unroll
    for (int i = 0; i < 2; i++)
        pb[i] = *(const float4*)(Wo + (size_t)krb[i]*HH + nqb[i]*4);

    for (int kc = 0; kc < HH; kc += KC) {
        {
            float* d = &As[(kqA*4)*SLA64 + 2*raA];
            *(float2*)(d + 0*SLA64) = make_float2(pa.x, pa.x);
            *(float2*)(d + 1*SLA64) = make_float2(pa.y, pa.y);
            *(float2*)(d + 2*SLA64) = make_float2(pa.z, pa.z);
            *(float2*)(d + 3*SLA64) = make_float2(pa.w, pa.w);
        }
        #pragma unroll
        for (int i = 0; i < 2; i++)
            *(float4*)&Bs[krb[i]*SLB + nqb[i]*4] = pb[i];
        __syncthreads();
        if (kc + KC < HH) {
            size_t o2 = (size_t)(m0 + raA)*HH + kc + KC + kqA*4;
            a4 = *(const float4*)(g_ctxA + o2);
            b4 = *(const float4*)(g_ctxB + o2);
            pa = make_float4(a4.x + b4.x, a4.y + b4.y, a4.z + b4.z, a4.w + b4.w);
            #pragma unroll
            for (int i = 0; i < 2; i++)
                pb[i] = *(const float4*)(Wo + (size_t)(kc + KC + krb[i])*HH + nqb[i]*4);
        }
        #pragma unroll
        for (int kk = 0; kk < KC; kk++)
            micro4(As + kk*SLA64, Bs + kk*SLB, tx, ty, c2);
        __syncthreads();
    }

    float4 b0 = *(const float4*)&bo[tx*4];
    float4 b1 = *(const float4*)&bo[64 + tx*4];
    float4 g0 = *(const float4*)&gamma[tx*4];
    float4 g1 = *(const float4*)&gamma[64 + tx*4];
    float4 e0 = *(const float4*)&beta[tx*4];
    float4 e1 = *(const float4*)&beta[64 + tx*4];
    float bv[8] = {b0.x,b0.y,b0.z,b0.w,b1.x,b1.y,b1.z,b1.w};
    float gv[8] = {g0.x,g0.y,g0.z,g0.w,g1.x,g1.y,g1.z,g1.w};
    float ev[8] = {e0.x,e0.y,e0.z,e0.w,e1.x,e1.y,e1.z,e1.w};

    #pragma unroll
    for (int i = 0; i < 4; i++) {
        int row = m0 + ty*4 + i;
        float4 x0 = *(const float4*)&x[(size_t)row*HH + tx*4];
        float4 x1 = *(const float4*)&x[(size_t)row*HH + 64 + tx*4];
        float xv[8] = {x0.x,x0.y,x0.z,x0.w,x1.x,x1.y,x1.z,x1.w};
        float yv[8];
        float s = 0.f;
        #pragma unroll
        for (int jp = 0; jp < 4; jp++) {
            float2 f = up2(c2[i][jp]);
            yv[jp*2]   = f.x + bv[jp*2]   + xv[jp*2];
            yv[jp*2+1] = f.y + bv[jp*2+1] + xv[jp*2+1];
            s += yv[jp*2] + yv[jp*2+1];
        }
        #pragma unroll
        for (int o = 1; o < 16; o <<= 1) s += __shfl_xor_sync(0xffffffffu, s, o, 16);
        float mu = s * (1.0f / HH);
        float q = 0.f;
        #pragma unroll
        for (int j = 0; j < 8; j++) { yv[j] -= mu; q += yv[j]*yv[j]; }
        #pragma unroll
        for (int o = 1; o < 16; o <<= 1) q += __shfl_xor_sync(0xffffffffu, q, o, 16);
        float rstd = rsqrtf(q * (1.0f / HH) + 1e-5f);
        *(float4*)&y[(size_t)row*HH + tx*4] =
            make_float4(yv[0]*rstd*gv[0] + ev[0], yv[1]*rstd*gv[1] + ev[1],
                        yv[2]*rstd*gv[2] + ev[2], yv[3]*rstd*gv[3] + ev[3]);
        *(float4*)&y[(size_t)row*HH + 64 + tx*4] =
            make_float4(yv[4]*rstd*gv[4] + ev[4], yv[5]*rstd*gv[5] + ev[5],
                        yv[6]*rstd*gv[6] + ev[6], yv[7]*rstd*gv[7] + ev[7]);
    }
}

// ============================================================
extern "C" void kernel_launch(void* const* d_in, const int* in_sizes, int n_in,
                              void* d_out, int out_size)
{
    const float* x     = (const float*)d_in[0];
    const float* Wq    = (const float*)d_in[1];
    const float* bq    = (const float*)d_in[2];
    const float* Wk    = (const float*)d_in[3];
    const float* bk    = (const float*)d_in[4];
    const float* Wv    = (const float*)d_in[5];
    const float* bv    = (const float*)d_in[6];
    const float* rel_k = (const float*)d_in[7];
    const float* rel_v = (const float*)d_in[8];
    const float* Wo    = (const float*)d_in[9];
    const float* bo    = (const float*)d_in[10];
    const float* gamma = (const float*)d_in[11];
    const float* beta  = (const float*)d_in[12];

    float* y    = (float*)d_out;
    float* attn = (float*)d_out + (size_t)BB * SS * HH;

    cudaFuncSetAttribute(scores_mma, cudaFuncAttributeMaxDynamicSharedMemorySize, SCORES_SMEM);
    cudaFuncSetAttribute(qrel_mma,   cudaFuncAttributeMaxDynamicSharedMemorySize, QREL_SMEM);
    cudaFuncSetAttribute(ctx_mma,    cudaFuncAttributeMaxDynamicSharedMemorySize, CTX_SMEM);

    qkv_gemm<<<dim3(64, 3), 256>>>(x, Wq, bq, Wk, bk, Wv, bv);
    vsplitT<<<dim3(16, 2, 8), 256>>>();
    relvt_prep<<<128, 256>>>(rel_v);
    rksplit_prep<<<144, 128>>>(rel_k);
    qrel_mma<<<64, 256, QREL_SMEM>>>();
    scores_mma<<<dim3(8, 8, 8), 256, SCORES_SMEM>>>(attn);
    softmax_arel<<<NROWS, 256>>>(attn);
    ctx_mma<<<dim3(16, 8, 2), 256, CTX_SMEM>>>();
    outln_gemm<<<128, 256>>>(x, Wo, bo, gamma, beta, y);
}

// round 9
// speedup vs baseline: 2.2759x; 1.1576x over previous
#include <cuda_runtime.h>
#include <cuda_bf16.h>
#include <math.h>
#include <stdint.h>

#define BB 8
#define SS 1024
#define HH 128
#define PP 129
#define QSTR 132
#define AW 256            // padded arel width
#define NROWS (BB*SS)
#define KC 16
#define SLA 260
#define SLA64 132
#define SLB 132
#define SMS 136           // scores/qrel smem tile stride (bf16 elems)
#define SMC 72            // ctx smem tile stride
#define SCORES_SMEM ((2*128 + 2*64)*SMS*2)        // 104448 B -> 2 blocks/SM
#define QREL_SMEM ((2*128 + 2*144)*SMS*2)         // 147968 B
#define CTX_SMEM ((2*64*SMC + 2*128*SMC)*2)       // 55296 B

typedef unsigned long long ull;

// -------- device scratch --------
__device__ float g_q[NROWS*HH];
__device__ float g_v[NROWS*HH];
__device__ float g_qrel[NROWS*QSTR];
__device__ float g_ctxA[NROWS*HH];
__device__ float g_ctxB[NROWS*HH];
__device__ float g_arel[NROWS*AW];
__device__ unsigned short g_qh[NROWS*HH], g_ql[NROWS*HH];
__device__ unsigned short g_kh[NROWS*HH], g_kl[NROWS*HH];
__device__ unsigned short g_vth[BB*HH*SS], g_vtl[BB*HH*SS];
__device__ unsigned short g_rvh[HH*AW], g_rvl[HH*AW];
__device__ unsigned short g_rkh[144*HH], g_rkl[144*HH];

// ---------------- f32x2 helpers ----------------
__device__ __forceinline__ ull bcast2(float x) {
    unsigned int u = __float_as_uint(x);
    ull r; asm("mov.b64 %0, {%1, %2};" : "=l"(r) : "r"(u), "r"(u));
    return r;
}
__device__ __forceinline__ void ffma2(ull& c, ull a, ull b) {
    asm("fma.rn.f32x2 %0, %1, %2, %0;" : "+l"(c) : "l"(a), "l"(b));
}
__device__ __forceinline__ float2 up2(ull v) {
    unsigned int lo, hi;
    asm("mov.b64 {%0, %1}, %2;" : "=r"(lo), "=r"(hi) : "l"(v));
    return make_float2(__uint_as_float(lo), __uint_as_float(hi));
}
__device__ __forceinline__ void fsplit(float f, unsigned short& h, unsigned short& l) {
    __nv_bfloat16 bh = __float2bfloat16(f);
    h = __bfloat16_as_ushort(bh);
    l = __bfloat16_as_ushort(__float2bfloat16(f - __bfloat162float(bh)));
}
// 8 fp32 -> packed hi uint4 + lo uint4 (bf16x2 lanes)
__device__ __forceinline__ void cvt8(float4 f0, float4 f1, uint4& h, uint4& l) {
    unsigned short hh[8], ll[8];
    float v[8] = {f0.x, f0.y, f0.z, f0.w, f1.x, f1.y, f1.z, f1.w};
    #pragma unroll
    for (int t = 0; t < 8; t++) fsplit(v[t], hh[t], ll[t]);
    h = make_uint4((uint32_t)hh[0] | ((uint32_t)hh[1] << 16),
                   (uint32_t)hh[2] | ((uint32_t)hh[3] << 16),
                   (uint32_t)hh[4] | ((uint32_t)hh[5] << 16),
                   (uint32_t)hh[6] | ((uint32_t)hh[7] << 16));
    l = make_uint4((uint32_t)ll[0] | ((uint32_t)ll[1] << 16),
                   (uint32_t)ll[2] | ((uint32_t)ll[3] << 16),
                   (uint32_t)ll[4] | ((uint32_t)ll[5] << 16),
                   (uint32_t)ll[6] | ((uint32_t)ll[7] << 16));
}

// ---------------- mma.sync helpers ----------------
__device__ __forceinline__ uint32_t smem_u32(const void* p) {
    uint32_t a;
    asm("{ .reg .u64 t; cvta.to.shared.u64 t, %1; cvt.u32.u64 %0, t; }" : "=r"(a) : "l"(p));
    return a;
}
__device__ __forceinline__ void ldmx4(uint32_t* r, uint32_t addr) {
    asm volatile("ldmatrix.sync.aligned.m8n8.x4.shared.b16 {%0,%1,%2,%3}, [%4];"
        : "=r"(r[0]), "=r"(r[1]), "=r"(r[2]), "=r"(r[3]) : "r"(addr));
}
__device__ __forceinline__ void mma16816(float* c, const uint32_t* a, const uint32_t* b) {
    asm volatile("mma.sync.aligned.m16n8k16.row.col.f32.bf16.bf16.f32 "
        "{%0,%1,%2,%3}, {%4,%5,%6,%7}, {%8,%9}, {%0,%1,%2,%3};"
        : "+f"(c[0]), "+f"(c[1]), "+f"(c[2]), "+f"(c[3])
        : "r"(a[0]), "r"(a[1]), "r"(a[2]), "r"(a[3]), "r"(b[0]), "r"(b[1]));
}

// fp32 micro kernels (scalar GEMM path)
__device__ __forceinline__ void micro8(const float* __restrict__ akd,
                                       const float* __restrict__ bk,
                                       int tx, int ty, ull (&c2)[8][4]) {
    ulonglong2 a01 = *(const ulonglong2*)(akd + 8*ty);
    ulonglong2 a23 = *(const ulonglong2*)(akd + 8*ty + 4);
    ulonglong2 a45 = *(const ulonglong2*)(akd + 128 + 8*ty);
    ulonglong2 a67 = *(const ulonglong2*)(akd + 128 + 8*ty + 4);
    ulonglong2 b0 = *(const ulonglong2*)(bk + tx*4);
    ulonglong2 b1 = *(const ulonglong2*)(bk + 64 + tx*4);
    ull aa[8] = {a01.x, a01.y, a23.x, a23.y, a45.x, a45.y, a67.x, a67.y};
    ull bb[4] = {b0.x, b0.y, b1.x, b1.y};
    #pragma unroll
    for (int i = 0; i < 8; i++)
        #pragma unroll
        for (int j = 0; j < 4; j++) ffma2(c2[i][j], aa[i], bb[j]);
}
__device__ __forceinline__ void micro4(const float* __restrict__ akd,
                                       const float* __restrict__ bk,
                                       int tx, int ty, ull (&c2)[4][4]) {
    ulonglong2 a01 = *(const ulonglong2*)(akd + 8*ty);
    ulonglong2 a23 = *(const ulonglong2*)(akd + 8*ty + 4);
    ulonglong2 b0 = *(const ulonglong2*)(bk + tx*4);
    ulonglong2 b1 = *(const ulonglong2*)(bk + 64 + tx*4);
    ull aa[4] = {a01.x, a01.y, a23.x, a23.y};
    ull bb[4] = {b0.x, b0.y, b1.x, b1.y};
    #pragma unroll
    for (int i = 0; i < 4; i++)
        #pragma unroll
        for (int j = 0; j < 4; j++) ffma2(c2[i][j], aa[i], bb[j]);
}

// ============================================================
// K1: q/k/v = x@W + b. tile 128x128, grid (64,3), 256 thr.
// ============================================================
__global__ __launch_bounds__(256) void qkv_gemm(
    const float* __restrict__ x,
    const float* __restrict__ Wq, const float* __restrict__ bq,
    const float* __restrict__ Wk, const float* __restrict__ bk,
    const float* __restrict__ Wv, const float* __restrict__ bv)
{
    __shared__ __align__(16) float As[KC*SLA];
    __shared__ __align__(16) float Bs[KC*SLB];
    int z = blockIdx.y;
    const float* W    = (z == 0) ? Wq : (z == 1) ? Wk : Wv;
    const float* bias = (z == 0) ? bq : (z == 1) ? bk : bv;
    int m0 = blockIdx.x * 128;
    int tid = threadIdx.x, tx = tid & 15, ty = tid >> 4;

    int ra[2], kqa[2], krb[2], nqb[2];
    #pragma unroll
    for (int i = 0; i < 2; i++) {
        int idx = tid + i*256;
        ra[i] = idx >> 2; kqa[i] = idx & 3;
        krb[i] = idx >> 5; nqb[i] = idx & 31;
    }

    ull c2[8][4];
    ull z2 = bcast2(0.f);
    #pragma unroll
    for (int i = 0; i < 8; i++) for (int j = 0; j < 4; j++) c2[i][j] = z2;

    float4 pa[2], pb[2];
    #pragma unroll
    for (int i = 0; i < 2; i++) {
        pa[i] = *(const float4*)(x + (size_t)(m0 + ra[i])*HH + kqa[i]*4);
        pb[i] = *(const float4*)(W + (size_t)krb[i]*HH + nqb[i]*4);
    }
    for (int kc = 0; kc < HH; kc += KC) {
        #pragma unroll
        for (int i = 0; i < 2; i++) {
            float* d = &As[(kqa[i]*4)*SLA + 2*ra[i]];
            *(float2*)(d + 0*SLA) = make_float2(pa[i].x, pa[i].x);
            *(float2*)(d + 1*SLA) = make_float2(pa[i].y, pa[i].y);
            *(float2*)(d + 2*SLA) = make_float2(pa[i].z, pa[i].z);
            *(float2*)(d + 3*SLA) = make_float2(pa[i].w, pa[i].w);
            *(float4*)&Bs[krb[i]*SLB + nqb[i]*4] = pb[i];
        }
        __syncthreads();
        if (kc + KC < HH) {
            #pragma unroll
            for (int i = 0; i < 2; i++) {
                pa[i] = *(const float4*)(x + (size_t)(m0 + ra[i])*HH + kc + KC + kqa[i]*4);
                pb[i] = *(const float4*)(W + (size_t)(kc + KC + krb[i])*HH + nqb[i]*4);
            }
        }
        #pragma unroll
        for (int kk = 0; kk < KC; kk++)
            micro8(As + kk*SLA, Bs + kk*SLB, tx, ty, c2);
        __syncthreads();
    }
    float4 bv0 = *(const float4*)&bias[tx*4];
    float4 bv1 = *(const float4*)&bias[64 + tx*4];
    #pragma unroll
    for (int i = 0; i < 8; i++) {
        int row = m0 + ((i < 4) ? ty*4 + i : 64 + ty*4 + i - 4);
        float2 f0 = up2(c2[i][0]), f1 = up2(c2[i][1]);
        float2 f2 = up2(c2[i][2]), f3 = up2(c2[i][3]);
        float v0[4] = {f0.x + bv0.x, f0.y + bv0.y, f1.x + bv0.z, f1.y + bv0.w};
        float v1[4] = {f2.x + bv1.x, f2.y + bv1.y, f3.x + bv1.z, f3.y + bv1.w};
        if (z == 2) {
            *(float4*)&g_v[(size_t)row*HH + tx*4]      = make_float4(v0[0],v0[1],v0[2],v0[3]);
            *(float4*)&g_v[(size_t)row*HH + 64 + tx*4] = make_float4(v1[0],v1[1],v1[2],v1[3]);
        } else {
            if (z == 0) {
                *(float4*)&g_q[(size_t)row*HH + tx*4]      = make_float4(v0[0],v0[1],v0[2],v0[3]);
                *(float4*)&g_q[(size_t)row*HH + 64 + tx*4] = make_float4(v1[0],v1[1],v1[2],v1[3]);
            }
            unsigned short* dh = (z == 0) ? g_qh : g_kh;
            unsigned short* dl = (z == 0) ? g_ql : g_kl;
            unsigned short h0[4], l0[4], h1[4], l1[4];
            #pragma unroll
            for (int t = 0; t < 4; t++) { fsplit(v0[t], h0[t], l0[t]); fsplit(v1[t], h1[t], l1[t]); }
            *(ushort4*)&dh[(size_t)row*HH + tx*4]      = make_ushort4(h0[0],h0[1],h0[2],h0[3]);
            *(ushort4*)&dh[(size_t)row*HH + 64 + tx*4] = make_ushort4(h1[0],h1[1],h1[2],h1[3]);
            *(ushort4*)&dl[(size_t)row*HH + tx*4]      = make_ushort4(l0[0],l0[1],l0[2],l0[3]);
            *(ushort4*)&dl[(size_t)row*HH + 64 + tx*4] = make_ushort4(l1[0],l1[1],l1[2],l1[3]);
        }
    }
}

// ============================================================
// K2: v transpose + split. grid (16,2,8), 256 thr
// ============================================================
__global__ __launch_bounds__(256) void vsplitT()
{
    __shared__ float tile[64][65];
    int b = blockIdx.z, k0 = blockIdx.x*64, n0 = blockIdx.y*64;
    int tx = threadIdx.x & 63, ty = threadIdx.x >> 6;
    #pragma unroll
    for (int i = 0; i < 16; i++)
        tile[ty + i*4][tx] = g_v[(size_t)(b*SS + k0 + ty + i*4)*HH + n0 + tx];
    __syncthreads();
    #pragma unroll
    for (int i = 0; i < 16; i++) {
        int n = n0 + ty + i*4;
        float val = tile[tx][ty + i*4];
        unsigned short h, l; fsplit(val, h, l);
        size_t o = ((size_t)b*HH + n)*SS + k0 + tx;
        g_vth[o] = h; g_vtl[o] = l;
    }
}

// ============================================================
// K3: merged rel prep: rel_v transpose+split AND rel_k split.
// grid (144), 256 thr
// ============================================================
__global__ __launch_bounds__(256) void rel_prep(const float* __restrict__ rel_v,
                                                const float* __restrict__ rel_k)
{
    int n = blockIdx.x, tid = threadIdx.x;
    if (n < HH) {
        // rel_vT[n][k], k padded to 256
        float val = (tid < PP) ? rel_v[(size_t)tid*HH + n] : 0.f;
        unsigned short h, l; fsplit(val, h, l);
        g_rvh[n*AW + tid] = h; g_rvl[n*AW + tid] = l;
    }
    if (tid < HH) {
        // rel_k rows padded to 144
        float val = (n < PP) ? rel_k[(size_t)n*HH + tid] : 0.f;
        unsigned short h, l; fsplit(val, h, l);
        g_rkh[n*HH + tid] = h; g_rkl[n*HH + tid] = l;
    }
}

// ============================================================
// K4: qrel = q @ rel_k^T via mma (N=136 covers p=0..128). grid (64), 256 thr
// ============================================================
__global__ __launch_bounds__(256) void qrel_mma()
{
    extern __shared__ __align__(16) unsigned short smz[];
    unsigned short* QAh = smz;
    unsigned short* QAl = smz + 128*SMS;
    unsigned short* QBh = smz + 2*128*SMS;
    unsigned short* QBl = smz + 2*128*SMS + 144*SMS;
    int tid = threadIdx.x;
    int m0 = blockIdx.x * 128;

    #pragma unroll
    for (int it = 0; it < 8; it++) {
        int idx = tid + it*256;
        int row = idx >> 4, c8 = (idx & 15)*8;
        *(uint4*)&QAh[row*SMS + c8] = *(const uint4*)(g_qh + (size_t)(m0 + row)*HH + c8);
        *(uint4*)&QAl[row*SMS + c8] = *(const uint4*)(g_ql + (size_t)(m0 + row)*HH + c8);
    }
    #pragma unroll
    for (int it = 0; it < 9; it++) {
        int idx = tid + it*256;
        int row = idx >> 4, c8 = (idx & 15)*8;
        *(uint4*)&QBh[row*SMS + c8] = *(const uint4*)(g_rkh + (size_t)row*HH + c8);
        *(uint4*)&QBl[row*SMS + c8] = *(const uint4*)(g_rkl + (size_t)row*HH + c8);
    }
    __syncthreads();

    int warp = tid >> 5, lane = tid & 31;
    int mw = warp * 16;

    uint32_t aBh = smem_u32(&QAh[(mw + (lane & 15))*SMS]) + (lane >> 4)*16;
    uint32_t aBl = smem_u32(&QAl[(mw + (lane & 15))*SMS]) + (lane >> 4)*16;
    int bn_base = ((lane >> 4)*8) + (lane & 7);
    int bk16 = ((lane >> 3) & 1)*8;
    uint32_t bBh = smem_u32(&QBh[bn_base*SMS + bk16]);
    uint32_t bBl = smem_u32(&QBl[bn_base*SMS + bk16]);

    float acc[17][4] = {};
    #pragma unroll
    for (int k = 0; k < 8; k++) {
        uint32_t ah[4], al[4], bh[9][4], bl[9][4];
        uint32_t aoff = (k*16)*2;
        ldmx4(ah, aBh + aoff);
        ldmx4(al, aBl + aoff);
        #pragma unroll
        for (int np = 0; np < 9; np++) {
            uint32_t off = (np*16*SMS + k*16)*2;
            ldmx4(bh[np], bBh + off);
            ldmx4(bl[np], bBl + off);
        }
        #pragma unroll
        for (int nt = 0; nt < 17; nt++) {
            const uint32_t* fh = bh[nt >> 1] + (nt & 1)*2;
            const uint32_t* fl = bl[nt >> 1] + (nt & 1)*2;
            mma16816(acc[nt], ah, fh);
            mma16816(acc[nt], ah, fl);
            mma16816(acc[nt], al, fh);
        }
    }

    #pragma unroll
    for (int half = 0; half < 2; half++) {
        int row = m0 + mw + (lane >> 2) + half*8;
        float* qr = g_qrel + (size_t)row*QSTR;
        #pragma unroll
        for (int nt = 0; nt < 17; nt++) {
            int col = nt*8 + (lane & 3)*2;
            if (nt < 16 || (lane & 3) == 0)
                *(float2*)&qr[col] = make_float2(acc[nt][half*2], acc[nt][half*2 + 1]);
        }
    }
}

// ============================================================
// K5: scores via mma.sync bf16 3-GEMM. tile 128x64, grid (16,8,8), 256 thr
// ============================================================
__global__ __launch_bounds__(256) void scores_mma(float* __restrict__ scores)
{
    extern __shared__ __align__(16) unsigned short smz[];
    unsigned short* SAh = smz;
    unsigned short* SAl = smz + 128*SMS;
    unsigned short* SBh = smz + 2*128*SMS;
    unsigned short* SBl = smz + 2*128*SMS + 64*SMS;
    int tid = threadIdx.x;
    int b = blockIdx.z, m0 = blockIdx.y*128, n0 = blockIdx.x*64;

    const unsigned short* gqh = g_qh + (size_t)(b*SS + m0)*HH;
    const unsigned short* gql = g_ql + (size_t)(b*SS + m0)*HH;
    const unsigned short* gkh = g_kh + (size_t)(b*SS + n0)*HH;
    const unsigned short* gkl = g_kl + (size_t)(b*SS + n0)*HH;
    #pragma unroll
    for (int it = 0; it < 8; it++) {
        int idx = tid + it*256;
        int row = idx >> 4, c8 = (idx & 15)*8;
        *(uint4*)&SAh[row*SMS + c8] = *(const uint4*)(gqh + (size_t)row*HH + c8);
        *(uint4*)&SAl[row*SMS + c8] = *(const uint4*)(gql + (size_t)row*HH + c8);
    }
    #pragma unroll
    for (int it = 0; it < 4; it++) {
        int idx = tid + it*256;
        int row = idx >> 4, c8 = (idx & 15)*8;
        *(uint4*)&SBh[row*SMS + c8] = *(const uint4*)(gkh + (size_t)row*HH + c8);
        *(uint4*)&SBl[row*SMS + c8] = *(const uint4*)(gkl + (size_t)row*HH + c8);
    }
    __syncthreads();

    int warp = tid >> 5, lane = tid & 31;
    int mw = (warp >> 1)*32, nw = (warp & 1)*32;

    uint32_t aBh = smem_u32(&SAh[(mw + (lane & 15))*SMS]) + (lane >> 4)*16;
    uint32_t aBl = smem_u32(&SAl[(mw + (lane & 15))*SMS]) + (lane >> 4)*16;
    int bn = nw + ((lane >> 4)*8) + (lane & 7);
    int bk16 = ((lane >> 3) & 1)*8;
    uint32_t bBh = smem_u32(&SBh[bn*SMS + bk16]);
    uint32_t bBl = smem_u32(&SBl[bn*SMS + bk16]);

    float acc[2][4][4] = {};
    #pragma unroll
    for (int k = 0; k < 8; k++) {
        uint32_t ah[2][4], al[2][4], bh[2][4], bl[2][4];
        #pragma unroll
        for (int mt = 0; mt < 2; mt++) {
            uint32_t off = (mt*16*SMS + k*16)*2;
            ldmx4(ah[mt], aBh + off);
            ldmx4(al[mt], aBl + off);
        }
        #pragma unroll
        for (int np = 0; np < 2; np++) {
            uint32_t off = (np*16*SMS + k*16)*2;
            ldmx4(bh[np], bBh + off);
            ldmx4(bl[np], bBl + off);
        }
        #pragma unroll
        for (int mt = 0; mt < 2; mt++)
            #pragma unroll
            for (int nt = 0; nt < 4; nt++) {
                const uint32_t* fh = bh[nt >> 1] + (nt & 1)*2;
                const uint32_t* fl = bl[nt >> 1] + (nt & 1)*2;
                mma16816(acc[mt][nt], ah[mt], fh);
                mma16816(acc[mt][nt], ah[mt], fl);
                mma16816(acc[mt][nt], al[mt], fh);
            }
    }

    const float invscale = 0.08838834764831845f;
    #pragma unroll
    for (int mt = 0; mt < 2; mt++) {
        #pragma unroll
        for (int half = 0; half < 2; half++) {
            int row = m0 + mw + mt*16 + (lane >> 2) + half*8;
            size_t gr = (size_t)b*SS + row;
            const float* qr = g_qrel + gr*QSTR;
            float* srow = scores + gr*SS;
            #pragma unroll
            for (int nt = 0; nt < 4; nt++) {
                int col = n0 + nw + nt*8 + (lane & 3)*2;
                int d0 = col - row;     d0 = (d0 < -64) ? -64 : (d0 > 64) ? 64 : d0;
                int d1 = col + 1 - row; d1 = (d1 < -64) ? -64 : (d1 > 64) ? 64 : d1;
                float v0 = acc[mt][nt][half*2 + 0]*invscale + qr[d0 + 64];
                float v1 = acc[mt][nt][half*2 + 1]*invscale + qr[d1 + 64];
                *(float2*)&srow[col] = make_float2(v0, v1);
            }
        }
    }
}

// ============================================================
// K6: softmax + arel (fp32). grid 8192, 256 thr
// ============================================================
__global__ __launch_bounds__(256) void softmax_arel(float* __restrict__ scores)
{
    __shared__ __align__(16) float rowbuf[SS];
    __shared__ float smx[8];
    __shared__ float sred[16];
    __shared__ float stot[2];
    int r = blockIdx.x, tid = threadIdx.x;
    int i = r & (SS - 1);
    float* sr = scores + (size_t)r * SS;
    int lane = tid & 31, wid = tid >> 5;

    float4 v = ((const float4*)sr)[tid];

    float m = fmaxf(fmaxf(v.x, v.y), fmaxf(v.z, v.w));
    #pragma unroll
    for (int o = 16; o > 0; o >>= 1) m = fmaxf(m, __shfl_xor_sync(0xffffffffu, m, o));
    if (lane == 0) smx[wid] = m;
    __syncthreads();
    m = fmaxf(fmaxf(fmaxf(smx[0], smx[1]), fmaxf(smx[2], smx[3])),
              fmaxf(fmaxf(smx[4], smx[5]), fmaxf(smx[6], smx[7])));
    __syncthreads();

    v.x = __expf(v.x - m); v.y = __expf(v.y - m);
    v.z = __expf(v.z - m); v.w = __expf(v.w - m);
    float s = v.x + v.y + v.z + v.w;
    #pragma unroll
    for (int o = 16; o > 0; o >>= 1) s += __shfl_xor_sync(0xffffffffu, s, o);
    if (lane == 0) smx[wid] = s;
    __syncthreads();
    s = smx[0] + smx[1] + smx[2] + smx[3] + smx[4] + smx[5] + smx[6] + smx[7];
    float inv = 1.0f / s;
    v.x *= inv; v.y *= inv; v.z *= inv; v.w *= inv;

    ((float4*)sr)[tid] = v;
    ((float4*)rowbuf)[tid] = v;

    int j0 = tid * 4;
    float p[4] = {v.x, v.y, v.z, v.w};
    float slo = 0.f, shi = 0.f;
    #pragma unroll
    for (int t = 0; t < 4; t++) {
        int d = j0 + t - i;
        if (d <= -64) slo += p[t];
        else if (d >= 64) shi += p[t];
    }
    #pragma unroll
    for (int o = 16; o > 0; o >>= 1) {
        slo += __shfl_xor_sync(0xffffffffu, slo, o);
        shi += __shfl_xor_sync(0xffffffffu, shi, o);
    }
    if (lane == 0) { sred[wid] = slo; sred[8 + wid] = shi; }
    __syncthreads();
    if (tid == 0) {
        float a = 0.f, bb2 = 0.f;
        #pragma unroll
        for (int w = 0; w < 8; w++) { a += sred[w]; bb2 += sred[8 + w]; }
        stot[0] = a; stot[1] = bb2;
    }
    __syncthreads();

    {
        float val;
        if (tid == 0)        val = stot[0];
        else if (tid == 128) val = stot[1];
        else if (tid < 128) {
            int j = i + tid - 64;
            val = (j >= 0 && j < SS) ? rowbuf[j] : 0.f;
        } else val = 0.f;
        g_arel[(size_t)r*AW + tid] = val;
    }
}

// ============================================================
// K7: ctx via mma.sync, K=1280, z-split halves of 640, reg-prefetch,
// fp32 attn/arel read with on-the-fly bf16 split.
// grid (16,8,2), 256 thr, tile 64x128
// ============================================================
__device__ __forceinline__ void ctx_loadA(const float* __restrict__ attn,
                                          int b, int m0, int kglob, int row, int c8,
                                          float4& f0, float4& f1) {
    const float* src;
    if (kglob < SS) src = attn + (size_t)(b*SS + m0 + row)*SS + kglob + c8;
    else            src = g_arel + (size_t)(b*SS + m0 + row)*AW + (kglob - SS) + c8;
    f0 = *(const float4*)src;
    f1 = *(const float4*)(src + 4);
}
__device__ __forceinline__ void ctx_loadB(int b, int kglob, int row, int c8,
                                          uint4& h, uint4& l) {
    if (kglob < SS) {
        size_t o = ((size_t)b*HH + row)*SS + kglob + c8;
        h = *(const uint4*)&g_vth[o]; l = *(const uint4*)&g_vtl[o];
    } else {
        size_t o = (size_t)row*AW + (kglob - SS) + c8;
        h = *(const uint4*)&g_rvh[o]; l = *(const uint4*)&g_rvl[o];
    }
}

__global__ __launch_bounds__(256) void ctx_mma(const float* __restrict__ attn)
{
    extern __shared__ __align__(16) unsigned short smz[];
    unsigned short* CAh = smz;
    unsigned short* CAl = smz + 64*SMC;
    unsigned short* CBh = smz + 2*64*SMC;
    unsigned short* CBl = smz + 2*64*SMC + 128*SMC;
    int tid = threadIdx.x;
    int m0 = blockIdx.x*64, b = blockIdx.y, z = blockIdx.z;

    int warp = tid >> 5, lane = tid & 31;
    int mw = (warp >> 2)*32, nw = (warp & 3)*32;

    uint32_t aBh = smem_u32(&CAh[(mw + (lane & 15))*SMC]) + (lane >> 4)*16;
    uint32_t aBl = smem_u32(&CAl[(mw + (lane & 15))*SMC]) + (lane >> 4)*16;
    int bn = nw + ((lane >> 4)*8) + (lane & 7);
    int bk16 = ((lane >> 3) & 1)*8;
    uint32_t bBh = smem_u32(&CBh[bn*SMC + bk16]);
    uint32_t bBl = smem_u32(&CBl[bn*SMC + bk16]);

    int arow[2], ac8[2], brow[4], bc8[4];
    #pragma unroll
    for (int it = 0; it < 2; it++) { int idx = tid + it*256; arow[it] = idx >> 3; ac8[it] = (idx & 7)*8; }
    #pragma unroll
    for (int it = 0; it < 4; it++) { int idx = tid + it*256; brow[it] = idx >> 3; bc8[it] = (idx & 7)*8; }

    float acc[2][4][4] = {};
    float4 raf0[2], raf1[2];
    uint4 rbh[4], rbl[4];

    {
        int kglob = z*640;
        #pragma unroll
        for (int it = 0; it < 2; it++) ctx_loadA(attn, b, m0, kglob, arow[it], ac8[it], raf0[it], raf1[it]);
        #pragma unroll
        for (int it = 0; it < 4; it++) ctx_loadB(b, kglob, brow[it], bc8[it], rbh[it], rbl[it]);
    }

    for (int ci = 0; ci < 10; ci++) {
        #pragma unroll
        for (int it = 0; it < 2; it++) {
            uint4 h, l;
            cvt8(raf0[it], raf1[it], h, l);
            *(uint4*)&CAh[arow[it]*SMC + ac8[it]] = h;
            *(uint4*)&CAl[arow[it]*SMC + ac8[it]] = l;
        }
        #pragma unroll
        for (int it = 0; it < 4; it++) {
            *(uint4*)&CBh[brow[it]*SMC + bc8[it]] = rbh[it];
            *(uint4*)&CBl[brow[it]*SMC + bc8[it]] = rbl[it];
        }
        __syncthreads();
        if (ci < 9) {
            int kglob = z*640 + (ci + 1)*64;
            #pragma unroll
            for (int it = 0; it < 2; it++) ctx_loadA(attn, b, m0, kglob, arow[it], ac8[it], raf0[it], raf1[it]);
            #pragma unroll
            for (int it = 0; it < 4; it++) ctx_loadB(b, kglob, brow[it], bc8[it], rbh[it], rbl[it]);
        }

        #pragma unroll
        for (int k = 0; k < 4; k++) {
            uint32_t ah[2][4], al[2][4], bh[2][4], bl[2][4];
            #pragma unroll
            for (int mt = 0; mt < 2; mt++) {
                uint32_t off = (mt*16*SMC + k*16)*2;
                ldmx4(ah[mt], aBh + off);
                ldmx4(al[mt], aBl + off);
            }
            #pragma unroll
            for (int np = 0; np < 2; np++) {
                uint32_t off = (np*16*SMC + k*16)*2;
                ldmx4(bh[np], bBh + off);
                ldmx4(bl[np], bBl + off);
            }
            #pragma unroll
            for (int mt = 0; mt < 2; mt++)
                #pragma unroll
                for (int nt = 0; nt < 4; nt++) {
                    const uint32_t* fh = bh[nt >> 1] + (nt & 1)*2;
                    const uint32_t* fl = bl[nt >> 1] + (nt & 1)*2;
                    mma16816(acc[mt][nt], ah[mt], fh);
                    mma16816(acc[mt][nt], ah[mt], fl);
                    mma16816(acc[mt][nt], al[mt], fh);
                }
        }
        __syncthreads();
    }

    float* out = z ? g_ctxB : g_ctxA;
    #pragma unroll
    for (int mt = 0; mt < 2; mt++) {
        #pragma unroll
        for (int half = 0; half < 2; half++) {
            int row = m0 + mw + mt*16 + (lane >> 2) + half*8;
            float* orow = out + ((size_t)b*SS + row)*HH;
            #pragma unroll
            for (int nt = 0; nt < 4; nt++) {
                int col = nw + nt*8 + (lane & 3)*2;
                *(float2*)&orow[col] = make_float2(acc[mt][nt][half*2], acc[mt][nt][half*2 + 1]);
            }
        }
    }
}

// ============================================================
// K8: out = (ctxA+ctxB)@Wo + bo; y = LN(out + x). grid (128), 256 thr
// ============================================================
__global__ __launch_bounds__(256) void outln_gemm(
    const float* __restrict__ x, const float* __restrict__ Wo,
    const float* __restrict__ bo, const float* __restrict__ gamma,
    const float* __restrict__ beta, float* __restrict__ y)
{
    __shared__ __align__(16) float As[KC*SLA64];
    __shared__ __align__(16) float Bs[KC*SLB];
    int m0 = blockIdx.x * 64;
    int tid = threadIdx.x, tx = tid & 15, ty = tid >> 4;

    int raA = tid >> 2, kqA = tid & 3;
    int krb[2], nqb[2];
    #pragma unroll
    for (int i = 0; i < 2; i++) { int idx = tid + i*256; krb[i] = idx >> 5; nqb[i] = idx & 31; }

    ull c2[4][4];
    ull z2 = bcast2(0.f);
    #pragma unroll
    for (int i = 0; i < 4; i++) for (int j = 0; j < 4; j++) c2[i][j] = z2;

    size_t aoff = (size_t)(m0 + raA)*HH + kqA*4;
    float4 a4 = *(const float4*)(g_ctxA + aoff);
    float4 b4 = *(const float4*)(g_ctxB + aoff);
    float4 pa = make_float4(a4.x + b4.x, a4.y + b4.y, a4.z + b4.z, a4.w + b4.w);
    float4 pb[2];
    #pragma unroll
    for (int i = 0; i < 2; i++)
        pb[i] = *(const float4*)(Wo + (size_t)krb[i]*HH + nqb[i]*4);

    for (int kc = 0; kc < HH; kc += KC) {
        {
            float* d = &As[(kqA*4)*SLA64 + 2*raA];
            *(float2*)(d + 0*SLA64) = make_float2(pa.x, pa.x);
            *(float2*)(d + 1*SLA64) = make_float2(pa.y, pa.y);
            *(float2*)(d + 2*SLA64) = make_float2(pa.z, pa.z);
            *(float2*)(d + 3*SLA64) = make_float2(pa.w, pa.w);
        }
        #pragma unroll
        for (int i = 0; i < 2; i++)
            *(float4*)&Bs[krb[i]*SLB + nqb[i]*4] = pb[i];
        __syncthreads();
        if (kc + KC < HH) {
            size_t o2 = (size_t)(m0 + raA)*HH + kc + KC + kqA*4;
            a4 = *(const float4*)(g_ctxA + o2);
            b4 = *(const float4*)(g_ctxB + o2);
            pa = make_float4(a4.x + b4.x, a4.y + b4.y, a4.z + b4.z, a4.w + b4.w);
            #pragma unroll
            for (int i = 0; i < 2; i++)
                pb[i] = *(const float4*)(Wo + (size_t)(kc + KC + krb[i])*HH + nqb[i]*4);
        }
        #pragma unroll
        for (int kk = 0; kk < KC; kk++)
            micro4(As + kk*SLA64, Bs + kk*SLB, tx, ty, c2);
        __syncthreads();
    }

    float4 b0 = *(const float4*)&bo[tx*4];
    float4 b1 = *(const float4*)&bo[64 + tx*4];
    float4 g0 = *(const float4*)&gamma[tx*4];
    float4 g1 = *(const float4*)&gamma[64 + tx*4];
    float4 e0 = *(const float4*)&beta[tx*4];
    float4 e1 = *(const float4*)&beta[64 + tx*4];
    float bv[8] = {b0.x,b0.y,b0.z,b0.w,b1.x,b1.y,b1.z,b1.w};
    float gv[8] = {g0.x,g0.y,g0.z,g0.w,g1.x,g1.y,g1.z,g1.w};
    float ev[8] = {e0.x,e0.y,e0.z,e0.w,e1.x,e1.y,e1.z,e1.w};

    #pragma unroll
    for (int i = 0; i < 4; i++) {
        int row = m0 + ty*4 + i;
        float4 x0 = *(const float4*)&x[(size_t)row*HH + tx*4];
        float4 x1 = *(const float4*)&x[(size_t)row*HH + 64 + tx*4];
        float xv[8] = {x0.x,x0.y,x0.z,x0.w,x1.x,x1.y,x1.z,x1.w};
        float yv[8];
        float s = 0.f;
        #pragma unroll
        for (int jp = 0; jp < 4; jp++) {
            float2 f = up2(c2[i][jp]);
            yv[jp*2]   = f.x + bv[jp*2]   + xv[jp*2];
            yv[jp*2+1] = f.y + bv[jp*2+1] + xv[jp*2+1];
            s += yv[jp*2] + yv[jp*2+1];
        }
        #pragma unroll
        for (int o = 1; o < 16; o <<= 1) s += __shfl_xor_sync(0xffffffffu, s, o, 16);
        float mu = s * (1.0f / HH);
        float q = 0.f;
        #pragma unroll
        for (int j = 0; j < 8; j++) { yv[j] -= mu; q += yv[j]*yv[j]; }
        #pragma unroll
        for (int o = 1; o < 16; o <<= 1) q += __shfl_xor_sync(0xffffffffu, q, o, 16);
        float rstd = rsqrtf(q * (1.0f / HH) + 1e-5f);
        *(float4*)&y[(size_t)row*HH + tx*4] =
            make_float4(yv[0]*rstd*gv[0] + ev[0], yv[1]*rstd*gv[1] + ev[1],
                        yv[2]*rstd*gv[2] + ev[2], yv[3]*rstd*gv[3] + ev[3]);
        *(float4*)&y[(size_t)row*HH + 64 + tx*4] =
            make_float4(yv[4]*rstd*gv[4] + ev[4], yv[5]*rstd*gv[5] + ev[5],
                        yv[6]*rstd*gv[6] + ev[6], yv[7]*rstd*gv[7] + ev[7]);
    }
}

// ============================================================
extern "C" void kernel_launch(void* const* d_in, const int* in_sizes, int n_in,
                              void* d_out, int out_size)
{
    const float* x     = (const float*)d_in[0];
    const float* Wq    = (const float*)d_in[1];
    const float* bq    = (const float*)d_in[2];
    const float* Wk    = (const float*)d_in[3];
    const float* bk    = (const float*)d_in[4];
    const float* Wv    = (const float*)d_in[5];
    const float* bv    = (const float*)d_in[6];
    const float* rel_k = (const float*)d_in[7];
    const float* rel_v = (const float*)d_in[8];
    const float* Wo    = (const float*)d_in[9];
    const float* bo    = (const float*)d_in[10];
    const float* gamma = (const float*)d_in[11];
    const float* beta  = (const float*)d_in[12];

    float* y    = (float*)d_out;
    float* attn = (float*)d_out + (size_t)BB * SS * HH;

    cudaFuncSetAttribute(scores_mma, cudaFuncAttributeMaxDynamicSharedMemorySize, SCORES_SMEM);
    cudaFuncSetAttribute(qrel_mma,   cudaFuncAttributeMaxDynamicSharedMemorySize, QREL_SMEM);
    cudaFuncSetAttribute(ctx_mma,    cudaFuncAttributeMaxDynamicSharedMemorySize, CTX_SMEM);

    qkv_gemm<<<dim3(64, 3), 256>>>(x, Wq, bq, Wk, bk, Wv, bv);
    vsplitT<<<dim3(16, 2, 8), 256>>>();
    rel_prep<<<144, 256>>>(rel_v, rel_k);
    qrel_mma<<<64, 256, QREL_SMEM>>>();
    scores_mma<<<dim3(16, 8, 8), 256, SCORES_SMEM>>>(attn);
    softmax_arel<<<NROWS, 256>>>(attn);
    ctx_mma<<<dim3(16, 8, 2), 256, CTX_SMEM>>>(attn);
    outln_gemm<<<128, 256>>>(x, Wo, bo, gamma, beta, y);
}

// round 10
// speedup vs baseline: 2.5331x; 1.1130x over previous
#include <cuda_runtime.h>
#include <cuda_bf16.h>
#include <math.h>
#include <stdint.h>

#define BB 8
#define SS 1024
#define HH 128
#define PP 129
#define QSTR 132
#define AW 256            // padded arel width
#define NROWS (BB*SS)
#define KC 16
#define SLA64 132
#define SLB 132
#define SMS 136           // scores/qrel/qkv smem tile stride (bf16 elems)
#define SMC 72            // ctx smem tile stride
#define SCORES_SMEM ((2*128 + 2*64)*SMS*2)        // 104448 B -> 2 blocks/SM
#define QKV_SMEM (4*128*SMS*2)                    // 139264 B
#define QREL_SMEM ((2*64 + 2*144)*SMS*2)          // 113152 B
#define CTX_SMEM ((2*64*SMC + 2*128*SMC)*2)       // 55296 B

typedef unsigned long long ull;

// -------- device scratch --------
__device__ float g_v[NROWS*HH];
__device__ float g_qrel[NROWS*QSTR];
__device__ float g_ctxA[NROWS*HH];
__device__ float g_ctxB[NROWS*HH];
__device__ float g_arel[NROWS*AW];
__device__ unsigned short g_qh[NROWS*HH], g_ql[NROWS*HH];
__device__ unsigned short g_kh[NROWS*HH], g_kl[NROWS*HH];
__device__ unsigned short g_vth[BB*HH*SS], g_vtl[BB*HH*SS];
__device__ unsigned short g_rvh[HH*AW], g_rvl[HH*AW];
__device__ unsigned short g_rkh[144*HH], g_rkl[144*HH];
__device__ unsigned short g_wth[3*HH*HH], g_wtl[3*HH*HH];   // W^T bf16 splits

// ---------------- f32x2 helpers (outln scalar path) ----------------
__device__ __forceinline__ ull bcast2(float x) {
    unsigned int u = __float_as_uint(x);
    ull r; asm("mov.b64 %0, {%1, %2};" : "=l"(r) : "r"(u), "r"(u));
    return r;
}
__device__ __forceinline__ void ffma2(ull& c, ull a, ull b) {
    asm("fma.rn.f32x2 %0, %1, %2, %0;" : "+l"(c) : "l"(a), "l"(b));
}
__device__ __forceinline__ float2 up2(ull v) {
    unsigned int lo, hi;
    asm("mov.b64 {%0, %1}, %2;" : "=r"(lo), "=r"(hi) : "l"(v));
    return make_float2(__uint_as_float(lo), __uint_as_float(hi));
}
__device__ __forceinline__ void fsplit(float f, unsigned short& h, unsigned short& l) {
    __nv_bfloat16 bh = __float2bfloat16(f);
    h = __bfloat16_as_ushort(bh);
    l = __bfloat16_as_ushort(__float2bfloat16(f - __bfloat162float(bh)));
}
__device__ __forceinline__ void cvt8(float4 f0, float4 f1, uint4& h, uint4& l) {
    unsigned short hh[8], ll[8];
    float v[8] = {f0.x, f0.y, f0.z, f0.w, f1.x, f1.y, f1.z, f1.w};
    #pragma unroll
    for (int t = 0; t < 8; t++) fsplit(v[t], hh[t], ll[t]);
    h = make_uint4((uint32_t)hh[0] | ((uint32_t)hh[1] << 16),
                   (uint32_t)hh[2] | ((uint32_t)hh[3] << 16),
                   (uint32_t)hh[4] | ((uint32_t)hh[5] << 16),
                   (uint32_t)hh[6] | ((uint32_t)hh[7] << 16));
    l = make_uint4((uint32_t)ll[0] | ((uint32_t)ll[1] << 16),
                   (uint32_t)ll[2] | ((uint32_t)ll[3] << 16),
                   (uint32_t)ll[4] | ((uint32_t)ll[5] << 16),
                   (uint32_t)ll[6] | ((uint32_t)ll[7] << 16));
}

// ---------------- mma.sync helpers ----------------
__device__ __forceinline__ uint32_t smem_u32(const void* p) {
    uint32_t a;
    asm("{ .reg .u64 t; cvta.to.shared.u64 t, %1; cvt.u32.u64 %0, t; }" : "=r"(a) : "l"(p));
    return a;
}
__device__ __forceinline__ void ldmx4(uint32_t* r, uint32_t addr) {
    asm volatile("ldmatrix.sync.aligned.m8n8.x4.shared.b16 {%0,%1,%2,%3}, [%4];"
        : "=r"(r[0]), "=r"(r[1]), "=r"(r[2]), "=r"(r[3]) : "r"(addr));
}
__device__ __forceinline__ void mma16816(float* c, const uint32_t* a, const uint32_t* b) {
    asm volatile("mma.sync.aligned.m16n8k16.row.col.f32.bf16.bf16.f32 "
        "{%0,%1,%2,%3}, {%4,%5,%6,%7}, {%8,%9}, {%0,%1,%2,%3};"
        : "+f"(c[0]), "+f"(c[1]), "+f"(c[2]), "+f"(c[3])
        : "r"(a[0]), "r"(a[1]), "r"(a[2]), "r"(a[3]), "r"(b[0]), "r"(b[1]));
}

__device__ __forceinline__ void micro4(const float* __restrict__ akd,
                                       const float* __restrict__ bk,
                                       int tx, int ty, ull (&c2)[4][4]) {
    ulonglong2 a01 = *(const ulonglong2*)(akd + 8*ty);
    ulonglong2 a23 = *(const ulonglong2*)(akd + 8*ty + 4);
    ulonglong2 b0 = *(const ulonglong2*)(bk + tx*4);
    ulonglong2 b1 = *(const ulonglong2*)(bk + 64 + tx*4);
    ull aa[4] = {a01.x, a01.y, a23.x, a23.y};
    ull bb[4] = {b0.x, b0.y, b1.x, b1.y};
    #pragma unroll
    for (int i = 0; i < 4; i++)
        #pragma unroll
        for (int j = 0; j < 4; j++) ffma2(c2[i][j], aa[i], bb[j]);
}

// ============================================================
// K0: W^T bf16 splits for Wq/Wk/Wv. grid (64,3), 256 thr
// ============================================================
__global__ __launch_bounds__(256) void wsplit_prep(
    const float* __restrict__ Wq, const float* __restrict__ Wk,
    const float* __restrict__ Wv)
{
    int z = blockIdx.y;
    const float* W = (z == 0) ? Wq : (z == 1) ? Wk : Wv;
    int idx = blockIdx.x*256 + threadIdx.x;       // 0..16383
    int n = idx >> 7, k = idx & 127;
    float val = W[(size_t)k*HH + n];
    unsigned short h, l; fsplit(val, h, l);
    g_wth[(size_t)z*HH*HH + n*HH + k] = h;
    g_wtl[(size_t)z*HH*HH + n*HH + k] = l;
}

// ============================================================
// K1: q/k/v = x@W + b via mma (split-bf16 3-GEMM). grid (64,3), 256 thr
// z=0 -> qh/ql, z=1 -> kh/kl, z=2 -> g_v fp32
// ============================================================
__global__ __launch_bounds__(256) void qkv_mma(
    const float* __restrict__ x,
    const float* __restrict__ bq, const float* __restrict__ bk2,
    const float* __restrict__ bv2)
{
    extern __shared__ __align__(16) unsigned short smz[];
    unsigned short* SAh = smz;
    unsigned short* SAl = smz + 128*SMS;
    unsigned short* SBh = smz + 2*128*SMS;
    unsigned short* SBl = smz + 3*128*SMS;
    int tid = threadIdx.x;
    int z = blockIdx.y, m0 = blockIdx.x*128;
    const unsigned short* Wth = g_wth + (size_t)z*HH*HH;
    const unsigned short* Wtl = g_wtl + (size_t)z*HH*HH;
    const float* bias = (z == 0) ? bq : (z == 1) ? bk2 : bv2;

    #pragma unroll
    for (int it = 0; it < 8; it++) {
        int unit = tid + it*256;
        int row = unit >> 4, c8 = (unit & 15)*8;
        float4 f0 = *(const float4*)(x + (size_t)(m0 + row)*HH + c8);
        float4 f1 = *(const float4*)(x + (size_t)(m0 + row)*HH + c8 + 4);
        uint4 h, l; cvt8(f0, f1, h, l);
        *(uint4*)&SAh[row*SMS + c8] = h;
        *(uint4*)&SAl[row*SMS + c8] = l;
        *(uint4*)&SBh[row*SMS + c8] = *(const uint4*)(Wth + (size_t)row*HH + c8);
        *(uint4*)&SBl[row*SMS + c8] = *(const uint4*)(Wtl + (size_t)row*HH + c8);
    }
    __syncthreads();

    int warp = tid >> 5, lane = tid & 31;
    int mw = (warp >> 2)*64, nw = (warp & 3)*32;

    uint32_t aBh = smem_u32(&SAh[(mw + (lane & 15))*SMS]) + (lane >> 4)*16;
    uint32_t aBl = smem_u32(&SAl[(mw + (lane & 15))*SMS]) + (lane >> 4)*16;
    int bn = nw + ((lane >> 4)*8) + (lane & 7);
    int bk16 = ((lane >> 3) & 1)*8;
    uint32_t bBh = smem_u32(&SBh[bn*SMS + bk16]);
    uint32_t bBl = smem_u32(&SBl[bn*SMS + bk16]);

    float acc[4][4][4] = {};
    #pragma unroll
    for (int k = 0; k < 8; k++) {
        uint32_t ah[4][4], al[4][4], bh[2][4], bl[2][4];
        #pragma unroll
        for (int mt = 0; mt < 4; mt++) {
            uint32_t off = (mt*16*SMS + k*16)*2;
            ldmx4(ah[mt], aBh + off);
            ldmx4(al[mt], aBl + off);
        }
        #pragma unroll
        for (int np = 0; np < 2; np++) {
            uint32_t off = (np*16*SMS + k*16)*2;
            ldmx4(bh[np], bBh + off);
            ldmx4(bl[np], bBl + off);
        }
        #pragma unroll
        for (int mt = 0; mt < 4; mt++)
            #pragma unroll
            for (int nt = 0; nt < 4; nt++) {
                const uint32_t* fh = bh[nt >> 1] + (nt & 1)*2;
                const uint32_t* fl = bl[nt >> 1] + (nt & 1)*2;
                mma16816(acc[mt][nt], ah[mt], fh);
                mma16816(acc[mt][nt], ah[mt], fl);
                mma16816(acc[mt][nt], al[mt], fh);
            }
    }

    #pragma unroll
    for (int mt = 0; mt < 4; mt++) {
        #pragma unroll
        for (int half = 0; half < 2; half++) {
            int row = m0 + mw + mt*16 + (lane >> 2) + half*8;
            #pragma unroll
            for (int nt = 0; nt < 4; nt++) {
                int col = nw + nt*8 + (lane & 3)*2;
                float v0 = acc[mt][nt][half*2 + 0] + __ldg(&bias[col]);
                float v1 = acc[mt][nt][half*2 + 1] + __ldg(&bias[col + 1]);
                if (z == 2) {
                    *(float2*)&g_v[(size_t)row*HH + col] = make_float2(v0, v1);
                } else {
                    unsigned short* dh = (z == 0) ? g_qh : g_kh;
                    unsigned short* dl = (z == 0) ? g_ql : g_kl;
                    unsigned short h0, l0, h1, l1;
                    fsplit(v0, h0, l0); fsplit(v1, h1, l1);
                    *(ushort2*)&dh[(size_t)row*HH + col] = make_ushort2(h0, h1);
                    *(ushort2*)&dl[(size_t)row*HH + col] = make_ushort2(l0, l1);
                }
            }
        }
    }
}

// ============================================================
// K2: v transpose + split. grid (16,2,8), 256 thr
// ============================================================
__global__ __launch_bounds__(256) void vsplitT()
{
    __shared__ float tile[64][65];
    int b = blockIdx.z, k0 = blockIdx.x*64, n0 = blockIdx.y*64;
    int tx = threadIdx.x & 63, ty = threadIdx.x >> 6;
    #pragma unroll
    for (int i = 0; i < 16; i++)
        tile[ty + i*4][tx] = g_v[(size_t)(b*SS + k0 + ty + i*4)*HH + n0 + tx];
    __syncthreads();
    #pragma unroll
    for (int i = 0; i < 16; i++) {
        int n = n0 + ty + i*4;
        float val = tile[tx][ty + i*4];
        unsigned short h, l; fsplit(val, h, l);
        size_t o = ((size_t)b*HH + n)*SS + k0 + tx;
        g_vth[o] = h; g_vtl[o] = l;
    }
}

// ============================================================
// K3: merged rel prep: rel_v transpose+split AND rel_k split. grid (144), 256 thr
// ============================================================
__global__ __launch_bounds__(256) void rel_prep(const float* __restrict__ rel_v,
                                                const float* __restrict__ rel_k)
{
    int n = blockIdx.x, tid = threadIdx.x;
    if (n < HH) {
        float val = (tid < PP) ? rel_v[(size_t)tid*HH + n] : 0.f;
        unsigned short h, l; fsplit(val, h, l);
        g_rvh[n*AW + tid] = h; g_rvl[n*AW + tid] = l;
    }
    if (tid < HH) {
        float val = (n < PP) ? rel_k[(size_t)n*HH + tid] : 0.f;
        unsigned short h, l; fsplit(val, h, l);
        g_rkh[n*HH + tid] = h; g_rkl[n*HH + tid] = l;
    }
}

// ============================================================
// K4: qrel = q @ rel_k^T via mma. tile 64 rows, grid (128), 256 thr
// warps: wm = warp&3 (16-row m-tile), wn = warp>>2 (n-tiles 0..7 / 8..16)
// ============================================================
__global__ __launch_bounds__(256) void qrel_mma()
{
    extern __shared__ __align__(16) unsigned short smz[];
    unsigned short* QAh = smz;
    unsigned short* QAl = smz + 64*SMS;
    unsigned short* QBh = smz + 2*64*SMS;
    unsigned short* QBl = smz + 2*64*SMS + 144*SMS;
    int tid = threadIdx.x;
    int m0 = blockIdx.x * 64;

    #pragma unroll
    for (int it = 0; it < 4; it++) {
        int idx = tid + it*256;
        int row = idx >> 4, c8 = (idx & 15)*8;
        *(uint4*)&QAh[row*SMS + c8] = *(const uint4*)(g_qh + (size_t)(m0 + row)*HH + c8);
        *(uint4*)&QAl[row*SMS + c8] = *(const uint4*)(g_ql + (size_t)(m0 + row)*HH + c8);
    }
    #pragma unroll
    for (int it = 0; it < 9; it++) {
        int idx = tid + it*256;
        int row = idx >> 4, c8 = (idx & 15)*8;
        *(uint4*)&QBh[row*SMS + c8] = *(const uint4*)(g_rkh + (size_t)row*HH + c8);
        *(uint4*)&QBl[row*SMS + c8] = *(const uint4*)(g_rkl + (size_t)row*HH + c8);
    }
    __syncthreads();

    int warp = tid >> 5, lane = tid & 31;
    int wm = warp & 3, wn = warp >> 2;
    int mw = wm * 16;
    int nbase = wn * 8;                 // base n-tile
    int ntiles = wn ? 9 : 8;
    int npairs = wn ? 5 : 4;

    uint32_t aBh = smem_u32(&QAh[(mw + (lane & 15))*SMS]) + (lane >> 4)*16;
    uint32_t aBl = smem_u32(&QAl[(mw + (lane & 15))*SMS]) + (lane >> 4)*16;
    int bn = nbase*8 + ((lane >> 4)*8) + (lane & 7);
    int bk16 = ((lane >> 3) & 1)*8;
    uint32_t bBh = smem_u32(&QBh[bn*SMS + bk16]);
    uint32_t bBl = smem_u32(&QBl[bn*SMS + bk16]);

    float acc[9][4] = {};
    #pragma unroll
    for (int k = 0; k < 8; k++) {
        uint32_t ah[4], al[4], bh[5][4], bl[5][4];
        uint32_t aoff = (k*16)*2;
        ldmx4(ah, aBh + aoff);
        ldmx4(al, aBl + aoff);
        for (int np = 0; np < npairs; np++) {
            uint32_t off = (np*16*SMS + k*16)*2;
            ldmx4(bh[np], bBh + off);
            ldmx4(bl[np], bBl + off);
        }
        for (int nt = 0; nt < ntiles; nt++) {
            const uint32_t* fh = bh[nt >> 1] + (nt & 1)*2;
            const uint32_t* fl = bl[nt >> 1] + (nt & 1)*2;
            mma16816(acc[nt], ah, fh);
            mma16816(acc[nt], ah, fl);
            mma16816(acc[nt], al, fh);
        }
    }

    #pragma unroll
    for (int half = 0; half < 2; half++) {
        int row = m0 + mw + (lane >> 2) + half*8;
        float* qr = g_qrel + (size_t)row*QSTR;
        for (int nt = 0; nt < ntiles; nt++) {
            int col = (nbase + nt)*8 + (lane & 3)*2;
            if (col <= 128)   // cols 129..131 are row padding
                *(float2*)&qr[col] = make_float2(acc[nt][half*2], acc[nt][half*2 + 1]);
        }
    }
}

// ============================================================
// K5: scores via mma.sync bf16 3-GEMM. tile 128x64, grid (16,8,8), 256 thr
// ============================================================
__global__ __launch_bounds__(256) void scores_mma(float* __restrict__ scores)
{
    extern __shared__ __align__(16) unsigned short smz[];
    unsigned short* SAh = smz;
    unsigned short* SAl = smz + 128*SMS;
    unsigned short* SBh = smz + 2*128*SMS;
    unsigned short* SBl = smz + 2*128*SMS + 64*SMS;
    int tid = threadIdx.x;
    int b = blockIdx.z, m0 = blockIdx.y*128, n0 = blockIdx.x*64;

    const unsigned short* gqh = g_qh + (size_t)(b*SS + m0)*HH;
    const unsigned short* gql = g_ql + (size_t)(b*SS + m0)*HH;
    const unsigned short* gkh = g_kh + (size_t)(b*SS + n0)*HH;
    const unsigned short* gkl = g_kl + (size_t)(b*SS + n0)*HH;
    #pragma unroll
    for (int it = 0; it < 8; it++) {
        int idx = tid + it*256;
        int row = idx >> 4, c8 = (idx & 15)*8;
        *(uint4*)&SAh[row*SMS + c8] = *(const uint4*)(gqh + (size_t)row*HH + c8);
        *(uint4*)&SAl[row*SMS + c8] = *(const uint4*)(gql + (size_t)row*HH + c8);
    }
    #pragma unroll
    for (int it = 0; it < 4; it++) {
        int idx = tid + it*256;
        int row = idx >> 4, c8 = (idx & 15)*8;
        *(uint4*)&SBh[row*SMS + c8] = *(const uint4*)(gkh + (size_t)row*HH + c8);
        *(uint4*)&SBl[row*SMS + c8] = *(const uint4*)(gkl + (size_t)row*HH + c8);
    }
    __syncthreads();

    int warp = tid >> 5, lane = tid & 31;
    int mw = (warp >> 1)*32, nw = (warp & 1)*32;

    uint32_t aBh = smem_u32(&SAh[(mw + (lane & 15))*SMS]) + (lane >> 4)*16;
    uint32_t aBl = smem_u32(&SAl[(mw + (lane & 15))*SMS]) + (lane >> 4)*16;
    int bn = nw + ((lane >> 4)*8) + (lane & 7);
    int bk16 = ((lane >> 3) & 1)*8;
    uint32_t bBh = smem_u32(&SBh[bn*SMS + bk16]);
    uint32_t bBl = smem_u32(&SBl[bn*SMS + bk16]);

    float acc[2][4][4] = {};
    #pragma unroll
    for (int k = 0; k < 8; k++) {
        uint32_t ah[2][4], al[2][4], bh[2][4], bl[2][4];
        #pragma unroll
        for (int mt = 0; mt < 2; mt++) {
            uint32_t off = (mt*16*SMS + k*16)*2;
            ldmx4(ah[mt], aBh + off);
            ldmx4(al[mt], aBl + off);
        }
        #pragma unroll
        for (int np = 0; np < 2; np++) {
            uint32_t off = (np*16*SMS + k*16)*2;
            ldmx4(bh[np], bBh + off);
            ldmx4(bl[np], bBl + off);
        }
        #pragma unroll
        for (int mt = 0; mt < 2; mt++)
            #pragma unroll
            for (int nt = 0; nt < 4; nt++) {
                const uint32_t* fh = bh[nt >> 1] + (nt & 1)*2;
                const uint32_t* fl = bl[nt >> 1] + (nt & 1)*2;
                mma16816(acc[mt][nt], ah[mt], fh);
                mma16816(acc[mt][nt], ah[mt], fl);
                mma16816(acc[mt][nt], al[mt], fh);
            }
    }

    const float invscale = 0.08838834764831845f;
    #pragma unroll
    for (int mt = 0; mt < 2; mt++) {
        #pragma unroll
        for (int half = 0; half < 2; half++) {
            int row = m0 + mw + mt*16 + (lane >> 2) + half*8;
            size_t gr = (size_t)b*SS + row;
            const float* qr = g_qrel + gr*QSTR;
            float* srow = scores + gr*SS;
            #pragma unroll
            for (int nt = 0; nt < 4; nt++) {
                int col = n0 + nw + nt*8 + (lane & 3)*2;
                int d0 = col - row;     d0 = (d0 < -64) ? -64 : (d0 > 64) ? 64 : d0;
                int d1 = col + 1 - row; d1 = (d1 < -64) ? -64 : (d1 > 64) ? 64 : d1;
                float v0 = acc[mt][nt][half*2 + 0]*invscale + qr[d0 + 64];
                float v1 = acc[mt][nt][half*2 + 1]*invscale + qr[d1 + 64];
                *(float2*)&srow[col] = make_float2(v0, v1);
            }
        }
    }
}

// ============================================================
// K6: softmax + arel (fp32). grid 8192, 256 thr
// ============================================================
__global__ __launch_bounds__(256) void softmax_arel(float* __restrict__ scores)
{
    __shared__ __align__(16) float rowbuf[SS];
    __shared__ float smx[8];
    __shared__ float sred[16];
    __shared__ float stot[2];
    int r = blockIdx.x, tid = threadIdx.x;
    int i = r & (SS - 1);
    float* sr = scores + (size_t)r * SS;
    int lane = tid & 31, wid = tid >> 5;

    float4 v = ((const float4*)sr)[tid];

    float m = fmaxf(fmaxf(v.x, v.y), fmaxf(v.z, v.w));
    #pragma unroll
    for (int o = 16; o > 0; o >>= 1) m = fmaxf(m, __shfl_xor_sync(0xffffffffu, m, o));
    if (lane == 0) smx[wid] = m;
    __syncthreads();
    m = fmaxf(fmaxf(fmaxf(smx[0], smx[1]), fmaxf(smx[2], smx[3])),
              fmaxf(fmaxf(smx[4], smx[5]), fmaxf(smx[6], smx[7])));
    __syncthreads();

    v.x = __expf(v.x - m); v.y = __expf(v.y - m);
    v.z = __expf(v.z - m); v.w = __expf(v.w - m);
    float s = v.x + v.y + v.z + v.w;
    #pragma unroll
    for (int o = 16; o > 0; o >>= 1) s += __shfl_xor_sync(0xffffffffu, s, o);
    if (lane == 0) smx[wid] = s;
    __syncthreads();
    s = smx[0] + smx[1] + smx[2] + smx[3] + smx[4] + smx[5] + smx[6] + smx[7];
    float inv = 1.0f / s;
    v.x *= inv; v.y *= inv; v.z *= inv; v.w *= inv;

    ((float4*)sr)[tid] = v;
    ((float4*)rowbuf)[tid] = v;

    int j0 = tid * 4;
    float p[4] = {v.x, v.y, v.z, v.w};
    float slo = 0.f, shi = 0.f;
    #pragma unroll
    for (int t = 0; t < 4; t++) {
        int d = j0 + t - i;
        if (d <= -64) slo += p[t];
        else if (d >= 64) shi += p[t];
    }
    #pragma unroll
    for (int o = 16; o > 0; o >>= 1) {
        slo += __shfl_xor_sync(0xffffffffu, slo, o);
        shi += __shfl_xor_sync(0xffffffffu, shi, o);
    }
    if (lane == 0) { sred[wid] = slo; sred[8 + wid] = shi; }
    __syncthreads();
    if (tid == 0) {
        float a = 0.f, bb2 = 0.f;
        #pragma unroll
        for (int w = 0; w < 8; w++) { a += sred[w]; bb2 += sred[8 + w]; }
        stot[0] = a; stot[1] = bb2;
    }
    __syncthreads();

    {
        float val;
        if (tid == 0)        val = stot[0];
        else if (tid == 128) val = stot[1];
        else if (tid < 128) {
            int j = i + tid - 64;
            val = (j >= 0 && j < SS) ? rowbuf[j] : 0.f;
        } else val = 0.f;
        g_arel[(size_t)r*AW + tid] = val;
    }
}

// ============================================================
// K7: ctx via mma.sync, K=1280, z-split halves of 640, reg-prefetch,
// fp32 attn/arel read with on-the-fly bf16 split. grid (16,8,2), 256 thr
// ============================================================
__device__ __forceinline__ void ctx_loadA(const float* __restrict__ attn,
                                          int b, int m0, int kglob, int row, int c8,
                                          float4& f0, float4& f1) {
    const float* src;
    if (kglob < SS) src = attn + (size_t)(b*SS + m0 + row)*SS + kglob + c8;
    else            src = g_arel + (size_t)(b*SS + m0 + row)*AW + (kglob - SS) + c8;
    f0 = *(const float4*)src;
    f1 = *(const float4*)(src + 4);
}
__device__ __forceinline__ void ctx_loadB(int b, int kglob, int row, int c8,
                                          uint4& h, uint4& l) {
    if (kglob < SS) {
        size_t o = ((size_t)b*HH + row)*SS + kglob + c8;
        h = *(const uint4*)&g_vth[o]; l = *(const uint4*)&g_vtl[o];
    } else {
        size_t o = (size_t)row*AW + (kglob - SS) + c8;
        h = *(const uint4*)&g_rvh[o]; l = *(const uint4*)&g_rvl[o];
    }
}

__global__ __launch_bounds__(256) void ctx_mma(const float* __restrict__ attn)
{
    extern __shared__ __align__(16) unsigned short smz[];
    unsigned short* CAh = smz;
    unsigned short* CAl = smz + 64*SMC;
    unsigned short* CBh = smz + 2*64*SMC;
    unsigned short* CBl = smz + 2*64*SMC + 128*SMC;
    int tid = threadIdx.x;
    int m0 = blockIdx.x*64, b = blockIdx.y, z = blockIdx.z;

    int warp = tid >> 5, lane = tid & 31;
    int mw = (warp >> 2)*32, nw = (warp & 3)*32;

    uint32_t aBh = smem_u32(&CAh[(mw + (lane & 15))*SMC]) + (lane >> 4)*16;
    uint32_t aBl = smem_u32(&CAl[(mw + (lane & 15))*SMC]) + (lane >> 4)*16;
    int bn = nw + ((lane >> 4)*8) + (lane & 7);
    int bk16 = ((lane >> 3) & 1)*8;
    uint32_t bBh = smem_u32(&CBh[bn*SMC + bk16]);
    uint32_t bBl = smem_u32(&CBl[bn*SMC + bk16]);

    int arow[2], ac8[2], brow[4], bc8[4];
    #pragma unroll
    for (int it = 0; it < 2; it++) { int idx = tid + it*256; arow[it] = idx >> 3; ac8[it] = (idx & 7)*8; }
    #pragma unroll
    for (int it = 0; it < 4; it++) { int idx = tid + it*256; brow[it] = idx >> 3; bc8[it] = (idx & 7)*8; }

    float acc[2][4][4] = {};
    float4 raf0[2], raf1[2];
    uint4 rbh[4], rbl[4];

    {
        int kglob = z*640;
        #pragma unroll
        for (int it = 0; it < 2; it++) ctx_loadA(attn, b, m0, kglob, arow[it], ac8[it], raf0[it], raf1[it]);
        #pragma unroll
        for (int it = 0; it < 4; it++) ctx_loadB(b, kglob, brow[it], bc8[it], rbh[it], rbl[it]);
    }

    for (int ci = 0; ci < 10; ci++) {
        #pragma unroll
        for (int it = 0; it < 2; it++) {
            uint4 h, l;
            cvt8(raf0[it], raf1[it], h, l);
            *(uint4*)&CAh[arow[it]*SMC + ac8[it]] = h;
            *(uint4*)&CAl[arow[it]*SMC + ac8[it]] = l;
        }
        #pragma unroll
        for (int it = 0; it < 4; it++) {
            *(uint4*)&CBh[brow[it]*SMC + bc8[it]] = rbh[it];
            *(uint4*)&CBl[brow[it]*SMC + bc8[it]] = rbl[it];
        }
        __syncthreads();
        if (ci < 9) {
            int kglob = z*640 + (ci + 1)*64;
            #pragma unroll
            for (int it = 0; it < 2; it++) ctx_loadA(attn, b, m0, kglob, arow[it], ac8[it], raf0[it], raf1[it]);
            #pragma unroll
            for (int it = 0; it < 4; it++) ctx_loadB(b, kglob, brow[it], bc8[it], rbh[it], rbl[it]);
        }

        #pragma unroll
        for (int k = 0; k < 4; k++) {
            uint32_t ah[2][4], al[2][4], bh[2][4], bl[2][4];
            #pragma unroll
            for (int mt = 0; mt < 2; mt++) {
                uint32_t off = (mt*16*SMC + k*16)*2;
                ldmx4(ah[mt], aBh + off);
                ldmx4(al[mt], aBl + off);
            }
            #pragma unroll
            for (int np = 0; np < 2; np++) {
                uint32_t off = (np*16*SMC + k*16)*2;
                ldmx4(bh[np], bBh + off);
                ldmx4(bl[np], bBl + off);
            }
            #pragma unroll
            for (int mt = 0; mt < 2; mt++)
                #pragma unroll
                for (int nt = 0; nt < 4; nt++) {
                    const uint32_t* fh = bh[nt >> 1] + (nt & 1)*2;
                    const uint32_t* fl = bl[nt >> 1] + (nt & 1)*2;
                    mma16816(acc[mt][nt], ah[mt], fh);
                    mma16816(acc[mt][nt], ah[mt], fl);
                    mma16816(acc[mt][nt], al[mt], fh);
                }
        }
        __syncthreads();
    }

    float* out = z ? g_ctxB : g_ctxA;
    #pragma unroll
    for (int mt = 0; mt < 2; mt++) {
        #pragma unroll
        for (int half = 0; half < 2; half++) {
            int row = m0 + mw + mt*16 + (lane >> 2) + half*8;
            float* orow = out + ((size_t)b*SS + row)*HH;
            #pragma unroll
            for (int nt = 0; nt < 4; nt++) {
                int col = nw + nt*8 + (lane & 3)*2;
                *(float2*)&orow[col] = make_float2(acc[mt][nt][half*2], acc[mt][nt][half*2 + 1]);
            }
        }
    }
}

// ============================================================
// K8: out = (ctxA+ctxB)@Wo + bo; y = LN(out + x). grid (128), 256 thr
// ============================================================
__global__ __launch_bounds__(256) void outln_gemm(
    const float* __restrict__ x, const float* __restrict__ Wo,
    const float* __restrict__ bo, const float* __restrict__ gamma,
    const float* __restrict__ beta, float* __restrict__ y)
{
    __shared__ __align__(16) float As[KC*SLA64];
    __shared__ __align__(16) float Bs[KC*SLB];
    int m0 = blockIdx.x * 64;
    int tid = threadIdx.x, tx = tid & 15, ty = tid >> 4;

    int raA = tid >> 2, kqA = tid & 3;
    int krb[2], nqb[2];
    #pragma unroll
    for (int i = 0; i < 2; i++) { int idx = tid + i*256; krb[i] = idx >> 5; nqb[i] = idx & 31; }

    ull c2[4][4];
    ull z2 = bcast2(0.f);
    #pragma unroll
    for (int i = 0; i < 4; i++) for (int j = 0; j < 4; j++) c2[i][j] = z2;

    size_t aoff = (size_t)(m0 + raA)*HH + kqA*4;
    float4 a4 = *(const float4*)(g_ctxA + aoff);
    float4 b4 = *(const float4*)(g_ctxB + aoff);
    float4 pa = make_float4(a4.x + b4.x, a4.y + b4.y, a4.z + b4.z, a4.w + b4.w);
    float4 pb[2];
    #pragma unroll
    for (int i = 0; i < 2; i++)
        pb[i] = *(const float4*)(Wo + (size_t)krb[i]*HH + nqb[i]*4);

    for (int kc = 0; kc < HH; kc += KC) {
        {
            float* d = &As[(kqA*4)*SLA64 + 2*raA];
            *(float2*)(d + 0*SLA64) = make_float2(pa.x, pa.x);
            *(float2*)(d + 1*SLA64) = make_float2(pa.y, pa.y);
            *(float2*)(d + 2*SLA64) = make_float2(pa.z, pa.z);
            *(float2*)(d + 3*SLA64) = make_float2(pa.w, pa.w);
        }
        #pragma unroll
        for (int i = 0; i < 2; i++)
            *(float4*)&Bs[krb[i]*SLB + nqb[i]*4] = pb[i];
        __syncthreads();
        if (kc + KC < HH) {
            size_t o2 = (size_t)(m0 + raA)*HH + kc + KC + kqA*4;
            a4 = *(const float4*)(g_ctxA + o2);
            b4 = *(const float4*)(g_ctxB + o2);
            pa = make_float4(a4.x + b4.x, a4.y + b4.y, a4.z + b4.z, a4.w + b4.w);
            #pragma unroll
            for (int i = 0; i < 2; i++)
                pb[i] = *(const float4*)(Wo + (size_t)(kc + KC + krb[i])*HH + nqb[i]*4);
        }
        #pragma unroll
        for (int kk = 0; kk < KC; kk++)
            micro4(As + kk*SLA64, Bs + kk*SLB, tx, ty, c2);
        __syncthreads();
    }

    float4 b0 = *(const float4*)&bo[tx*4];
    float4 b1 = *(const float4*)&bo[64 + tx*4];
    float4 g0 = *(const float4*)&gamma[tx*4];
    float4 g1 = *(const float4*)&gamma[64 + tx*4];
    float4 e0 = *(const float4*)&beta[tx*4];
    float4 e1 = *(const float4*)&beta[64 + tx*4];
    float bv[8] = {b0.x,b0.y,b0.z,b0.w,b1.x,b1.y,b1.z,b1.w};
    float gv[8] = {g0.x,g0.y,g0.z,g0.w,g1.x,g1.y,g1.z,g1.w};
    float ev[8] = {e0.x,e0.y,e0.z,e0.w,e1.x,e1.y,e1.z,e1.w};

    #pragma unroll
    for (int i = 0; i < 4; i++) {
        int row = m0 + ty*4 + i;
        float4 x0 = *(const float4*)&x[(size_t)row*HH + tx*4];
        float4 x1 = *(const float4*)&x[(size_t)row*HH + 64 + tx*4];
        float xv[8] = {x0.x,x0.y,x0.z,x0.w,x1.x,x1.y,x1.z,x1.w};
        float yv[8];
        float s = 0.f;
        #pragma unroll
        for (int jp = 0; jp < 4; jp++) {
            float2 f = up2(c2[i][jp]);
            yv[jp*2]   = f.x + bv[jp*2]   + xv[jp*2];
            yv[jp*2+1] = f.y + bv[jp*2+1] + xv[jp*2+1];
            s += yv[jp*2] + yv[jp*2+1];
        }
        #pragma unroll
        for (int o = 1; o < 16; o <<= 1) s += __shfl_xor_sync(0xffffffffu, s, o, 16);
        float mu = s * (1.0f / HH);
        float q = 0.f;
        #pragma unroll
        for (int j = 0; j < 8; j++) { yv[j] -= mu; q += yv[j]*yv[j]; }
        #pragma unroll
        for (int o = 1; o < 16; o <<= 1) q += __shfl_xor_sync(0xffffffffu, q, o, 16);
        float rstd = rsqrtf(q * (1.0f / HH) + 1e-5f);
        *(float4*)&y[(size_t)row*HH + tx*4] =
            make_float4(yv[0]*rstd*gv[0] + ev[0], yv[1]*rstd*gv[1] + ev[1],
                        yv[2]*rstd*gv[2] + ev[2], yv[3]*rstd*gv[3] + ev[3]);
        *(float4*)&y[(size_t)row*HH + 64 + tx*4] =
            make_float4(yv[4]*rstd*gv[4] + ev[4], yv[5]*rstd*gv[5] + ev[5],
                        yv[6]*rstd*gv[6] + ev[6], yv[7]*rstd*gv[7] + ev[7]);
    }
}

// ============================================================
extern "C" void kernel_launch(void* const* d_in, const int* in_sizes, int n_in,
                              void* d_out, int out_size)
{
    const float* x     = (const float*)d_in[0];
    const float* Wq    = (const float*)d_in[1];
    const float* bq    = (const float*)d_in[2];
    const float* Wk    = (const float*)d_in[3];
    const float* bk    = (const float*)d_in[4];
    const float* Wv    = (const float*)d_in[5];
    const float* bv    = (const float*)d_in[6];
    const float* rel_k = (const float*)d_in[7];
    const float* rel_v = (const float*)d_in[8];
    const float* Wo    = (const float*)d_in[9];
    const float* bo    = (const float*)d_in[10];
    const float* gamma = (const float*)d_in[11];
    const float* beta  = (const float*)d_in[12];

    float* y    = (float*)d_out;
    float* attn = (float*)d_out + (size_t)BB * SS * HH;

    cudaFuncSetAttribute(qkv_mma,    cudaFuncAttributeMaxDynamicSharedMemorySize, QKV_SMEM);
    cudaFuncSetAttribute(scores_mma, cudaFuncAttributeMaxDynamicSharedMemorySize, SCORES_SMEM);
    cudaFuncSetAttribute(qrel_mma,   cudaFuncAttributeMaxDynamicSharedMemorySize, QREL_SMEM);
    cudaFuncSetAttribute(ctx_mma,    cudaFuncAttributeMaxDynamicSharedMemorySize, CTX_SMEM);

    wsplit_prep<<<dim3(64, 3), 256>>>(Wq, Wk, Wv);
    qkv_mma<<<dim3(64, 3), 256, QKV_SMEM>>>(x, bq, bk, bv);
    vsplitT<<<dim3(16, 2, 8), 256>>>();
    rel_prep<<<144, 256>>>(rel_v, rel_k);
    qrel_mma<<<128, 256, QREL_SMEM>>>();
    scores_mma<<<dim3(16, 8, 8), 256, SCORES_SMEM>>>(attn);
    softmax_arel<<<NROWS, 256>>>(attn);
    ctx_mma<<<dim3(16, 8, 2), 256, CTX_SMEM>>>(attn);
    outln_gemm<<<128, 256>>>(x, Wo, bo, gamma, beta, y);
}

// round 11
// speedup vs baseline: 2.6170x; 1.0331x over previous
#include <cuda_runtime.h>
#include <cuda_bf16.h>
#include <math.h>
#include <stdint.h>

#define BB 8
#define SS 1024
#define HH 128
#define PP 129
#define QSTR 132
#define AW 256            // padded arel width / rel_v padded k-rows
#define NROWS (BB*SS)
#define KC 16
#define SLA64 132
#define SLB 132
#define SMS 136           // scores/qrel/qkv smem tile stride (bf16 elems)
#define SMC 72            // ctx A smem stride
#define SMB 136           // ctx B smem stride (row-major k x n)
#define SCORES_SMEM ((2*128 + 2*64)*SMS*2)        // 104448 B
#define QKV_SMEM (4*128*SMS*2)                    // 139264 B
#define QREL_SMEM ((2*64 + 2*144)*SMS*2)          // 113152 B
#define CTX_SMEM ((2*64*SMC + 2*64*SMB)*2)        // 53248 B

typedef unsigned long long ull;

// -------- device scratch --------
__device__ float g_qrel[NROWS*QSTR];
__device__ float g_ctxA[NROWS*HH];
__device__ float g_ctxB[NROWS*HH];
__device__ float g_arel[NROWS*AW];
__device__ unsigned short g_qh[NROWS*HH], g_ql[NROWS*HH];
__device__ unsigned short g_kh[NROWS*HH], g_kl[NROWS*HH];
__device__ unsigned short g_vh[NROWS*HH], g_vl[NROWS*HH];   // row-major [k][n]
__device__ unsigned short g_rvh[AW*HH], g_rvl[AW*HH];       // row-major [k][n], rows padded to 256
__device__ unsigned short g_rkh[144*HH], g_rkl[144*HH];
__device__ unsigned short g_wth[3*HH*HH], g_wtl[3*HH*HH];

// ---------------- f32x2 helpers (outln scalar path) ----------------
__device__ __forceinline__ ull bcast2(float x) {
    unsigned int u = __float_as_uint(x);
    ull r; asm("mov.b64 %0, {%1, %2};" : "=l"(r) : "r"(u), "r"(u));
    return r;
}
__device__ __forceinline__ void ffma2(ull& c, ull a, ull b) {
    asm("fma.rn.f32x2 %0, %1, %2, %0;" : "+l"(c) : "l"(a), "l"(b));
}
__device__ __forceinline__ float2 up2(ull v) {
    unsigned int lo, hi;
    asm("mov.b64 {%0, %1}, %2;" : "=r"(lo), "=r"(hi) : "l"(v));
    return make_float2(__uint_as_float(lo), __uint_as_float(hi));
}
__device__ __forceinline__ void fsplit(float f, unsigned short& h, unsigned short& l) {
    __nv_bfloat16 bh = __float2bfloat16(f);
    h = __bfloat16_as_ushort(bh);
    l = __bfloat16_as_ushort(__float2bfloat16(f - __bfloat162float(bh)));
}
__device__ __forceinline__ void cvt8(float4 f0, float4 f1, uint4& h, uint4& l) {
    unsigned short hh[8], ll[8];
    float v[8] = {f0.x, f0.y, f0.z, f0.w, f1.x, f1.y, f1.z, f1.w};
    #pragma unroll
    for (int t = 0; t < 8; t++) fsplit(v[t], hh[t], ll[t]);
    h = make_uint4((uint32_t)hh[0] | ((uint32_t)hh[1] << 16),
                   (uint32_t)hh[2] | ((uint32_t)hh[3] << 16),
                   (uint32_t)hh[4] | ((uint32_t)hh[5] << 16),
                   (uint32_t)hh[6] | ((uint32_t)hh[7] << 16));
    l = make_uint4((uint32_t)ll[0] | ((uint32_t)ll[1] << 16),
                   (uint32_t)ll[2] | ((uint32_t)ll[3] << 16),
                   (uint32_t)ll[4] | ((uint32_t)ll[5] << 16),
                   (uint32_t)ll[6] | ((uint32_t)ll[7] << 16));
}

// ---------------- mma.sync helpers ----------------
__device__ __forceinline__ uint32_t smem_u32(const void* p) {
    uint32_t a;
    asm("{ .reg .u64 t; cvta.to.shared.u64 t, %1; cvt.u32.u64 %0, t; }" : "=r"(a) : "l"(p));
    return a;
}
__device__ __forceinline__ void ldmx4(uint32_t* r, uint32_t addr) {
    asm volatile("ldmatrix.sync.aligned.m8n8.x4.shared.b16 {%0,%1,%2,%3}, [%4];"
        : "=r"(r[0]), "=r"(r[1]), "=r"(r[2]), "=r"(r[3]) : "r"(addr));
}
__device__ __forceinline__ void ldmx4t(uint32_t* r, uint32_t addr) {
    asm volatile("ldmatrix.sync.aligned.m8n8.x4.trans.shared.b16 {%0,%1,%2,%3}, [%4];"
        : "=r"(r[0]), "=r"(r[1]), "=r"(r[2]), "=r"(r[3]) : "r"(addr));
}
__device__ __forceinline__ void mma16816(float* c, const uint32_t* a, const uint32_t* b) {
    asm volatile("mma.sync.aligned.m16n8k16.row.col.f32.bf16.bf16.f32 "
        "{%0,%1,%2,%3}, {%4,%5,%6,%7}, {%8,%9}, {%0,%1,%2,%3};"
        : "+f"(c[0]), "+f"(c[1]), "+f"(c[2]), "+f"(c[3])
        : "r"(a[0]), "r"(a[1]), "r"(a[2]), "r"(a[3]), "r"(b[0]), "r"(b[1]));
}

__device__ __forceinline__ void micro4(const float* __restrict__ akd,
                                       const float* __restrict__ bk,
                                       int tx, int ty, ull (&c2)[4][4]) {
    ulonglong2 a01 = *(const ulonglong2*)(akd + 8*ty);
    ulonglong2 a23 = *(const ulonglong2*)(akd + 8*ty + 4);
    ulonglong2 b0 = *(const ulonglong2*)(bk + tx*4);
    ulonglong2 b1 = *(const ulonglong2*)(bk + 64 + tx*4);
    ull aa[4] = {a01.x, a01.y, a23.x, a23.y};
    ull bb[4] = {b0.x, b0.y, b1.x, b1.y};
    #pragma unroll
    for (int i = 0; i < 4; i++)
        #pragma unroll
        for (int j = 0; j < 4; j++) ffma2(c2[i][j], aa[i], bb[j]);
}

// ============================================================
// K0: merged prep: W^T splits, rel_v split ([k][n], rows pad 256),
// rel_k split (rows pad 144). grid (392), 256 thr
// ============================================================
__global__ __launch_bounds__(256) void prep_all(
    const float* __restrict__ Wq, const float* __restrict__ Wk,
    const float* __restrict__ Wv, const float* __restrict__ rel_v,
    const float* __restrict__ rel_k)
{
    int bx = blockIdx.x, tid = threadIdx.x;
    if (bx < 192) {
        int z = bx >> 6;
        const float* W = (z == 0) ? Wq : (z == 1) ? Wk : Wv;
        int idx = (bx & 63)*256 + tid;
        int n = idx >> 7, k = idx & 127;
        float val = W[(size_t)k*HH + n];
        unsigned short h, l; fsplit(val, h, l);
        g_wth[(size_t)z*HH*HH + n*HH + k] = h;
        g_wtl[(size_t)z*HH*HH + n*HH + k] = l;
    } else if (bx < 320) {
        int idx = (bx - 192)*256 + tid;      // 0..32767
        int k = idx >> 7, n = idx & 127;
        float val = (k < PP) ? rel_v[(size_t)k*HH + n] : 0.f;
        unsigned short h, l; fsplit(val, h, l);
        g_rvh[k*HH + n] = h; g_rvl[k*HH + n] = l;
    } else {
        int idx = (bx - 320)*256 + tid;      // 0..18431
        int n = idx >> 7, k = idx & 127;
        float val = (n < PP) ? rel_k[(size_t)n*HH + k] : 0.f;
        unsigned short h, l; fsplit(val, h, l);
        g_rkh[n*HH + k] = h; g_rkl[n*HH + k] = l;
    }
}

// ============================================================
// K1: q/k/v = x@W + b via mma, all outputs bf16 splits. grid (64,3), 256 thr
// ============================================================
__global__ __launch_bounds__(256) void qkv_mma(
    const float* __restrict__ x,
    const float* __restrict__ bq, const float* __restrict__ bk2,
    const float* __restrict__ bv2)
{
    extern __shared__ __align__(16) unsigned short smz[];
    unsigned short* SAh = smz;
    unsigned short* SAl = smz + 128*SMS;
    unsigned short* SBh = smz + 2*128*SMS;
    unsigned short* SBl = smz + 3*128*SMS;
    int tid = threadIdx.x;
    int z = blockIdx.y, m0 = blockIdx.x*128;
    const unsigned short* Wth = g_wth + (size_t)z*HH*HH;
    const unsigned short* Wtl = g_wtl + (size_t)z*HH*HH;
    const float* bias = (z == 0) ? bq : (z == 1) ? bk2 : bv2;

    #pragma unroll
    for (int it = 0; it < 8; it++) {
        int unit = tid + it*256;
        int row = unit >> 4, c8 = (unit & 15)*8;
        float4 f0 = *(const float4*)(x + (size_t)(m0 + row)*HH + c8);
        float4 f1 = *(const float4*)(x + (size_t)(m0 + row)*HH + c8 + 4);
        uint4 h, l; cvt8(f0, f1, h, l);
        *(uint4*)&SAh[row*SMS + c8] = h;
        *(uint4*)&SAl[row*SMS + c8] = l;
        *(uint4*)&SBh[row*SMS + c8] = *(const uint4*)(Wth + (size_t)row*HH + c8);
        *(uint4*)&SBl[row*SMS + c8] = *(const uint4*)(Wtl + (size_t)row*HH + c8);
    }
    __syncthreads();

    int warp = tid >> 5, lane = tid & 31;
    int mw = (warp >> 2)*64, nw = (warp & 3)*32;

    uint32_t aBh = smem_u32(&SAh[(mw + (lane & 15))*SMS]) + (lane >> 4)*16;
    uint32_t aBl = smem_u32(&SAl[(mw + (lane & 15))*SMS]) + (lane >> 4)*16;
    int bn = nw + ((lane >> 4)*8) + (lane & 7);
    int bk16 = ((lane >> 3) & 1)*8;
    uint32_t bBh = smem_u32(&SBh[bn*SMS + bk16]);
    uint32_t bBl = smem_u32(&SBl[bn*SMS + bk16]);

    float acc[4][4][4] = {};
    #pragma unroll
    for (int k = 0; k < 8; k++) {
        uint32_t ah[4][4], al[4][4], bh[2][4], bl[2][4];
        #pragma unroll
        for (int mt = 0; mt < 4; mt++) {
            uint32_t off = (mt*16*SMS + k*16)*2;
            ldmx4(ah[mt], aBh + off);
            ldmx4(al[mt], aBl + off);
        }
        #pragma unroll
        for (int np = 0; np < 2; np++) {
            uint32_t off = (np*16*SMS + k*16)*2;
            ldmx4(bh[np], bBh + off);
            ldmx4(bl[np], bBl + off);
        }
        #pragma unroll
        for (int mt = 0; mt < 4; mt++)
            #pragma unroll
            for (int nt = 0; nt < 4; nt++) {
                const uint32_t* fh = bh[nt >> 1] + (nt & 1)*2;
                const uint32_t* fl = bl[nt >> 1] + (nt & 1)*2;
                mma16816(acc[mt][nt], ah[mt], fh);
                mma16816(acc[mt][nt], ah[mt], fl);
                mma16816(acc[mt][nt], al[mt], fh);
            }
    }

    unsigned short* dh = (z == 0) ? g_qh : (z == 1) ? g_kh : g_vh;
    unsigned short* dl = (z == 0) ? g_ql : (z == 1) ? g_kl : g_vl;
    #pragma unroll
    for (int mt = 0; mt < 4; mt++) {
        #pragma unroll
        for (int half = 0; half < 2; half++) {
            int row = m0 + mw + mt*16 + (lane >> 2) + half*8;
            #pragma unroll
            for (int nt = 0; nt < 4; nt++) {
                int col = nw + nt*8 + (lane & 3)*2;
                float v0 = acc[mt][nt][half*2 + 0] + __ldg(&bias[col]);
                float v1 = acc[mt][nt][half*2 + 1] + __ldg(&bias[col + 1]);
                unsigned short h0, l0, h1, l1;
                fsplit(v0, h0, l0); fsplit(v1, h1, l1);
                *(ushort2*)&dh[(size_t)row*HH + col] = make_ushort2(h0, h1);
                *(ushort2*)&dl[(size_t)row*HH + col] = make_ushort2(l0, l1);
            }
        }
    }
}

// ============================================================
// K2: qrel = q @ rel_k^T via mma. tile 64 rows, grid (128), 256 thr
// ============================================================
__global__ __launch_bounds__(256) void qrel_mma()
{
    extern __shared__ __align__(16) unsigned short smz[];
    unsigned short* QAh = smz;
    unsigned short* QAl = smz + 64*SMS;
    unsigned short* QBh = smz + 2*64*SMS;
    unsigned short* QBl = smz + 2*64*SMS + 144*SMS;
    int tid = threadIdx.x;
    int m0 = blockIdx.x * 64;

    #pragma unroll
    for (int it = 0; it < 4; it++) {
        int idx = tid + it*256;
        int row = idx >> 4, c8 = (idx & 15)*8;
        *(uint4*)&QAh[row*SMS + c8] = *(const uint4*)(g_qh + (size_t)(m0 + row)*HH + c8);
        *(uint4*)&QAl[row*SMS + c8] = *(const uint4*)(g_ql + (size_t)(m0 + row)*HH + c8);
    }
    #pragma unroll
    for (int it = 0; it < 9; it++) {
        int idx = tid + it*256;
        int row = idx >> 4, c8 = (idx & 15)*8;
        *(uint4*)&QBh[row*SMS + c8] = *(const uint4*)(g_rkh + (size_t)row*HH + c8);
        *(uint4*)&QBl[row*SMS + c8] = *(const uint4*)(g_rkl + (size_t)row*HH + c8);
    }
    __syncthreads();

    int warp = tid >> 5, lane = tid & 31;
    int wm = warp & 3, wn = warp >> 2;
    int mw = wm * 16;
    int nbase = wn * 8;
    int ntiles = wn ? 9 : 8;
    int npairs = wn ? 5 : 4;

    uint32_t aBh = smem_u32(&QAh[(mw + (lane & 15))*SMS]) + (lane >> 4)*16;
    uint32_t aBl = smem_u32(&QAl[(mw + (lane & 15))*SMS]) + (lane >> 4)*16;
    int bn = nbase*8 + ((lane >> 4)*8) + (lane & 7);
    int bk16 = ((lane >> 3) & 1)*8;
    uint32_t bBh = smem_u32(&QBh[bn*SMS + bk16]);
    uint32_t bBl = smem_u32(&QBl[bn*SMS + bk16]);

    float acc[9][4] = {};
    #pragma unroll
    for (int k = 0; k < 8; k++) {
        uint32_t ah[4], al[4], bh[5][4], bl[5][4];
        uint32_t aoff = (k*16)*2;
        ldmx4(ah, aBh + aoff);
        ldmx4(al, aBl + aoff);
        for (int np = 0; np < npairs; np++) {
            uint32_t off = (np*16*SMS + k*16)*2;
            ldmx4(bh[np], bBh + off);
            ldmx4(bl[np], bBl + off);
        }
        for (int nt = 0; nt < ntiles; nt++) {
            const uint32_t* fh = bh[nt >> 1] + (nt & 1)*2;
            const uint32_t* fl = bl[nt >> 1] + (nt & 1)*2;
            mma16816(acc[nt], ah, fh);
            mma16816(acc[nt], ah, fl);
            mma16816(acc[nt], al, fh);
        }
    }

    #pragma unroll
    for (int half = 0; half < 2; half++) {
        int row = m0 + mw + (lane >> 2) + half*8;
        float* qr = g_qrel + (size_t)row*QSTR;
        for (int nt = 0; nt < ntiles; nt++) {
            int col = (nbase + nt)*8 + (lane & 3)*2;
            if (col <= 128)
                *(float2*)&qr[col] = make_float2(acc[nt][half*2], acc[nt][half*2 + 1]);
        }
    }
}

// ============================================================
// K3: scores via mma.sync bf16 3-GEMM. tile 128x64, grid (16,8,8), 256 thr
// ============================================================
__global__ __launch_bounds__(256) void scores_mma(float* __restrict__ scores)
{
    extern __shared__ __align__(16) unsigned short smz[];
    unsigned short* SAh = smz;
    unsigned short* SAl = smz + 128*SMS;
    unsigned short* SBh = smz + 2*128*SMS;
    unsigned short* SBl = smz + 2*128*SMS + 64*SMS;
    int tid = threadIdx.x;
    int b = blockIdx.z, m0 = blockIdx.y*128, n0 = blockIdx.x*64;

    const unsigned short* gqh = g_qh + (size_t)(b*SS + m0)*HH;
    const unsigned short* gql = g_ql + (size_t)(b*SS + m0)*HH;
    const unsigned short* gkh = g_kh + (size_t)(b*SS + n0)*HH;
    const unsigned short* gkl = g_kl + (size_t)(b*SS + n0)*HH;
    #pragma unroll
    for (int it = 0; it < 8; it++) {
        int idx = tid + it*256;
        int row = idx >> 4, c8 = (idx & 15)*8;
        *(uint4*)&SAh[row*SMS + c8] = *(const uint4*)(gqh + (size_t)row*HH + c8);
        *(uint4*)&SAl[row*SMS + c8] = *(const uint4*)(gql + (size_t)row*HH + c8);
    }
    #pragma unroll
    for (int it = 0; it < 4; it++) {
        int idx = tid + it*256;
        int row = idx >> 4, c8 = (idx & 15)*8;
        *(uint4*)&SBh[row*SMS + c8] = *(const uint4*)(gkh + (size_t)row*HH + c8);
        *(uint4*)&SBl[row*SMS + c8] = *(const uint4*)(gkl + (size_t)row*HH + c8);
    }
    __syncthreads();

    int warp = tid >> 5, lane = tid & 31;
    int mw = (warp >> 1)*32, nw = (warp & 1)*32;

    uint32_t aBh = smem_u32(&SAh[(mw + (lane & 15))*SMS]) + (lane >> 4)*16;
    uint32_t aBl = smem_u32(&SAl[(mw + (lane & 15))*SMS]) + (lane >> 4)*16;
    int bn = nw + ((lane >> 4)*8) + (lane & 7);
    int bk16 = ((lane >> 3) & 1)*8;
    uint32_t bBh = smem_u32(&SBh[bn*SMS + bk16]);
    uint32_t bBl = smem_u32(&SBl[bn*SMS + bk16]);

    float acc[2][4][4] = {};
    #pragma unroll
    for (int k = 0; k < 8; k++) {
        uint32_t ah[2][4], al[2][4], bh[2][4], bl[2][4];
        #pragma unroll
        for (int mt = 0; mt < 2; mt++) {
            uint32_t off = (mt*16*SMS + k*16)*2;
            ldmx4(ah[mt], aBh + off);
            ldmx4(al[mt], aBl + off);
        }
        #pragma unroll
        for (int np = 0; np < 2; np++) {
            uint32_t off = (np*16*SMS + k*16)*2;
            ldmx4(bh[np], bBh + off);
            ldmx4(bl[np], bBl + off);
        }
        #pragma unroll
        for (int mt = 0; mt < 2; mt++)
            #pragma unroll
            for (int nt = 0; nt < 4; nt++) {
                const uint32_t* fh = bh[nt >> 1] + (nt & 1)*2;
                const uint32_t* fl = bl[nt >> 1] + (nt & 1)*2;
                mma16816(acc[mt][nt], ah[mt], fh);
                mma16816(acc[mt][nt], ah[mt], fl);
                mma16816(acc[mt][nt], al[mt], fh);
            }
    }

    const float invscale = 0.08838834764831845f;
    #pragma unroll
    for (int mt = 0; mt < 2; mt++) {
        #pragma unroll
        for (int half = 0; half < 2; half++) {
            int row = m0 + mw + mt*16 + (lane >> 2) + half*8;
            size_t gr = (size_t)b*SS + row;
            const float* qr = g_qrel + gr*QSTR;
            float* srow = scores + gr*SS;
            #pragma unroll
            for (int nt = 0; nt < 4; nt++) {
                int col = n0 + nw + nt*8 + (lane & 3)*2;
                int d0 = col - row;     d0 = (d0 < -64) ? -64 : (d0 > 64) ? 64 : d0;
                int d1 = col + 1 - row; d1 = (d1 < -64) ? -64 : (d1 > 64) ? 64 : d1;
                float v0 = acc[mt][nt][half*2 + 0]*invscale + qr[d0 + 64];
                float v1 = acc[mt][nt][half*2 + 1]*invscale + qr[d1 + 64];
                *(float2*)&srow[col] = make_float2(v0, v1);
            }
        }
    }
}

// ============================================================
// K4: softmax + arel (fp32). grid 8192, 256 thr
// ============================================================
__global__ __launch_bounds__(256) void softmax_arel(float* __restrict__ scores)
{
    __shared__ __align__(16) float rowbuf[SS];
    __shared__ float smx[8];
    __shared__ float sred[16];
    __shared__ float stot[2];
    int r = blockIdx.x, tid = threadIdx.x;
    int i = r & (SS - 1);
    float* sr = scores + (size_t)r * SS;
    int lane = tid & 31, wid = tid >> 5;

    float4 v = ((const float4*)sr)[tid];

    float m = fmaxf(fmaxf(v.x, v.y), fmaxf(v.z, v.w));
    #pragma unroll
    for (int o = 16; o > 0; o >>= 1) m = fmaxf(m, __shfl_xor_sync(0xffffffffu, m, o));
    if (lane == 0) smx[wid] = m;
    __syncthreads();
    m = fmaxf(fmaxf(fmaxf(smx[0], smx[1]), fmaxf(smx[2], smx[3])),
              fmaxf(fmaxf(smx[4], smx[5]), fmaxf(smx[6], smx[7])));
    __syncthreads();

    v.x = __expf(v.x - m); v.y = __expf(v.y - m);
    v.z = __expf(v.z - m); v.w = __expf(v.w - m);
    float s = v.x + v.y + v.z + v.w;
    #pragma unroll
    for (int o = 16; o > 0; o >>= 1) s += __shfl_xor_sync(0xffffffffu, s, o);
    if (lane == 0) smx[wid] = s;
    __syncthreads();
    s = smx[0] + smx[1] + smx[2] + smx[3] + smx[4] + smx[5] + smx[6] + smx[7];
    float inv = 1.0f / s;
    v.x *= inv; v.y *= inv; v.z *= inv; v.w *= inv;

    ((float4*)sr)[tid] = v;
    ((float4*)rowbuf)[tid] = v;

    int j0 = tid * 4;
    float p[4] = {v.x, v.y, v.z, v.w};
    float slo = 0.f, shi = 0.f;
    #pragma unroll
    for (int t = 0; t < 4; t++) {
        int d = j0 + t - i;
        if (d <= -64) slo += p[t];
        else if (d >= 64) shi += p[t];
    }
    #pragma unroll
    for (int o = 16; o > 0; o >>= 1) {
        slo += __shfl_xor_sync(0xffffffffu, slo, o);
        shi += __shfl_xor_sync(0xffffffffu, shi, o);
    }
    if (lane == 0) { sred[wid] = slo; sred[8 + wid] = shi; }
    __syncthreads();
    if (tid == 0) {
        float a = 0.f, bb2 = 0.f;
        #pragma unroll
        for (int w = 0; w < 8; w++) { a += sred[w]; bb2 += sred[8 + w]; }
        stot[0] = a; stot[1] = bb2;
    }
    __syncthreads();

    {
        float val;
        if (tid == 0)        val = stot[0];
        else if (tid == 128) val = stot[1];
        else if (tid < 128) {
            int j = i + tid - 64;
            val = (j >= 0 && j < SS) ? rowbuf[j] : 0.f;
        } else val = 0.f;
        g_arel[(size_t)r*AW + tid] = val;
    }
}

// ============================================================
// K5: ctx via mma.sync, K=1280, z-split halves of 640, reg-prefetch.
// B loaded row-major [k][n] + ldmatrix.trans. grid (16,8,2), 256 thr
// ============================================================
__device__ __forceinline__ void ctx_loadA(const float* __restrict__ attn,
                                          int b, int m0, int kglob, int row, int c8,
                                          float4& f0, float4& f1) {
    const float* src;
    if (kglob < SS) src = attn + (size_t)(b*SS + m0 + row)*SS + kglob + c8;
    else            src = g_arel + (size_t)(b*SS + m0 + row)*AW + (kglob - SS) + c8;
    f0 = *(const float4*)src;
    f1 = *(const float4*)(src + 4);
}
__device__ __forceinline__ void ctx_loadB(int b, int kglob, int row, int c8,
                                          uint4& h, uint4& l) {
    if (kglob < SS) {
        size_t o = (size_t)(b*SS + kglob + row)*HH + c8;
        h = *(const uint4*)&g_vh[o]; l = *(const uint4*)&g_vl[o];
    } else {
        size_t o = (size_t)(kglob - SS + row)*HH + c8;
        h = *(const uint4*)&g_rvh[o]; l = *(const uint4*)&g_rvl[o];
    }
}

__global__ __launch_bounds__(256) void ctx_mma(const float* __restrict__ attn)
{
    extern __shared__ __align__(16) unsigned short smz[];
    unsigned short* CAh = smz;
    unsigned short* CAl = smz + 64*SMC;
    unsigned short* CBh = smz + 2*64*SMC;
    unsigned short* CBl = smz + 2*64*SMC + 64*SMB;
    int tid = threadIdx.x;
    int m0 = blockIdx.x*64, b = blockIdx.y, z = blockIdx.z;

    int warp = tid >> 5, lane = tid & 31;
    int mw = (warp >> 2)*32, nw = (warp & 3)*32;

    uint32_t aBh = smem_u32(&CAh[(mw + (lane & 15))*SMC]) + (lane >> 4)*16;
    uint32_t aBl = smem_u32(&CAl[(mw + (lane & 15))*SMC]) + (lane >> 4)*16;
    // trans-B lane addressing: lanes 0-15 rows k+(lane&15) at col base, lanes 16-31 at col base+8
    uint32_t bBh = smem_u32(CBh) + (((lane & 15)*SMB) + nw + ((lane >> 4)*8))*2;
    uint32_t bBl = smem_u32(CBl) + (((lane & 15)*SMB) + nw + ((lane >> 4)*8))*2;

    int arow[2], ac8[2], brow[4], bc8[4];
    #pragma unroll
    for (int it = 0; it < 2; it++) { int idx = tid + it*256; arow[it] = idx >> 3; ac8[it] = (idx & 7)*8; }
    #pragma unroll
    for (int it = 0; it < 4; it++) { int idx = tid + it*256; brow[it] = idx >> 4; bc8[it] = (idx & 15)*8; }

    float acc[2][4][4] = {};
    float4 raf0[2], raf1[2];
    uint4 rbh[4], rbl[4];

    {
        int kglob = z*640;
        #pragma unroll
        for (int it = 0; it < 2; it++) ctx_loadA(attn, b, m0, kglob, arow[it], ac8[it], raf0[it], raf1[it]);
        #pragma unroll
        for (int it = 0; it < 4; it++) ctx_loadB(b, kglob, brow[it], bc8[it], rbh[it], rbl[it]);
    }

    for (int ci = 0; ci < 10; ci++) {
        #pragma unroll
        for (int it = 0; it < 2; it++) {
            uint4 h, l;
            cvt8(raf0[it], raf1[it], h, l);
            *(uint4*)&CAh[arow[it]*SMC + ac8[it]] = h;
            *(uint4*)&CAl[arow[it]*SMC + ac8[it]] = l;
        }
        #pragma unroll
        for (int it = 0; it < 4; it++) {
            *(uint4*)&CBh[brow[it]*SMB + bc8[it]] = rbh[it];
            *(uint4*)&CBl[brow[it]*SMB + bc8[it]] = rbl[it];
        }
        __syncthreads();
        if (ci < 9) {
            int kglob = z*640 + (ci + 1)*64;
            #pragma unroll
            for (int it = 0; it < 2; it++) ctx_loadA(attn, b, m0, kglob, arow[it], ac8[it], raf0[it], raf1[it]);
            #pragma unroll
            for (int it = 0; it < 4; it++) ctx_loadB(b, kglob, brow[it], bc8[it], rbh[it], rbl[it]);
        }

        #pragma unroll
        for (int k = 0; k < 4; k++) {
            uint32_t ah[2][4], al[2][4], bh[2][4], bl[2][4];
            #pragma unroll
            for (int mt = 0; mt < 2; mt++) {
                uint32_t off = (mt*16*SMC + k*16)*2;
                ldmx4(ah[mt], aBh + off);
                ldmx4(al[mt], aBl + off);
            }
            #pragma unroll
            for (int np = 0; np < 2; np++) {
                uint32_t off = (k*16*SMB + np*16)*2;
                ldmx4t(bh[np], bBh + off);
                ldmx4t(bl[np], bBl + off);
            }
            #pragma unroll
            for (int mt = 0; mt < 2; mt++)
                #pragma unroll
                for (int nt = 0; nt < 4; nt++) {
                    const uint32_t* fh = bh[nt >> 1] + (nt & 1)*2;
                    const uint32_t* fl = bl[nt >> 1] + (nt & 1)*2;
                    mma16816(acc[mt][nt], ah[mt], fh);
                    mma16816(acc[mt][nt], ah[mt], fl);
                    mma16816(acc[mt][nt], al[mt], fh);
                }
        }
        __syncthreads();
    }

    float* out = z ? g_ctxB : g_ctxA;
    #pragma unroll
    for (int mt = 0; mt < 2; mt++) {
        #pragma unroll
        for (int half = 0; half < 2; half++) {
            int row = m0 + mw + mt*16 + (lane >> 2) + half*8;
            float* orow = out + ((size_t)b*SS + row)*HH;
            #pragma unroll
            for (int nt = 0; nt < 4; nt++) {
                int col = nw + nt*8 + (lane & 3)*2;
                *(float2*)&orow[col] = make_float2(acc[mt][nt][half*2], acc[mt][nt][half*2 + 1]);
            }
        }
    }
}

// ============================================================
// K6: out = (ctxA+ctxB)@Wo + bo; y = LN(out + x). grid (128), 256 thr
// ============================================================
__global__ __launch_bounds__(256) void outln_gemm(
    const float* __restrict__ x, const float* __restrict__ Wo,
    const float* __restrict__ bo, const float* __restrict__ gamma,
    const float* __restrict__ beta, float* __restrict__ y)
{
    __shared__ __align__(16) float As[KC*SLA64];
    __shared__ __align__(16) float Bs[KC*SLB];
    int m0 = blockIdx.x * 64;
    int tid = threadIdx.x, tx = tid & 15, ty = tid >> 4;

    int raA = tid >> 2, kqA = tid & 3;
    int krb[2], nqb[2];
    #pragma unroll
    for (int i = 0; i < 2; i++) { int idx = tid + i*256; krb[i] = idx >> 5; nqb[i] = idx & 31; }

    ull c2[4][4];
    ull z2 = bcast2(0.f);
    #pragma unroll
    for (int i = 0; i < 4; i++) for (int j = 0; j < 4; j++) c2[i][j] = z2;

    size_t aoff = (size_t)(m0 + raA)*HH + kqA*4;
    float4 a4 = *(const float4*)(g_ctxA + aoff);
    float4 b4 = *(const float4*)(g_ctxB + aoff);
    float4 pa = make_float4(a4.x + b4.x, a4.y + b4.y, a4.z + b4.z, a4.w + b4.w);
    float4 pb[2];
    #pragma unroll
    for (int i = 0; i < 2; i++)
        pb[i] = *(const float4*)(Wo + (size_t)krb[i]*HH + nqb[i]*4);

    for (int kc = 0; kc < HH; kc += KC) {
        {
            float* d = &As[(kqA*4)*SLA64 + 2*raA];
            *(float2*)(d + 0*SLA64) = make_float2(pa.x, pa.x);
            *(float2*)(d + 1*SLA64) = make_float2(pa.y, pa.y);
            *(float2*)(d + 2*SLA64) = make_float2(pa.z, pa.z);
            *(float2*)(d + 3*SLA64) = make_float2(pa.w, pa.w);
        }
        #pragma unroll
        for (int i = 0; i < 2; i++)
            *(float4*)&Bs[krb[i]*SLB + nqb[i]*4] = pb[i];
        __syncthreads();
        if (kc + KC < HH) {
            size_t o2 = (size_t)(m0 + raA)*HH + kc + KC + kqA*4;
            a4 = *(const float4*)(g_ctxA + o2);
            b4 = *(const float4*)(g_ctxB + o2);
            pa = make_float4(a4.x + b4.x, a4.y + b4.y, a4.z + b4.z, a4.w + b4.w);
            #pragma unroll
            for (int i = 0; i < 2; i++)
                pb[i] = *(const float4*)(Wo + (size_t)(kc + KC + krb[i])*HH + nqb[i]*4);
        }
        #pragma unroll
        for (int kk = 0; kk < KC; kk++)
            micro4(As + kk*SLA64, Bs + kk*SLB, tx, ty, c2);
        __syncthreads();
    }

    float4 b0 = *(const float4*)&bo[tx*4];
    float4 b1 = *(const float4*)&bo[64 + tx*4];
    float4 g0 = *(const float4*)&gamma[tx*4];
    float4 g1 = *(const float4*)&gamma[64 + tx*4];
    float4 e0 = *(const float4*)&beta[tx*4];
    float4 e1 = *(const float4*)&beta[64 + tx*4];
    float bv[8] = {b0.x,b0.y,b0.z,b0.w,b1.x,b1.y,b1.z,b1.w};
    float gv[8] = {g0.x,g0.y,g0.z,g0.w,g1.x,g1.y,g1.z,g1.w};
    float ev[8] = {e0.x,e0.y,e0.z,e0.w,e1.x,e1.y,e1.z,e1.w};

    #pragma unroll
    for (int i = 0; i < 4; i++) {
        int row = m0 + ty*4 + i;
        float4 x0 = *(const float4*)&x[(size_t)row*HH + tx*4];
        float4 x1 = *(const float4*)&x[(size_t)row*HH + 64 + tx*4];
        float xv[8] = {x0.x,x0.y,x0.z,x0.w,x1.x,x1.y,x1.z,x1.w};
        float yv[8];
        float s = 0.f;
        #pragma unroll
        for (int jp = 0; jp < 4; jp++) {
            float2 f = up2(c2[i][jp]);
            yv[jp*2]   = f.x + bv[jp*2]   + xv[jp*2];
            yv[jp*2+1] = f.y + bv[jp*2+1] + xv[jp*2+1];
            s += yv[jp*2] + yv[jp*2+1];
        }
        #pragma unroll
        for (int o = 1; o < 16; o <<= 1) s += __shfl_xor_sync(0xffffffffu, s, o, 16);
        float mu = s * (1.0f / HH);
        float q = 0.f;
        #pragma unroll
        for (int j = 0; j < 8; j++) { yv[j] -= mu; q += yv[j]*yv[j]; }
        #pragma unroll
        for (int o = 1; o < 16; o <<= 1) q += __shfl_xor_sync(0xffffffffu, q, o, 16);
        float rstd = rsqrtf(q * (1.0f / HH) + 1e-5f);
        *(float4*)&y[(size_t)row*HH + tx*4] =
            make_float4(yv[0]*rstd*gv[0] + ev[0], yv[1]*rstd*gv[1] + ev[1],
                        yv[2]*rstd*gv[2] + ev[2], yv[3]*rstd*gv[3] + ev[3]);
        *(float4*)&y[(size_t)row*HH + 64 + tx*4] =
            make_float4(yv[4]*rstd*gv[4] + ev[4], yv[5]*rstd*gv[5] + ev[5],
                        yv[6]*rstd*gv[6] + ev[6], yv[7]*rstd*gv[7] + ev[7]);
    }
}

// ============================================================
extern "C" void kernel_launch(void* const* d_in, const int* in_sizes, int n_in,
                              void* d_out, int out_size)
{
    const float* x     = (const float*)d_in[0];
    const float* Wq    = (const float*)d_in[1];
    const float* bq    = (const float*)d_in[2];
    const float* Wk    = (const float*)d_in[3];
    const float* bk    = (const float*)d_in[4];
    const float* Wv    = (const float*)d_in[5];
    const float* bv    = (const float*)d_in[6];
    const float* rel_k = (const float*)d_in[7];
    const float* rel_v = (const float*)d_in[8];
    const float* Wo    = (const float*)d_in[9];
    const float* bo    = (const float*)d_in[10];
    const float* gamma = (const float*)d_in[11];
    const float* beta  = (const float*)d_in[12];

    float* y    = (float*)d_out;
    float* attn = (float*)d_out + (size_t)BB * SS * HH;

    cudaFuncSetAttribute(qkv_mma,    cudaFuncAttributeMaxDynamicSharedMemorySize, QKV_SMEM);
    cudaFuncSetAttribute(scores_mma, cudaFuncAttributeMaxDynamicSharedMemorySize, SCORES_SMEM);
    cudaFuncSetAttribute(qrel_mma,   cudaFuncAttributeMaxDynamicSharedMemorySize, QREL_SMEM);
    cudaFuncSetAttribute(ctx_mma,    cudaFuncAttributeMaxDynamicSharedMemorySize, CTX_SMEM);

    prep_all<<<392, 256>>>(Wq, Wk, Wv, rel_v, rel_k);
    qkv_mma<<<dim3(64, 3), 256, QKV_SMEM>>>(x, bq, bk, bv);
    qrel_mma<<<128, 256, QREL_SMEM>>>();
    scores_mma<<<dim3(16, 8, 8), 256, SCORES_SMEM>>>(attn);
    softmax_arel<<<NROWS, 256>>>(attn);
    ctx_mma<<<dim3(16, 8, 2), 256, CTX_SMEM>>>(attn);
    outln_gemm<<<128, 256>>>(x, Wo, bo, gamma, beta, y);
}